// round 7
// baseline (speedup 1.0000x reference)
#include <cuda_runtime.h>
#include <math.h>
#include <stdint.h>

#define NVAR   100000
#define NCLS   400000
#define NEDG   600000
#define HDIM   128
#define NSTEPS 9

// ---------------- scratch (device globals) ----------------
__device__ float g_hv [NVAR * HDIM];
__device__ float g_hv2[NVAR * HDIM];
__device__ float g_cv [NVAR * HDIM];
__device__ float g_hc [NCLS * HDIM];
__device__ float g_hc2[NCLS * HDIM];
__device__ float g_cc [NCLS * HDIM];
__device__ float g_t1 [NCLS * HDIM];
__device__ float g_m  [NCLS * HDIM];
__device__ float g_z  [NCLS];
__device__ float    g_red[HDIM];
__device__ float    g_sum;
__device__ unsigned g_maxu;
// tf32-rounded weights: eW1 | eW2 | eW3 | Wih' | Whh' | pbias
#define OFF_E1  0
#define OFF_E2  65536
#define OFF_E3  131072
#define OFF_WIH 196608
#define OFF_WHH 327680
#define OFF_PB  458752
__device__ float g_wr[459776];

// ---------------- helpers ----------------
__device__ __forceinline__ unsigned f2ord(float f) {
    unsigned b = __float_as_uint(f);
    return (b & 0x80000000u) ? ~b : (b | 0x80000000u);
}
__device__ __forceinline__ float ord2f(unsigned u) {
    unsigned b = (u & 0x80000000u) ? (u ^ 0x80000000u) : ~u;
    return __uint_as_float(b);
}
__device__ __forceinline__ float sigmoidf(float x) { return 1.0f / (1.0f + expf(-x)); }

__device__ __forceinline__ uint32_t f2tf32(float f) {
    uint32_t o;
    asm("cvt.rna.tf32.f32 %0, %1;" : "=r"(o) : "f"(f));
    return o;
}
__device__ __forceinline__ uint32_t smem_u32(const void* p) {
    uint32_t a;
    asm("{ .reg .u64 t; cvta.to.shared.u64 t, %1; cvt.u32.u64 %0, t; }" : "=r"(a) : "l"(p));
    return a;
}
__device__ __forceinline__ void cp_async16(uint32_t dst, const void* src, int srcbytes) {
    asm volatile("cp.async.cg.shared.global [%0], [%1], 16, %2;"
                 :: "r"(dst), "l"(src), "r"(srcbytes) : "memory");
}
__device__ __forceinline__ void cp_commit() {
    asm volatile("cp.async.commit_group;" ::: "memory");
}
__device__ __forceinline__ void mma_tf32(float* c, const uint32_t* a, uint32_t b0, uint32_t b1) {
    asm volatile(
        "mma.sync.aligned.m16n8k8.row.col.f32.tf32.tf32.f32 "
        "{%0,%1,%2,%3}, {%4,%5,%6,%7}, {%8,%9}, {%0,%1,%2,%3};"
        : "+f"(c[0]), "+f"(c[1]), "+f"(c[2]), "+f"(c[3])
        : "r"(a[0]), "r"(a[1]), "r"(a[2]), "r"(a[3]), "r"(b0), "r"(b1));
}

// ---------------- prep kernels ----------------
__global__ void round_tf32(const float* __restrict__ src, float* __restrict__ dst, int n) {
    int i = blockIdx.x * blockDim.x + threadIdx.x;
    if (i < n) dst[i] = __uint_as_float(f2tf32(src[i]));
}
// LSTM weight permute: src[rel][j*128+f][k] -> dst[rel][4f+j][k] (tf32-rounded)
__global__ void permute_lstm_w(const float* __restrict__ src, float* __restrict__ dst) {
    int i = blockIdx.x * blockDim.x + threadIdx.x;   // 2*512*128
    if (i >= 131072) return;
    int rel = i >> 16;
    int rem = i & 65535;
    int r_old = rem >> 7;
    int k = rem & 127;
    int j = r_old >> 7;
    int f = r_old & 127;
    int r_new = (f << 2) | j;
    dst[(rel << 16) + (r_new << 7) + k] = __uint_as_float(f2tf32(src[i]));
}
__global__ void permute_lstm_b(const float* __restrict__ bih, const float* __restrict__ bhh,
                               float* __restrict__ pb) {
    int i = blockIdx.x * blockDim.x + threadIdx.x;   // 1024
    if (i >= 1024) return;
    int rel = i >> 9;
    int r_old = i & 511;
    int j = r_old >> 7;
    int f = r_old & 127;
    pb[(rel << 9) + (f << 2) + j] = bih[i] + bhh[i];
}

// ---------------- init: h = c = embed[x] ----------------
__global__ void init_embed(const int* __restrict__ x, const float* __restrict__ embed,
                           float* __restrict__ h, float* __restrict__ c, int n) {
    int i = blockIdx.x * blockDim.x + threadIdx.x;
    if (i >= n * HDIM) return;
    int node = i >> 7, col = i & 127;
    float v = embed[x[node] * HDIM + col];
    h[i] = v;
    c[i] = v;
}

// ============ fused 3-layer MLP: Y = relu(relu(relu(X W1^T+b1) W2^T+b2) W3^T+b3) ============
__global__ void __launch_bounds__(256)
mlp3_fused(const float* __restrict__ X,
           const float* __restrict__ W1l, const float* __restrict__ W2l,
           const float* __restrict__ W3l,
           const float* __restrict__ B1, const float* __restrict__ B2,
           const float* __restrict__ B3,
           float* __restrict__ Y, int N)
{
    extern __shared__ float sm[];
    float* X0s = sm;                 // 128*132
    float* X1s = sm + 16896;         // 128*132
    float* Wc  = sm + 33792;         // 2*4608
    float* sb  = sm + 43008;         // 3*128

    const int tid    = threadIdx.x;
    const int wid    = tid >> 5;
    const int lane   = tid & 31;
    const int warp_m = wid & 3;
    const int warp_n = wid >> 2;
    const int gid    = lane >> 2;
    const int thid   = lane & 3;
    const int row0   = blockIdx.x << 7;

    const uint32_t x0addr = smem_u32(X0s);
    const uint32_t wcaddr = smem_u32(Wc);
    const float* WL[3] = {W1l, W2l, W3l};

    if (tid < 128) {
        sb[tid]       = B1[tid];
        sb[128 + tid] = B2[tid];
        sb[256 + tid] = B3[tid];
    }

    auto issueW = [&](int g, int st) {
        const float* Wl = WL[g >> 2];
        const int kc = (g & 3) << 5;
#pragma unroll
        for (int it = 0; it < 4; it++) {
            int idx = it * 256 + tid;
            int r   = idx >> 3;
            int c4  = idx & 7;
            int gk  = kc + (c4 << 2);
            cp_async16(wcaddr + (uint32_t)(st * 4608 + r * 36 + c4 * 4) * 4u,
                       Wl + (size_t)r * 128 + gk, 16);
        }
        cp_commit();
    };

    // prologue: FULL 128x128 X tile (4096 float4s) + first two W chunks
#pragma unroll
    for (int it = 0; it < 16; it++) {
        int idx = it * 256 + tid;      // 0..4095
        int r   = idx >> 5;            // 0..127
        int c4  = idx & 31;            // 0..31  (32 float4 per 128-float row)
        int gk  = c4 << 2;
        int grow = row0 + r;
        const float* xp = (grow < N) ? (X + (size_t)grow * 128 + gk) : X;
        cp_async16(x0addr + (uint32_t)(r * 132 + c4 * 4) * 4u, xp, (grow < N) ? 16 : 0);
    }
    cp_commit();
    issueW(0, 0);
    issueW(1, 1);

    int gc = 0;
    for (int layer = 0; layer < 3; layer++) {
        const float* Xin = (layer & 1) ? X1s : X0s;
        float* Xout      = (layer & 1) ? X0s : X1s;

        float acc[2][8][4];
#pragma unroll
        for (int mt = 0; mt < 2; mt++)
#pragma unroll
            for (int nt = 0; nt < 8; nt++)
#pragma unroll
                for (int r = 0; r < 4; r++) acc[mt][nt][r] = 0.f;

        for (int q = 0; q < 4; q++, gc++) {
            if (gc + 1 < 12) asm volatile("cp.async.wait_group 1;" ::: "memory");
            else             asm volatile("cp.async.wait_group 0;" ::: "memory");
            __syncthreads();

            const float* Wb = Wc + (gc & 1) * 4608;
            const int kg0 = q << 5;
#pragma unroll
            for (int ks = 0; ks < 4; ks++) {
                const int kb = ks * 8;
                const int kg = kg0 + kb;
                uint32_t a[2][4];
#pragma unroll
                for (int mt = 0; mt < 2; mt++) {
                    int rr = warp_m * 32 + mt * 16 + gid;
                    a[mt][0] = f2tf32(Xin[rr * 132 + kg + thid]);
                    a[mt][1] = f2tf32(Xin[(rr + 8) * 132 + kg + thid]);
                    a[mt][2] = f2tf32(Xin[rr * 132 + kg + thid + 4]);
                    a[mt][3] = f2tf32(Xin[(rr + 8) * 132 + kg + thid + 4]);
                }
#pragma unroll
                for (int nt = 0; nt < 8; nt++) {
                    int cc_ = warp_n * 64 + nt * 8 + gid;
                    uint32_t b0 = __float_as_uint(Wb[cc_ * 36 + kb + thid]);
                    uint32_t b1 = __float_as_uint(Wb[cc_ * 36 + kb + thid + 4]);
                    mma_tf32(acc[0][nt], a[0], b0, b1);
                    mma_tf32(acc[1][nt], a[1], b0, b1);
                }
            }
            __syncthreads();
            if (gc + 2 < 12) issueW(gc + 2, gc & 1);
        }

        // layer epilogue
        if (layer < 2) {
#pragma unroll
            for (int mt = 0; mt < 2; mt++) {
                int rloc = warp_m * 32 + mt * 16 + gid;
#pragma unroll
                for (int nt = 0; nt < 8; nt++) {
                    int colL = warp_n * 64 + nt * 8 + thid * 2;
                    float b0 = sb[layer * 128 + colL], b1 = sb[layer * 128 + colL + 1];
                    Xout[rloc * 132 + colL]           = fmaxf(acc[mt][nt][0] + b0, 0.f);
                    Xout[rloc * 132 + colL + 1]       = fmaxf(acc[mt][nt][1] + b1, 0.f);
                    Xout[(rloc + 8) * 132 + colL]     = fmaxf(acc[mt][nt][2] + b0, 0.f);
                    Xout[(rloc + 8) * 132 + colL + 1] = fmaxf(acc[mt][nt][3] + b1, 0.f);
                }
            }
        } else {
#pragma unroll
            for (int mt = 0; mt < 2; mt++) {
                int rbase = row0 + warp_m * 32 + mt * 16 + gid;
#pragma unroll
                for (int nt = 0; nt < 8; nt++) {
                    int colL = warp_n * 64 + nt * 8 + thid * 2;
                    float b0 = sb[256 + colL], b1 = sb[256 + colL + 1];
                    float2 v0, v1;
                    v0.x = fmaxf(acc[mt][nt][0] + b0, 0.f);
                    v0.y = fmaxf(acc[mt][nt][1] + b1, 0.f);
                    v1.x = fmaxf(acc[mt][nt][2] + b0, 0.f);
                    v1.y = fmaxf(acc[mt][nt][3] + b1, 0.f);
                    if (rbase < N)     *(float2*)(Y + (size_t)rbase * 128 + colL)       = v0;
                    if (rbase + 8 < N) *(float2*)(Y + (size_t)(rbase + 8) * 128 + colL) = v1;
                }
            }
        }
    }
}

// ============ LSTM gate GEMM with fused pointwise epilogue ============
// G = [m|h_in] @ [Wih'|Whh']^T + pbias, gate-permuted cols (col = 4*feat+gate).
// Writes h_out (ping-pong, never the h_in operand) and updates c in place.
__global__ void __launch_bounds__(256)
gemm_lstm(const float* __restrict__ X1, const float* __restrict__ X2,
          const float* __restrict__ W1, const float* __restrict__ W2,
          const float* __restrict__ pb,
          float* __restrict__ hout, float* __restrict__ c, int N)
{
    extern __shared__ float sm[];
    float* Xs = sm;            // 2 * 4608
    float* Ws = sm + 9216;     // 2 * 4608

    const int tid    = threadIdx.x;
    const int wid    = tid >> 5;
    const int lane   = tid & 31;
    const int warp_m = wid & 3;
    const int warp_n = wid >> 2;
    const int gid    = lane >> 2;
    const int thid   = lane & 3;
    const int row0   = blockIdx.x << 7;
    const int col0   = blockIdx.y << 7;
    const int Q      = 8;                     // K=256

    const uint32_t xaddr = smem_u32(Xs);
    const uint32_t waddr = smem_u32(Ws);

    float acc[2][8][4];
#pragma unroll
    for (int mt = 0; mt < 2; mt++)
#pragma unroll
        for (int nt = 0; nt < 8; nt++)
#pragma unroll
            for (int r = 0; r < 4; r++) acc[mt][nt][r] = 0.f;

    auto issue = [&](int q, int st) {
        const int kc = q << 5;
        const uint32_t xb = xaddr + (uint32_t)st * 4608u * 4u;
        const uint32_t wb = waddr + (uint32_t)st * 4608u * 4u;
#pragma unroll
        for (int it = 0; it < 4; it++) {
            int idx = it * 256 + tid;
            int r   = idx >> 3;
            int c4  = idx & 7;
            int gk  = kc + (c4 << 2);
            uint32_t soff = (uint32_t)(r * 36 + c4 * 4) * 4u;
            {
                int grow = row0 + r;
                const float* xp = X1;
                int sz = 0;
                if (grow < N) {
                    xp = (gk < 128) ? (X1 + (size_t)grow * 128 + gk)
                                    : (X2 + (size_t)grow * 128 + (gk - 128));
                    sz = 16;
                }
                cp_async16(xb + soff, xp, sz);
            }
            {
                int gcol = col0 + r;
                const float* wp = (gk < 128) ? (W1 + (size_t)gcol * 128 + gk)
                                             : (W2 + (size_t)gcol * 128 + (gk - 128));
                cp_async16(wb + soff, wp, 16);
            }
        }
        cp_commit();
    };

    issue(0, 0);
    for (int q = 0; q < Q; q++) {
        if (q + 1 < Q) {
            issue(q + 1, (q + 1) & 1);
            asm volatile("cp.async.wait_group 1;" ::: "memory");
        } else {
            asm volatile("cp.async.wait_group 0;" ::: "memory");
        }
        __syncthreads();

        const float* Xb = Xs + (q & 1) * 4608;
        const float* Wb = Ws + (q & 1) * 4608;
#pragma unroll
        for (int ks = 0; ks < 4; ks++) {
            const int kb = ks * 8;
            uint32_t a[2][4];
#pragma unroll
            for (int mt = 0; mt < 2; mt++) {
                int rr = warp_m * 32 + mt * 16 + gid;
                a[mt][0] = f2tf32(Xb[rr * 36 + kb + thid]);
                a[mt][1] = f2tf32(Xb[(rr + 8) * 36 + kb + thid]);
                a[mt][2] = f2tf32(Xb[rr * 36 + kb + thid + 4]);
                a[mt][3] = f2tf32(Xb[(rr + 8) * 36 + kb + thid + 4]);
            }
#pragma unroll
            for (int nt = 0; nt < 8; nt++) {
                int cc_ = warp_n * 64 + nt * 8 + gid;
                uint32_t b0 = __float_as_uint(Wb[cc_ * 36 + kb + thid]);
                uint32_t b1 = __float_as_uint(Wb[cc_ * 36 + kb + thid + 4]);
                mma_tf32(acc[0][nt], a[0], b0, b1);
                mma_tf32(acc[1][nt], a[1], b0, b1);
            }
        }
        __syncthreads();
    }

    // ---- fused LSTM epilogue (even/odd lane pair exchange via shfl_xor(1)) ----
    const bool odd = (lane & 1);
    const int featbase = (col0 + warp_n * 64) >> 2;
#pragma unroll
    for (int mt = 0; mt < 2; mt++) {
        int rbase = row0 + warp_m * 32 + mt * 16 + gid;
#pragma unroll
        for (int nt = 0; nt < 8; nt++) {
            int colL = warp_n * 64 + nt * 8 + thid * 2;
            float b0 = pb[col0 + colL], b1 = pb[col0 + colL + 1];
            float v00 = acc[mt][nt][0] + b0;   // row rbase
            float v01 = acc[mt][nt][1] + b1;
            float v10 = acc[mt][nt][2] + b0;   // row rbase+8
            float v11 = acc[mt][nt][3] + b1;
            float s0 = odd ? v00 : v10;
            float s1 = odd ? v01 : v11;
            float t0 = __shfl_xor_sync(0xFFFFFFFFu, s0, 1);
            float t1 = __shfl_xor_sync(0xFFFFFFFFu, s1, 1);
            float gi = odd ? t0 : v00;
            float gf = odd ? t1 : v01;
            float gg = odd ? v10 : t0;
            float go = odd ? v11 : t1;
            int row  = rbase + (odd ? 8 : 0);
            int feat = featbase + nt * 2 + (thid >> 1);
            if (row < N) {
                size_t o = (size_t)row * 128 + feat;
                float cp = c[o];
                float cn = sigmoidf(gf) * cp + sigmoidf(gi) * tanhf(gg);
                hout[o] = sigmoidf(go) * tanhf(cn);
                c[o] = fmaxf(cn, 0.f);
            }
        }
    }
}

// ---------------- edge scatter-add: m[dst] += t[src] (vector red) ----------------
__global__ void scatter_add(const float* __restrict__ t, const int* __restrict__ src,
                            const int* __restrict__ dst, float* __restrict__ m, int E)
{
    int idx  = blockIdx.x * blockDim.x + threadIdx.x;
    int e    = idx >> 5;
    int lane = idx & 31;
    if (e >= E) return;
    int s = src[e], d = dst[e];
    float4 v = *(const float4*)(t + (size_t)s * HDIM + lane * 4);
    float* out = m + (size_t)d * HDIM + lane * 4;
    asm volatile("red.global.add.v4.f32 [%0], {%1, %2, %3, %4};"
                 :: "l"(out), "f"(v.x), "f"(v.y), "f"(v.z), "f"(v.w) : "memory");
}

// ---------------- attention pooling ----------------
__global__ void pool_reset(unsigned* maxu, float* sum, float* red) {
    if (threadIdx.x == 0) { *maxu = 0u; *sum = 0.f; }
    if (threadIdx.x < HDIM) red[threadIdx.x] = 0.f;
}

__global__ void gate_logits(const float* __restrict__ cc, const float* __restrict__ gW,
                            const float* __restrict__ gb, float* __restrict__ z,
                            unsigned* __restrict__ maxu, int n)
{
    __shared__ float smax[8];
    int gw   = (blockIdx.x * blockDim.x + threadIdx.x) >> 5;
    int lane = threadIdx.x & 31;
    int wid  = threadIdx.x >> 5;
    float myz = -1e30f;
    if (gw < n) {
        float4 a = *(const float4*)(cc + (size_t)gw * HDIM + lane * 4);
        float4 b = *(const float4*)(gW + lane * 4);
        float p = a.x * b.x + a.y * b.y + a.z * b.z + a.w * b.w;
        p += __shfl_down_sync(0xFFFFFFFFu, p, 16);
        p += __shfl_down_sync(0xFFFFFFFFu, p, 8);
        p += __shfl_down_sync(0xFFFFFFFFu, p, 4);
        p += __shfl_down_sync(0xFFFFFFFFu, p, 2);
        p += __shfl_down_sync(0xFFFFFFFFu, p, 1);
        if (lane == 0) {
            myz = p + gb[0];
            z[gw] = myz;
        }
    }
    if (lane == 0) smax[wid] = myz;
    __syncthreads();
    if (threadIdx.x == 0) {
        float mx = smax[0];
#pragma unroll
        for (int w = 1; w < 8; w++) mx = fmaxf(mx, smax[w]);
        atomicMax(maxu, f2ord(mx));
    }
}

__global__ void softmax_accum(const float* __restrict__ cc, const float* __restrict__ z,
                              const unsigned* __restrict__ maxu,
                              float* __restrict__ sum, float* __restrict__ red, int n)
{
    int t = threadIdx.x;
    float zmax = ord2f(*maxu);
    int c0 = blockIdx.x * 64;
    float acc = 0.f, wsum = 0.f;
    for (int i = 0; i < 64; i++) {
        int c = c0 + i;
        if (c >= n) break;
        float w = expf(z[c] - zmax);
        acc  += w * cc[(size_t)c * HDIM + t];
        wsum += w;
    }
    atomicAdd(&red[t], acc);
    if (t == 0) atomicAdd(sum, wsum);
}

__global__ void final_mlp(const float* __restrict__ red, const float* __restrict__ sum,
                          const float* __restrict__ mW1, const float* __restrict__ mb1,
                          const float* __restrict__ mW2, const float* __restrict__ mb2,
                          const float* __restrict__ mW3, const float* __restrict__ mb3,
                          float* __restrict__ out)
{
    __shared__ float x0[HDIM], x1[HDIM], x2[HDIM];
    int t = threadIdx.x;
    x0[t] = red[t] / (*sum);
    __syncthreads();
    {
        float a = mb1[t];
        for (int k = 0; k < HDIM; k++) a = fmaf(x0[k], mW1[t * HDIM + k], a);
        x1[t] = fmaxf(a, 0.f);
    }
    __syncthreads();
    {
        float a = mb2[t];
        for (int k = 0; k < HDIM; k++) a = fmaf(x1[k], mW2[t * HDIM + k], a);
        x2[t] = fmaxf(a, 0.f);
    }
    __syncthreads();
    if (t < 2) {
        float a = mb3[t];
        for (int k = 0; k < HDIM; k++) a = fmaf(x2[k], mW3[t * HDIM + k], a);
        out[t] = a;
    }
}

// ---------------- host orchestration ----------------
#define MLP_SMEM  ((43008 + 384) * 4)     // 173568 bytes
#define LSTM_SMEM (18432 * 4)             // 73728 bytes

extern "C" void kernel_launch(void* const* d_in, const int* in_sizes, int n_in,
                              void* d_out, int out_size)
{
    const int*   var_x    = (const int*)  d_in[0];
    const int*   clause_x = (const int*)  d_in[1];
    const int*   pos_src  = (const int*)  d_in[2];
    const int*   pos_dst  = (const int*)  d_in[3];
    const int*   neg_src  = (const int*)  d_in[4];
    const int*   neg_dst  = (const int*)  d_in[5];
    const int*   posr_src = (const int*)  d_in[6];
    const int*   posr_dst = (const int*)  d_in[7];
    const int*   negr_src = (const int*)  d_in[8];
    const int*   negr_dst = (const int*)  d_in[9];
    const float* embed    = (const float*)d_in[10];
    const float* eW1      = (const float*)d_in[11];
    const float* eb1      = (const float*)d_in[12];
    const float* eW2      = (const float*)d_in[13];
    const float* eb2      = (const float*)d_in[14];
    const float* eW3      = (const float*)d_in[15];
    const float* eb3      = (const float*)d_in[16];
    const float* Wih      = (const float*)d_in[17];
    const float* Whh      = (const float*)d_in[18];
    const float* bih      = (const float*)d_in[19];
    const float* bhh      = (const float*)d_in[20];
    const float* gW       = (const float*)d_in[21];
    const float* gb       = (const float*)d_in[22];
    const float* mW1      = (const float*)d_in[23];
    const float* mb1      = (const float*)d_in[24];
    const float* mW2      = (const float*)d_in[25];
    const float* mb2      = (const float*)d_in[26];
    const float* mW3      = (const float*)d_in[27];
    const float* mb3      = (const float*)d_in[28];
    float* out = (float*)d_out;

    cudaFuncSetAttribute(mlp3_fused, cudaFuncAttributeMaxDynamicSharedMemorySize, MLP_SMEM);
    cudaFuncSetAttribute(gemm_lstm, cudaFuncAttributeMaxDynamicSharedMemorySize, LSTM_SMEM);

    float *hv, *hv2, *cv, *hc, *hc2, *cc, *t1, *m, *z, *red, *sum, *wr;
    unsigned* maxu;
    cudaGetSymbolAddress((void**)&hv,   g_hv);
    cudaGetSymbolAddress((void**)&hv2,  g_hv2);
    cudaGetSymbolAddress((void**)&cv,   g_cv);
    cudaGetSymbolAddress((void**)&hc,   g_hc);
    cudaGetSymbolAddress((void**)&hc2,  g_hc2);
    cudaGetSymbolAddress((void**)&cc,   g_cc);
    cudaGetSymbolAddress((void**)&t1,   g_t1);
    cudaGetSymbolAddress((void**)&m,    g_m);
    cudaGetSymbolAddress((void**)&z,    g_z);
    cudaGetSymbolAddress((void**)&red,  g_red);
    cudaGetSymbolAddress((void**)&sum,  g_sum);
    cudaGetSymbolAddress((void**)&maxu, g_maxu);
    cudaGetSymbolAddress((void**)&wr,   g_wr);

    // prep: round MLP weights to tf32; permute+round LSTM weights; permuted biases
    round_tf32<<<(65536 + 255) / 256, 256>>>(eW1, wr + OFF_E1, 65536);
    round_tf32<<<(65536 + 255) / 256, 256>>>(eW2, wr + OFF_E2, 65536);
    round_tf32<<<(65536 + 255) / 256, 256>>>(eW3, wr + OFF_E3, 65536);
    permute_lstm_w<<<(131072 + 255) / 256, 256>>>(Wih, wr + OFF_WIH);
    permute_lstm_w<<<(131072 + 255) / 256, 256>>>(Whh, wr + OFF_WHH);
    permute_lstm_b<<<4, 256>>>(bih, bhh, wr + OFF_PB);

    init_embed<<<(NVAR * HDIM + 255) / 256, 256>>>(var_x,    embed, hv, cv, NVAR);
    init_embed<<<(NCLS * HDIM + 255) / 256, 256>>>(clause_x, embed, hc, cc, NCLS);

    const int HH = HDIM * HDIM;
    const int scat_blocks = (NEDG * 32 + 255) / 256;
    const float* E1 = wr + OFF_E1;
    const float* E2 = wr + OFF_E2;
    const float* E3 = wr + OFF_E3;
    const float* WIH = wr + OFF_WIH;
    const float* WHH = wr + OFF_WHH;
    const float* PB  = wr + OFF_PB;

    const int vgrid = (NVAR + 127) / 128;   // 782
    const int cgrid = (NCLS + 127) / 128;   // 3125

    // h ping-pong: LSTM reads h[cur], writes h[next] (h is ONLY consumed by the LSTM GEMM)
    float* hcs[2] = {hc, hc2};
    float* hvs[2] = {hv, hv2};
    int hci = 0, hvi = 0;

    for (int s = 0; s < NSTEPS; s++) {
        // ---- relation 0: var -> clause (etypes 0 pos, 1 neg) ----
        mlp3_fused<<<vgrid, 256, MLP_SMEM>>>(cv, E1 + 0 * HH, E2 + 0 * HH, E3 + 0 * HH,
                                             eb1 + 0 * HDIM, eb2 + 0 * HDIM, eb3 + 0 * HDIM,
                                             t1, NVAR);
        cudaMemsetAsync(m, 0, (size_t)NCLS * HDIM * sizeof(float));
        scatter_add<<<scat_blocks, 256>>>(t1, pos_src, pos_dst, m, NEDG);

        mlp3_fused<<<vgrid, 256, MLP_SMEM>>>(cv, E1 + 1 * HH, E2 + 1 * HH, E3 + 1 * HH,
                                             eb1 + 1 * HDIM, eb2 + 1 * HDIM, eb3 + 1 * HDIM,
                                             t1, NVAR);
        scatter_add<<<scat_blocks, 256>>>(t1, neg_src, neg_dst, m, NEDG);

        {   // clause LSTM (fused pointwise): read hcs[hci], write hcs[hci^1]
            dim3 grid(cgrid, 4);
            gemm_lstm<<<grid, 256, LSTM_SMEM>>>(m, hcs[hci], WIH, WHH, PB,
                                                hcs[hci ^ 1], cc, NCLS);
            hci ^= 1;
        }

        // ---- relation 1: clause -> var (etypes 2 pos_r, 3 neg_r) ----
        mlp3_fused<<<cgrid, 256, MLP_SMEM>>>(cc, E1 + 2 * HH, E2 + 2 * HH, E3 + 2 * HH,
                                             eb1 + 2 * HDIM, eb2 + 2 * HDIM, eb3 + 2 * HDIM,
                                             t1, NCLS);
        cudaMemsetAsync(m, 0, (size_t)NVAR * HDIM * sizeof(float));
        scatter_add<<<scat_blocks, 256>>>(t1, posr_src, posr_dst, m, NEDG);

        mlp3_fused<<<cgrid, 256, MLP_SMEM>>>(cc, E1 + 3 * HH, E2 + 3 * HH, E3 + 3 * HH,
                                             eb1 + 3 * HDIM, eb2 + 3 * HDIM, eb3 + 3 * HDIM,
                                             t1, NCLS);
        scatter_add<<<scat_blocks, 256>>>(t1, negr_src, negr_dst, m, NEDG);

        {   // var LSTM (fused pointwise): read hvs[hvi], write hvs[hvi^1]
            dim3 grid(vgrid, 4);
            gemm_lstm<<<grid, 256, LSTM_SMEM>>>(m, hvs[hvi], WIH + 65536, WHH + 65536,
                                                PB + 512, hvs[hvi ^ 1], cv, NVAR);
            hvi ^= 1;
        }
    }

    // ---- GlobalAttentionPooling + final MLP ----
    pool_reset<<<1, 128>>>(maxu, sum, red);
    gate_logits<<<(NCLS * 32 + 255) / 256, 256>>>(cc, gW, gb, z, maxu, NCLS);
    softmax_accum<<<(NCLS + 63) / 64, 128>>>(cc, z, maxu, sum, red, NCLS);
    final_mlp<<<1, 128>>>(red, sum, mW1, mb1, mW2, mb2, mW3, mb3, out);
}

// round 8
// speedup vs baseline: 1.0263x; 1.0263x over previous
#include <cuda_runtime.h>
#include <math.h>
#include <stdint.h>

#define NVAR   100000
#define NCLS   400000
#define NEDG   600000
#define HDIM   128
#define NSTEPS 9

// ---------------- scratch (device globals) ----------------
__device__ float g_hv [NVAR * HDIM];
__device__ float g_hv2[NVAR * HDIM];
__device__ float g_cv [NVAR * HDIM];
__device__ float g_hc [NCLS * HDIM];
__device__ float g_hc2[NCLS * HDIM];
__device__ float g_cc [NCLS * HDIM];
__device__ float g_t1 [NCLS * HDIM];
__device__ float g_m  [NCLS * HDIM];
__device__ float g_z  [NCLS];
__device__ float    g_red[HDIM];
__device__ float    g_sum;
__device__ unsigned g_maxu;
// tf32-rounded, K-pair-permuted weights: eW1 | eW2 | eW3 | Wih' | Whh' | pbias
#define OFF_E1  0
#define OFF_E2  65536
#define OFF_E3  131072
#define OFF_WIH 196608
#define OFF_WHH 327680
#define OFF_PB  458752
__device__ float g_wr[459776];

// ---------------- helpers ----------------
__device__ __forceinline__ unsigned f2ord(float f) {
    unsigned b = __float_as_uint(f);
    return (b & 0x80000000u) ? ~b : (b | 0x80000000u);
}
__device__ __forceinline__ float ord2f(unsigned u) {
    unsigned b = (u & 0x80000000u) ? (u ^ 0x80000000u) : ~u;
    return __uint_as_float(b);
}
__device__ __forceinline__ float sigmoidf(float x) { return 1.0f / (1.0f + expf(-x)); }

__device__ __forceinline__ uint32_t f2tf32(float f) {
    uint32_t o;
    asm("cvt.rna.tf32.f32 %0, %1;" : "=r"(o) : "f"(f));
    return o;
}
// paired-K permutation within each 8-group: hw-pair (k, k+4) stored adjacently
__device__ __forceinline__ int pkk(int k) {
    return (k & ~7) | ((k & 3) << 1) | ((k >> 2) & 1);
}
__device__ __forceinline__ uint32_t smem_u32(const void* p) {
    uint32_t a;
    asm("{ .reg .u64 t; cvta.to.shared.u64 t, %1; cvt.u32.u64 %0, t; }" : "=r"(a) : "l"(p));
    return a;
}
__device__ __forceinline__ void cp_async16(uint32_t dst, const void* src, int srcbytes) {
    asm volatile("cp.async.cg.shared.global [%0], [%1], 16, %2;"
                 :: "r"(dst), "l"(src), "r"(srcbytes) : "memory");
}
__device__ __forceinline__ void cp_commit() {
    asm volatile("cp.async.commit_group;" ::: "memory");
}
__device__ __forceinline__ void mma_tf32(float* c, const uint32_t* a, uint32_t b0, uint32_t b1) {
    asm volatile(
        "mma.sync.aligned.m16n8k8.row.col.f32.tf32.tf32.f32 "
        "{%0,%1,%2,%3}, {%4,%5,%6,%7}, {%8,%9}, {%0,%1,%2,%3};"
        : "+f"(c[0]), "+f"(c[1]), "+f"(c[2]), "+f"(c[3])
        : "r"(a[0]), "r"(a[1]), "r"(a[2]), "r"(a[3]), "r"(b0), "r"(b1));
}

// ---------------- prep kernels ----------------
// MLP weights: tf32-round + paired-K permute
__global__ void prep_w_pk(const float* __restrict__ src, float* __restrict__ dst, int n) {
    int i = blockIdx.x * blockDim.x + threadIdx.x;
    if (i >= n) return;
    int row = i >> 7, k = i & 127;
    dst[(row << 7) + pkk(k)] = __uint_as_float(f2tf32(src[i]));
}
// LSTM weights: row permute (j*128+f -> 4f+j) + paired-K + tf32 round
__global__ void permute_lstm_w(const float* __restrict__ src, float* __restrict__ dst) {
    int i = blockIdx.x * blockDim.x + threadIdx.x;   // 2*512*128
    if (i >= 131072) return;
    int rel = i >> 16;
    int rem = i & 65535;
    int r_old = rem >> 7;
    int k = rem & 127;
    int j = r_old >> 7;
    int f = r_old & 127;
    int r_new = (f << 2) | j;
    dst[(rel << 16) + (r_new << 7) + pkk(k)] = __uint_as_float(f2tf32(src[i]));
}
__global__ void permute_lstm_b(const float* __restrict__ bih, const float* __restrict__ bhh,
                               float* __restrict__ pb) {
    int i = blockIdx.x * blockDim.x + threadIdx.x;   // 1024
    if (i >= 1024) return;
    int rel = i >> 9;
    int r_old = i & 511;
    int j = r_old >> 7;
    int f = r_old & 127;
    pb[(rel << 9) + (f << 2) + j] = bih[i] + bhh[i];
}

// ---------------- init: h = c = embed[x] ----------------
__global__ void init_embed(const int* __restrict__ x, const float* __restrict__ embed,
                           float* __restrict__ h, float* __restrict__ c, int n) {
    int i = blockIdx.x * blockDim.x + threadIdx.x;
    if (i >= n * HDIM) return;
    int node = i >> 7, col = i & 127;
    float v = embed[x[node] * HDIM + col];
    h[i] = v;
    c[i] = v;
}

// ============ fused 3-layer MLP, paired-K fragments, in-place X (2 CTAs/SM) ============
// Smem: X[128*136] (paired-K, tf32-rounded) | W[2][128*40] | sb[384]
#define XSTR 136
#define WSTR 40
__global__ void __launch_bounds__(256, 2)
mlp3_fused(const float* __restrict__ X,
           const float* __restrict__ W1l, const float* __restrict__ W2l,
           const float* __restrict__ W3l,
           const float* __restrict__ B1, const float* __restrict__ B2,
           const float* __restrict__ B3,
           float* __restrict__ Y, int N)
{
    extern __shared__ float sm[];
    float* Xs = sm;                   // 128*136 = 17408
    float* Wc = sm + 17408;           // 2*5120  = 10240
    float* sb = sm + 27648;           // 384

    const int tid    = threadIdx.x;
    const int wid    = tid >> 5;
    const int lane   = tid & 31;
    const int warp_m = wid & 3;
    const int warp_n = wid >> 2;
    const int gid    = lane >> 2;
    const int thid   = lane & 3;
    const int row0   = blockIdx.x << 7;

    const uint32_t wcaddr = smem_u32(Wc);
    const float* WL[3] = {W1l, W2l, W3l};

    if (tid < 128) {
        sb[tid]       = B1[tid];
        sb[128 + tid] = B2[tid];
        sb[256 + tid] = B3[tid];
    }

    auto issueW = [&](int g, int st) {
        const float* Wl = WL[g >> 2];
        const int kc = (g & 3) << 5;
#pragma unroll
        for (int it = 0; it < 4; it++) {
            int idx = it * 256 + tid;    // 0..1023
            int r   = idx >> 3;          // 0..127
            int c4  = idx & 7;           // 0..7
            cp_async16(wcaddr + (uint32_t)(st * 5120 + r * WSTR + c4 * 4) * 4u,
                       Wl + (size_t)r * 128 + kc + c4 * 4, 16);
        }
        cp_commit();
    };

    issueW(0, 0);
    issueW(1, 1);

    // prologue: X tile -> smem, tf32-rounded, paired-K layout
#pragma unroll
    for (int it = 0; it < 16; it++) {
        int idx = it * 256 + tid;      // 0..4095
        int r   = idx >> 5;            // 0..127
        int c4  = idx & 31;            // 0..31
        int gk  = c4 << 2;
        int grow = row0 + r;
        float4 xv = make_float4(0.f, 0.f, 0.f, 0.f);
        if (grow < N) xv = *(const float4*)(X + (size_t)grow * 128 + gk);
        int base = r * XSTR + (gk & ~7) + ((gk >> 2) & 1);
        Xs[base + 0] = __uint_as_float(f2tf32(xv.x));
        Xs[base + 2] = __uint_as_float(f2tf32(xv.y));
        Xs[base + 4] = __uint_as_float(f2tf32(xv.z));
        Xs[base + 6] = __uint_as_float(f2tf32(xv.w));
    }

    int gc = 0;
    for (int layer = 0; layer < 3; layer++) {
        float acc[2][8][4];
#pragma unroll
        for (int mt = 0; mt < 2; mt++)
#pragma unroll
            for (int nt = 0; nt < 8; nt++)
#pragma unroll
                for (int r = 0; r < 4; r++) acc[mt][nt][r] = 0.f;

        for (int q = 0; q < 4; q++, gc++) {
            if (gc + 1 < 12) asm volatile("cp.async.wait_group 1;" ::: "memory");
            else             asm volatile("cp.async.wait_group 0;" ::: "memory");
            __syncthreads();

            const float* Wb = Wc + (gc & 1) * 5120;
            const int kg0 = q << 5;
#pragma unroll
            for (int ks = 0; ks < 4; ks++) {
                const int kb = ks * 8;
                const int kg = kg0 + kb;
                uint32_t a[2][4];
#pragma unroll
                for (int mt = 0; mt < 2; mt++) {
                    int rr = warp_m * 32 + mt * 16 + gid;
                    float2 a02 = *(const float2*)(Xs + rr * XSTR + kg + 2 * thid);
                    float2 a13 = *(const float2*)(Xs + (rr + 8) * XSTR + kg + 2 * thid);
                    a[mt][0] = __float_as_uint(a02.x);
                    a[mt][1] = __float_as_uint(a13.x);
                    a[mt][2] = __float_as_uint(a02.y);
                    a[mt][3] = __float_as_uint(a13.y);
                }
#pragma unroll
                for (int nt = 0; nt < 8; nt++) {
                    int cc_ = warp_n * 64 + nt * 8 + gid;
                    float2 bb = *(const float2*)(Wb + cc_ * WSTR + kb + 2 * thid);
                    uint32_t b0 = __float_as_uint(bb.x);
                    uint32_t b1 = __float_as_uint(bb.y);
                    mma_tf32(acc[0][nt], a[0], b0, b1);
                    mma_tf32(acc[1][nt], a[1], b0, b1);
                }
            }
            __syncthreads();
            if (gc + 2 < 12) issueW(gc + 2, gc & 1);
        }
        // all MMA reads of Xs complete (last __syncthreads above) -> in-place epilogue

        if (layer < 2) {
            // write back into Xs: paired-K positions, tf32-rounded, bias+relu
            int p0 = ((2 * thid) & 3) * 2 + ((2 * thid) >> 2);        // pk8(2*thid)
            int p1 = ((2 * thid + 1) & 3) * 2 + ((2 * thid + 1) >> 2); // pk8(2*thid+1)
#pragma unroll
            for (int mt = 0; mt < 2; mt++) {
                int rloc = warp_m * 32 + mt * 16 + gid;
#pragma unroll
                for (int nt = 0; nt < 8; nt++) {
                    int grp  = warp_n * 64 + nt * 8;
                    int colL = grp + thid * 2;
                    float b0 = sb[layer * 128 + colL], b1 = sb[layer * 128 + colL + 1];
                    float v00 = fmaxf(acc[mt][nt][0] + b0, 0.f);
                    float v01 = fmaxf(acc[mt][nt][1] + b1, 0.f);
                    float v10 = fmaxf(acc[mt][nt][2] + b0, 0.f);
                    float v11 = fmaxf(acc[mt][nt][3] + b1, 0.f);
                    Xs[rloc * XSTR + grp + p0]       = __uint_as_float(f2tf32(v00));
                    Xs[rloc * XSTR + grp + p1]       = __uint_as_float(f2tf32(v01));
                    Xs[(rloc + 8) * XSTR + grp + p0] = __uint_as_float(f2tf32(v10));
                    Xs[(rloc + 8) * XSTR + grp + p1] = __uint_as_float(f2tf32(v11));
                }
            }
            // next layer's first chunk waits on cp.async + __syncthreads before reading
        } else {
#pragma unroll
            for (int mt = 0; mt < 2; mt++) {
                int rbase = row0 + warp_m * 32 + mt * 16 + gid;
#pragma unroll
                for (int nt = 0; nt < 8; nt++) {
                    int colL = warp_n * 64 + nt * 8 + thid * 2;
                    float b0 = sb[256 + colL], b1 = sb[256 + colL + 1];
                    float2 v0, v1;
                    v0.x = fmaxf(acc[mt][nt][0] + b0, 0.f);
                    v0.y = fmaxf(acc[mt][nt][1] + b1, 0.f);
                    v1.x = fmaxf(acc[mt][nt][2] + b0, 0.f);
                    v1.y = fmaxf(acc[mt][nt][3] + b1, 0.f);
                    if (rbase < N)     *(float2*)(Y + (size_t)rbase * 128 + colL)       = v0;
                    if (rbase + 8 < N) *(float2*)(Y + (size_t)(rbase + 8) * 128 + colL) = v1;
                }
            }
        }
    }
}

// ============ LSTM gate GEMM (paired-K W) with fused pointwise epilogue ============
__global__ void __launch_bounds__(256, 2)
gemm_lstm(const float* __restrict__ X1, const float* __restrict__ X2,
          const float* __restrict__ W1, const float* __restrict__ W2,
          const float* __restrict__ pb,
          float* __restrict__ hout, float* __restrict__ c, int N)
{
    extern __shared__ float sm[];
    float* Xs = sm;            // 2 * 4608 (stride 36, natural K)
    float* Ws = sm + 9216;     // 2 * 5120 (stride 40, paired K)

    const int tid    = threadIdx.x;
    const int wid    = tid >> 5;
    const int lane   = tid & 31;
    const int warp_m = wid & 3;
    const int warp_n = wid >> 2;
    const int gid    = lane >> 2;
    const int thid   = lane & 3;
    const int row0   = blockIdx.x << 7;
    const int col0   = blockIdx.y << 7;
    const int Q      = 8;                     // K=256

    const uint32_t xaddr = smem_u32(Xs);
    const uint32_t waddr = smem_u32(Ws);

    float acc[2][8][4];
#pragma unroll
    for (int mt = 0; mt < 2; mt++)
#pragma unroll
        for (int nt = 0; nt < 8; nt++)
#pragma unroll
            for (int r = 0; r < 4; r++) acc[mt][nt][r] = 0.f;

    auto issue = [&](int q, int st) {
        const int kc = q << 5;
        const uint32_t xb = xaddr + (uint32_t)st * 4608u * 4u;
        const uint32_t wb = waddr + (uint32_t)st * 5120u * 4u;
#pragma unroll
        for (int it = 0; it < 4; it++) {
            int idx = it * 256 + tid;
            int r   = idx >> 3;
            int c4  = idx & 7;
            int gk  = kc + (c4 << 2);
            {
                int grow = row0 + r;
                const float* xp = X1;
                int sz = 0;
                if (grow < N) {
                    xp = (gk < 128) ? (X1 + (size_t)grow * 128 + gk)
                                    : (X2 + (size_t)grow * 128 + (gk - 128));
                    sz = 16;
                }
                cp_async16(xb + (uint32_t)(r * 36 + c4 * 4) * 4u, xp, sz);
            }
            {
                int gcol = col0 + r;
                const float* wp = (gk < 128) ? (W1 + (size_t)gcol * 128 + gk)
                                             : (W2 + (size_t)gcol * 128 + (gk - 128));
                cp_async16(wb + (uint32_t)(r * WSTR + c4 * 4) * 4u, wp, 16);
            }
        }
        cp_commit();
    };

    issue(0, 0);
    for (int q = 0; q < Q; q++) {
        if (q + 1 < Q) {
            issue(q + 1, (q + 1) & 1);
            asm volatile("cp.async.wait_group 1;" ::: "memory");
        } else {
            asm volatile("cp.async.wait_group 0;" ::: "memory");
        }
        __syncthreads();

        const float* Xb = Xs + (q & 1) * 4608;
        const float* Wb = Ws + (q & 1) * 5120;
#pragma unroll
        for (int ks = 0; ks < 4; ks++) {
            const int kb = ks * 8;
            uint32_t a[2][4];
#pragma unroll
            for (int mt = 0; mt < 2; mt++) {
                int rr = warp_m * 32 + mt * 16 + gid;
                a[mt][0] = f2tf32(Xb[rr * 36 + kb + thid]);
                a[mt][1] = f2tf32(Xb[(rr + 8) * 36 + kb + thid]);
                a[mt][2] = f2tf32(Xb[rr * 36 + kb + thid + 4]);
                a[mt][3] = f2tf32(Xb[(rr + 8) * 36 + kb + thid + 4]);
            }
#pragma unroll
            for (int nt = 0; nt < 8; nt++) {
                int cc_ = warp_n * 64 + nt * 8 + gid;
                float2 bb = *(const float2*)(Wb + cc_ * WSTR + kb + 2 * thid);
                uint32_t b0 = __float_as_uint(bb.x);
                uint32_t b1 = __float_as_uint(bb.y);
                mma_tf32(acc[0][nt], a[0], b0, b1);
                mma_tf32(acc[1][nt], a[1], b0, b1);
            }
        }
        __syncthreads();
    }

    // ---- fused LSTM epilogue ----
    const bool odd = (lane & 1);
    const int featbase = (col0 + warp_n * 64) >> 2;
#pragma unroll
    for (int mt = 0; mt < 2; mt++) {
        int rbase = row0 + warp_m * 32 + mt * 16 + gid;
#pragma unroll
        for (int nt = 0; nt < 8; nt++) {
            int colL = warp_n * 64 + nt * 8 + thid * 2;
            float b0 = pb[col0 + colL], b1 = pb[col0 + colL + 1];
            float v00 = acc[mt][nt][0] + b0;   // row rbase
            float v01 = acc[mt][nt][1] + b1;
            float v10 = acc[mt][nt][2] + b0;   // row rbase+8
            float v11 = acc[mt][nt][3] + b1;
            float s0 = odd ? v00 : v10;
            float s1 = odd ? v01 : v11;
            float t0 = __shfl_xor_sync(0xFFFFFFFFu, s0, 1);
            float t1 = __shfl_xor_sync(0xFFFFFFFFu, s1, 1);
            float gi = odd ? t0 : v00;
            float gf = odd ? t1 : v01;
            float gg = odd ? v10 : t0;
            float go = odd ? v11 : t1;
            int row  = rbase + (odd ? 8 : 0);
            int feat = featbase + nt * 2 + (thid >> 1);
            if (row < N) {
                size_t o = (size_t)row * 128 + feat;
                float cp = c[o];
                float cn = sigmoidf(gf) * cp + sigmoidf(gi) * tanhf(gg);
                hout[o] = sigmoidf(go) * tanhf(cn);
                c[o] = fmaxf(cn, 0.f);
            }
        }
    }
}

// ---------------- edge scatter-add ----------------
__global__ void scatter_add(const float* __restrict__ t, const int* __restrict__ src,
                            const int* __restrict__ dst, float* __restrict__ m, int E)
{
    int idx  = blockIdx.x * blockDim.x + threadIdx.x;
    int e    = idx >> 5;
    int lane = idx & 31;
    if (e >= E) return;
    int s = src[e], d = dst[e];
    float4 v = *(const float4*)(t + (size_t)s * HDIM + lane * 4);
    float* out = m + (size_t)d * HDIM + lane * 4;
    asm volatile("red.global.add.v4.f32 [%0], {%1, %2, %3, %4};"
                 :: "l"(out), "f"(v.x), "f"(v.y), "f"(v.z), "f"(v.w) : "memory");
}

// ---------------- attention pooling ----------------
__global__ void pool_reset(unsigned* maxu, float* sum, float* red) {
    if (threadIdx.x == 0) { *maxu = 0u; *sum = 0.f; }
    if (threadIdx.x < HDIM) red[threadIdx.x] = 0.f;
}

__global__ void gate_logits(const float* __restrict__ cc, const float* __restrict__ gW,
                            const float* __restrict__ gb, float* __restrict__ z,
                            unsigned* __restrict__ maxu, int n)
{
    __shared__ float smax[8];
    int gw   = (blockIdx.x * blockDim.x + threadIdx.x) >> 5;
    int lane = threadIdx.x & 31;
    int wid  = threadIdx.x >> 5;
    float myz = -1e30f;
    if (gw < n) {
        float4 a = *(const float4*)(cc + (size_t)gw * HDIM + lane * 4);
        float4 b = *(const float4*)(gW + lane * 4);
        float p = a.x * b.x + a.y * b.y + a.z * b.z + a.w * b.w;
        p += __shfl_down_sync(0xFFFFFFFFu, p, 16);
        p += __shfl_down_sync(0xFFFFFFFFu, p, 8);
        p += __shfl_down_sync(0xFFFFFFFFu, p, 4);
        p += __shfl_down_sync(0xFFFFFFFFu, p, 2);
        p += __shfl_down_sync(0xFFFFFFFFu, p, 1);
        if (lane == 0) {
            myz = p + gb[0];
            z[gw] = myz;
        }
    }
    if (lane == 0) smax[wid] = myz;
    __syncthreads();
    if (threadIdx.x == 0) {
        float mx = smax[0];
#pragma unroll
        for (int w = 1; w < 8; w++) mx = fmaxf(mx, smax[w]);
        atomicMax(maxu, f2ord(mx));
    }
}

__global__ void softmax_accum(const float* __restrict__ cc, const float* __restrict__ z,
                              const unsigned* __restrict__ maxu,
                              float* __restrict__ sum, float* __restrict__ red, int n)
{
    int t = threadIdx.x;
    float zmax = ord2f(*maxu);
    int c0 = blockIdx.x * 64;
    float acc = 0.f, wsum = 0.f;
    for (int i = 0; i < 64; i++) {
        int c = c0 + i;
        if (c >= n) break;
        float w = expf(z[c] - zmax);
        acc  += w * cc[(size_t)c * HDIM + t];
        wsum += w;
    }
    atomicAdd(&red[t], acc);
    if (t == 0) atomicAdd(sum, wsum);
}

__global__ void final_mlp(const float* __restrict__ red, const float* __restrict__ sum,
                          const float* __restrict__ mW1, const float* __restrict__ mb1,
                          const float* __restrict__ mW2, const float* __restrict__ mb2,
                          const float* __restrict__ mW3, const float* __restrict__ mb3,
                          float* __restrict__ out)
{
    __shared__ float x0[HDIM], x1[HDIM], x2[HDIM];
    int t = threadIdx.x;
    x0[t] = red[t] / (*sum);
    __syncthreads();
    {
        float a = mb1[t];
        for (int k = 0; k < HDIM; k++) a = fmaf(x0[k], mW1[t * HDIM + k], a);
        x1[t] = fmaxf(a, 0.f);
    }
    __syncthreads();
    {
        float a = mb2[t];
        for (int k = 0; k < HDIM; k++) a = fmaf(x1[k], mW2[t * HDIM + k], a);
        x2[t] = fmaxf(a, 0.f);
    }
    __syncthreads();
    if (t < 2) {
        float a = mb3[t];
        for (int k = 0; k < HDIM; k++) a = fmaf(x2[k], mW3[t * HDIM + k], a);
        out[t] = a;
    }
}

// ---------------- host orchestration ----------------
#define MLP_SMEM  (28032 * 4)    // 112128 bytes -> 2 CTAs/SM
#define LSTM_SMEM (19456 * 4)    // 77824 bytes  -> 2 CTAs/SM

extern "C" void kernel_launch(void* const* d_in, const int* in_sizes, int n_in,
                              void* d_out, int out_size)
{
    const int*   var_x    = (const int*)  d_in[0];
    const int*   clause_x = (const int*)  d_in[1];
    const int*   pos_src  = (const int*)  d_in[2];
    const int*   pos_dst  = (const int*)  d_in[3];
    const int*   neg_src  = (const int*)  d_in[4];
    const int*   neg_dst  = (const int*)  d_in[5];
    const int*   posr_src = (const int*)  d_in[6];
    const int*   posr_dst = (const int*)  d_in[7];
    const int*   negr_src = (const int*)  d_in[8];
    const int*   negr_dst = (const int*)  d_in[9];
    const float* embed    = (const float*)d_in[10];
    const float* eW1      = (const float*)d_in[11];
    const float* eb1      = (const float*)d_in[12];
    const float* eW2      = (const float*)d_in[13];
    const float* eb2      = (const float*)d_in[14];
    const float* eW3      = (const float*)d_in[15];
    const float* eb3      = (const float*)d_in[16];
    const float* Wih      = (const float*)d_in[17];
    const float* Whh      = (const float*)d_in[18];
    const float* bih      = (const float*)d_in[19];
    const float* bhh      = (const float*)d_in[20];
    const float* gW       = (const float*)d_in[21];
    const float* gb       = (const float*)d_in[22];
    const float* mW1      = (const float*)d_in[23];
    const float* mb1      = (const float*)d_in[24];
    const float* mW2      = (const float*)d_in[25];
    const float* mb2      = (const float*)d_in[26];
    const float* mW3      = (const float*)d_in[27];
    const float* mb3      = (const float*)d_in[28];
    float* out = (float*)d_out;

    cudaFuncSetAttribute(mlp3_fused, cudaFuncAttributeMaxDynamicSharedMemorySize, MLP_SMEM);
    cudaFuncSetAttribute(gemm_lstm, cudaFuncAttributeMaxDynamicSharedMemorySize, LSTM_SMEM);

    float *hv, *hv2, *cv, *hc, *hc2, *cc, *t1, *m, *z, *red, *sum, *wr;
    unsigned* maxu;
    cudaGetSymbolAddress((void**)&hv,   g_hv);
    cudaGetSymbolAddress((void**)&hv2,  g_hv2);
    cudaGetSymbolAddress((void**)&cv,   g_cv);
    cudaGetSymbolAddress((void**)&hc,   g_hc);
    cudaGetSymbolAddress((void**)&hc2,  g_hc2);
    cudaGetSymbolAddress((void**)&cc,   g_cc);
    cudaGetSymbolAddress((void**)&t1,   g_t1);
    cudaGetSymbolAddress((void**)&m,    g_m);
    cudaGetSymbolAddress((void**)&z,    g_z);
    cudaGetSymbolAddress((void**)&red,  g_red);
    cudaGetSymbolAddress((void**)&sum,  g_sum);
    cudaGetSymbolAddress((void**)&maxu, g_maxu);
    cudaGetSymbolAddress((void**)&wr,   g_wr);

    // prep: tf32-round + paired-K permute all GEMM weights
    prep_w_pk<<<(65536 + 255) / 256, 256>>>(eW1, wr + OFF_E1, 65536);
    prep_w_pk<<<(65536 + 255) / 256, 256>>>(eW2, wr + OFF_E2, 65536);
    prep_w_pk<<<(65536 + 255) / 256, 256>>>(eW3, wr + OFF_E3, 65536);
    permute_lstm_w<<<(131072 + 255) / 256, 256>>>(Wih, wr + OFF_WIH);
    permute_lstm_w<<<(131072 + 255) / 256, 256>>>(Whh, wr + OFF_WHH);
    permute_lstm_b<<<4, 256>>>(bih, bhh, wr + OFF_PB);

    init_embed<<<(NVAR * HDIM + 255) / 256, 256>>>(var_x,    embed, hv, cv, NVAR);
    init_embed<<<(NCLS * HDIM + 255) / 256, 256>>>(clause_x, embed, hc, cc, NCLS);

    const int HH = HDIM * HDIM;
    const int scat_blocks = (NEDG * 32 + 255) / 256;
    const float* E1 = wr + OFF_E1;
    const float* E2 = wr + OFF_E2;
    const float* E3 = wr + OFF_E3;
    const float* WIH = wr + OFF_WIH;
    const float* WHH = wr + OFF_WHH;
    const float* PB  = wr + OFF_PB;

    const int vgrid = (NVAR + 127) / 128;   // 782
    const int cgrid = (NCLS + 127) / 128;   // 3125

    // h ping-pong: LSTM reads h[cur], writes h[next]
    float* hcs[2] = {hc, hc2};
    float* hvs[2] = {hv, hv2};
    int hci = 0, hvi = 0;

    for (int s = 0; s < NSTEPS; s++) {
        // ---- relation 0: var -> clause ----
        mlp3_fused<<<vgrid, 256, MLP_SMEM>>>(cv, E1 + 0 * HH, E2 + 0 * HH, E3 + 0 * HH,
                                             eb1 + 0 * HDIM, eb2 + 0 * HDIM, eb3 + 0 * HDIM,
                                             t1, NVAR);
        cudaMemsetAsync(m, 0, (size_t)NCLS * HDIM * sizeof(float));
        scatter_add<<<scat_blocks, 256>>>(t1, pos_src, pos_dst, m, NEDG);

        mlp3_fused<<<vgrid, 256, MLP_SMEM>>>(cv, E1 + 1 * HH, E2 + 1 * HH, E3 + 1 * HH,
                                             eb1 + 1 * HDIM, eb2 + 1 * HDIM, eb3 + 1 * HDIM,
                                             t1, NVAR);
        scatter_add<<<scat_blocks, 256>>>(t1, neg_src, neg_dst, m, NEDG);

        {   // clause LSTM
            dim3 grid(cgrid, 4);
            gemm_lstm<<<grid, 256, LSTM_SMEM>>>(m, hcs[hci], WIH, WHH, PB,
                                                hcs[hci ^ 1], cc, NCLS);
            hci ^= 1;
        }

        // ---- relation 1: clause -> var ----
        mlp3_fused<<<cgrid, 256, MLP_SMEM>>>(cc, E1 + 2 * HH, E2 + 2 * HH, E3 + 2 * HH,
                                             eb1 + 2 * HDIM, eb2 + 2 * HDIM, eb3 + 2 * HDIM,
                                             t1, NCLS);
        cudaMemsetAsync(m, 0, (size_t)NVAR * HDIM * sizeof(float));
        scatter_add<<<scat_blocks, 256>>>(t1, posr_src, posr_dst, m, NEDG);

        mlp3_fused<<<cgrid, 256, MLP_SMEM>>>(cc, E1 + 3 * HH, E2 + 3 * HH, E3 + 3 * HH,
                                             eb1 + 3 * HDIM, eb2 + 3 * HDIM, eb3 + 3 * HDIM,
                                             t1, NCLS);
        scatter_add<<<scat_blocks, 256>>>(t1, negr_src, negr_dst, m, NEDG);

        {   // var LSTM
            dim3 grid(vgrid, 4);
            gemm_lstm<<<grid, 256, LSTM_SMEM>>>(m, hvs[hvi], WIH + 65536, WHH + 65536,
                                                PB + 512, hvs[hvi ^ 1], cv, NVAR);
            hvi ^= 1;
        }
    }

    // ---- GlobalAttentionPooling + final MLP ----
    pool_reset<<<1, 128>>>(maxu, sum, red);
    gate_logits<<<(NCLS * 32 + 255) / 256, 256>>>(cc, gW, gb, z, maxu, NCLS);
    softmax_accum<<<(NCLS + 63) / 64, 128>>>(cc, z, maxu, sum, red, NCLS);
    final_mlp<<<1, 128>>>(red, sum, mW1, mb1, mW2, mb2, mW3, mb3, out);
}

// round 9
// speedup vs baseline: 1.1194x; 1.0907x over previous
#include <cuda_runtime.h>
#include <math.h>
#include <stdint.h>

#define NVAR   100000
#define NCLS   400000
#define NEDG   600000
#define HDIM   128
#define NSTEPS 9

// ---------------- scratch (device globals) ----------------
__device__ float g_hv [NVAR * HDIM];
__device__ float g_hv2[NVAR * HDIM];
__device__ float g_cv [NVAR * HDIM];
__device__ float g_hc [NCLS * HDIM];
__device__ float g_hc2[NCLS * HDIM];
__device__ float g_cc [NCLS * HDIM];
__device__ float g_t1 [NCLS * HDIM];
__device__ float g_t2 [NCLS * HDIM];
__device__ float g_m  [NCLS * HDIM];
__device__ float g_z  [NCLS];
__device__ float    g_red[HDIM];
__device__ float    g_sum;
__device__ unsigned g_maxu;
// tf32-rounded, K-pair-permuted weights: eW1 | eW2 | eW3 | Wih' | Whh' | pbias
#define OFF_E1  0
#define OFF_E2  65536
#define OFF_E3  131072
#define OFF_WIH 196608
#define OFF_WHH 327680
#define OFF_PB  458752
#define PREP_N  459776
__device__ float g_wr[PREP_N];
// CSR (per etype): off becomes INCLUSIVE prefix after fill; csr holds src ids
__device__ int g_off[4][NCLS];
__device__ int g_csr[4][NEDG];
__device__ int g_cnt[NCLS];
__device__ int g_part[512];

// ---------------- helpers ----------------
__device__ __forceinline__ unsigned f2ord(float f) {
    unsigned b = __float_as_uint(f);
    return (b & 0x80000000u) ? ~b : (b | 0x80000000u);
}
__device__ __forceinline__ float ord2f(unsigned u) {
    unsigned b = (u & 0x80000000u) ? (u ^ 0x80000000u) : ~u;
    return __uint_as_float(b);
}
__device__ __forceinline__ float sigmoidf(float x) { return 1.0f / (1.0f + expf(-x)); }

__device__ __forceinline__ uint32_t f2tf32(float f) {
    uint32_t o;
    asm("cvt.rna.tf32.f32 %0, %1;" : "=r"(o) : "f"(f));
    return o;
}
// paired-K permutation within each 8-group: hw-pair (k, k+4) stored adjacently
__device__ __forceinline__ int pkk(int k) {
    return (k & ~7) | ((k & 3) << 1) | ((k >> 2) & 1);
}
__device__ __forceinline__ uint32_t smem_u32(const void* p) {
    uint32_t a;
    asm("{ .reg .u64 t; cvta.to.shared.u64 t, %1; cvt.u32.u64 %0, t; }" : "=r"(a) : "l"(p));
    return a;
}
__device__ __forceinline__ void cp_async16(uint32_t dst, const void* src, int srcbytes) {
    asm volatile("cp.async.cg.shared.global [%0], [%1], 16, %2;"
                 :: "r"(dst), "l"(src), "r"(srcbytes) : "memory");
}
__device__ __forceinline__ void cp_commit() {
    asm volatile("cp.async.commit_group;" ::: "memory");
}
__device__ __forceinline__ void mma_tf32(float* c, const uint32_t* a, uint32_t b0, uint32_t b1) {
    asm volatile(
        "mma.sync.aligned.m16n8k8.row.col.f32.tf32.tf32.f32 "
        "{%0,%1,%2,%3}, {%4,%5,%6,%7}, {%8,%9}, {%0,%1,%2,%3};"
        : "+f"(c[0]), "+f"(c[1]), "+f"(c[2]), "+f"(c[3])
        : "r"(a[0]), "r"(a[1]), "r"(a[2]), "r"(a[3]), "r"(b0), "r"(b1));
}

// ---------------- ONE fused weight-prep kernel ----------------
__global__ void prep_all(const float* __restrict__ eW1, const float* __restrict__ eW2,
                         const float* __restrict__ eW3, const float* __restrict__ Wih,
                         const float* __restrict__ Whh, const float* __restrict__ bih,
                         const float* __restrict__ bhh, float* __restrict__ wr)
{
    int i = blockIdx.x * blockDim.x + threadIdx.x;
    if (i >= PREP_N) return;
    if (i < 196608) {               // eW1|eW2|eW3, tf32-round + paired-K
        const float* src = (i < 65536) ? eW1 : (i < 131072) ? eW2 : eW3;
        int base = (i < 65536) ? OFF_E1 : (i < 131072) ? OFF_E2 : OFF_E3;
        int j = i & 65535;
        int row = j >> 7, k = j & 127;
        wr[base + (row << 7) + pkk(k)] = __uint_as_float(f2tf32(src[j]));
    } else if (i < 458752) {        // Wih' | Whh': gate-row permute + paired-K + round
        int j = i - 196608;
        const float* src = (j < 131072) ? Wih : Whh;
        int base = (j < 131072) ? OFF_WIH : OFF_WHH;
        j &= 131071;
        int rel = j >> 16;
        int rem = j & 65535;
        int r_old = rem >> 7, k = rem & 127;
        int g = r_old >> 7, f = r_old & 127;
        wr[base + (rel << 16) + (((f << 2) | g) << 7) + pkk(k)] =
            __uint_as_float(f2tf32(src[j]));
    } else {                        // permuted bias sum
        int j = i - 458752;
        int rel = j >> 9;
        int r_old = j & 511;
        int g = r_old >> 7, f = r_old & 127;
        wr[OFF_PB + (rel << 9) + (f << 2) + g] = bih[j] + bhh[j];
    }
}

// ---------------- CSR build kernels ----------------
__global__ void hist_k(const int* __restrict__ dst, int* __restrict__ cnt, int E) {
    int i = blockIdx.x * blockDim.x + threadIdx.x;
    if (i < E) atomicAdd(&cnt[dst[i]], 1);
}
__global__ void scan1_k(const int* __restrict__ cnt, int* __restrict__ off,
                        int* __restrict__ part, int N) {
    __shared__ int s[1024];
    int i = blockIdx.x * 1024 + threadIdx.x;
    int v = (i < N) ? cnt[i] : 0;
    s[threadIdx.x] = v;
    __syncthreads();
    for (int d = 1; d < 1024; d <<= 1) {
        int t = (threadIdx.x >= d) ? s[threadIdx.x - d] : 0;
        __syncthreads();
        s[threadIdx.x] += t;
        __syncthreads();
    }
    if (i < N) off[i] = s[threadIdx.x] - v;             // exclusive
    if (threadIdx.x == 1023) part[blockIdx.x] = s[1023];
}
__global__ void scan2_k(int* __restrict__ part, int NB) {
    __shared__ int s[512];
    int v = (threadIdx.x < NB) ? part[threadIdx.x] : 0;
    s[threadIdx.x] = v;
    __syncthreads();
    for (int d = 1; d < 512; d <<= 1) {
        int t = (threadIdx.x >= d) ? s[threadIdx.x - d] : 0;
        __syncthreads();
        s[threadIdx.x] += t;
        __syncthreads();
    }
    if (threadIdx.x < NB) part[threadIdx.x] = s[threadIdx.x] - v;  // exclusive
}
__global__ void scan3_k(int* __restrict__ off, const int* __restrict__ part, int N) {
    int i = blockIdx.x * 1024 + threadIdx.x;
    if (i < N) off[i] += part[blockIdx.x];
}
// fill: off -> inclusive prefix as side effect (atomic bump)
__global__ void fill_k(const int* __restrict__ src, const int* __restrict__ dst,
                       int* __restrict__ off, int* __restrict__ csr, int E) {
    int i = blockIdx.x * blockDim.x + threadIdx.x;
    if (i >= E) return;
    int p = atomicAdd(&off[dst[i]], 1);
    csr[p] = src[i];
}

// ---------------- init: h = c = embed[x] ----------------
__global__ void init_embed(const int* __restrict__ x, const float* __restrict__ embed,
                           float* __restrict__ h, float* __restrict__ c, int n) {
    int i = blockIdx.x * blockDim.x + threadIdx.x;
    if (i >= n * HDIM) return;
    int node = i >> 7, col = i & 127;
    float v = embed[x[node] * HDIM + col];
    h[i] = v;
    c[i] = v;
}

// ============ fused 3-layer MLP (R8: paired-K, in-place X, 2 CTAs/SM) ============
#define XSTR 136
#define WSTR 40
__global__ void __launch_bounds__(256, 2)
mlp3_fused(const float* __restrict__ X,
           const float* __restrict__ W1l, const float* __restrict__ W2l,
           const float* __restrict__ W3l,
           const float* __restrict__ B1, const float* __restrict__ B2,
           const float* __restrict__ B3,
           float* __restrict__ Y, int N)
{
    extern __shared__ float sm[];
    float* Xs = sm;                   // 128*136 = 17408
    float* Wc = sm + 17408;           // 2*5120  = 10240
    float* sb = sm + 27648;           // 384

    const int tid    = threadIdx.x;
    const int wid    = tid >> 5;
    const int lane   = tid & 31;
    const int warp_m = wid & 3;
    const int warp_n = wid >> 2;
    const int gid    = lane >> 2;
    const int thid   = lane & 3;
    const int row0   = blockIdx.x << 7;

    const uint32_t wcaddr = smem_u32(Wc);
    const float* WL[3] = {W1l, W2l, W3l};

    if (tid < 128) {
        sb[tid]       = B1[tid];
        sb[128 + tid] = B2[tid];
        sb[256 + tid] = B3[tid];
    }

    auto issueW = [&](int g, int st) {
        const float* Wl = WL[g >> 2];
        const int kc = (g & 3) << 5;
#pragma unroll
        for (int it = 0; it < 4; it++) {
            int idx = it * 256 + tid;
            int r   = idx >> 3;
            int c4  = idx & 7;
            cp_async16(wcaddr + (uint32_t)(st * 5120 + r * WSTR + c4 * 4) * 4u,
                       Wl + (size_t)r * 128 + kc + c4 * 4, 16);
        }
        cp_commit();
    };

    issueW(0, 0);
    issueW(1, 1);

    // prologue: X tile -> smem, tf32-rounded, paired-K layout
#pragma unroll
    for (int it = 0; it < 16; it++) {
        int idx = it * 256 + tid;
        int r   = idx >> 5;
        int c4  = idx & 31;
        int gk  = c4 << 2;
        int grow = row0 + r;
        float4 xv = make_float4(0.f, 0.f, 0.f, 0.f);
        if (grow < N) xv = *(const float4*)(X + (size_t)grow * 128 + gk);
        int base = r * XSTR + (gk & ~7) + ((gk >> 2) & 1);
        Xs[base + 0] = __uint_as_float(f2tf32(xv.x));
        Xs[base + 2] = __uint_as_float(f2tf32(xv.y));
        Xs[base + 4] = __uint_as_float(f2tf32(xv.z));
        Xs[base + 6] = __uint_as_float(f2tf32(xv.w));
    }

    int gc = 0;
    for (int layer = 0; layer < 3; layer++) {
        float acc[2][8][4];
#pragma unroll
        for (int mt = 0; mt < 2; mt++)
#pragma unroll
            for (int nt = 0; nt < 8; nt++)
#pragma unroll
                for (int r = 0; r < 4; r++) acc[mt][nt][r] = 0.f;

        for (int q = 0; q < 4; q++, gc++) {
            if (gc + 1 < 12) asm volatile("cp.async.wait_group 1;" ::: "memory");
            else             asm volatile("cp.async.wait_group 0;" ::: "memory");
            __syncthreads();

            const float* Wb = Wc + (gc & 1) * 5120;
            const int kg0 = q << 5;
#pragma unroll
            for (int ks = 0; ks < 4; ks++) {
                const int kb = ks * 8;
                const int kg = kg0 + kb;
                uint32_t a[2][4];
#pragma unroll
                for (int mt = 0; mt < 2; mt++) {
                    int rr = warp_m * 32 + mt * 16 + gid;
                    float2 a02 = *(const float2*)(Xs + rr * XSTR + kg + 2 * thid);
                    float2 a13 = *(const float2*)(Xs + (rr + 8) * XSTR + kg + 2 * thid);
                    a[mt][0] = __float_as_uint(a02.x);
                    a[mt][1] = __float_as_uint(a13.x);
                    a[mt][2] = __float_as_uint(a02.y);
                    a[mt][3] = __float_as_uint(a13.y);
                }
#pragma unroll
                for (int nt = 0; nt < 8; nt++) {
                    int cc_ = warp_n * 64 + nt * 8 + gid;
                    float2 bb = *(const float2*)(Wb + cc_ * WSTR + kb + 2 * thid);
                    mma_tf32(acc[0][nt], a[0], __float_as_uint(bb.x), __float_as_uint(bb.y));
                    mma_tf32(acc[1][nt], a[1], __float_as_uint(bb.x), __float_as_uint(bb.y));
                }
            }
            __syncthreads();
            if (gc + 2 < 12) issueW(gc + 2, gc & 1);
        }

        if (layer < 2) {
            int p0 = ((2 * thid) & 3) * 2 + ((2 * thid) >> 2);
            int p1 = ((2 * thid + 1) & 3) * 2 + ((2 * thid + 1) >> 2);
#pragma unroll
            for (int mt = 0; mt < 2; mt++) {
                int rloc = warp_m * 32 + mt * 16 + gid;
#pragma unroll
                for (int nt = 0; nt < 8; nt++) {
                    int grp  = warp_n * 64 + nt * 8;
                    int colL = grp + thid * 2;
                    float b0 = sb[layer * 128 + colL], b1 = sb[layer * 128 + colL + 1];
                    float v00 = fmaxf(acc[mt][nt][0] + b0, 0.f);
                    float v01 = fmaxf(acc[mt][nt][1] + b1, 0.f);
                    float v10 = fmaxf(acc[mt][nt][2] + b0, 0.f);
                    float v11 = fmaxf(acc[mt][nt][3] + b1, 0.f);
                    Xs[rloc * XSTR + grp + p0]       = __uint_as_float(f2tf32(v00));
                    Xs[rloc * XSTR + grp + p1]       = __uint_as_float(f2tf32(v01));
                    Xs[(rloc + 8) * XSTR + grp + p0] = __uint_as_float(f2tf32(v10));
                    Xs[(rloc + 8) * XSTR + grp + p1] = __uint_as_float(f2tf32(v11));
                }
            }
        } else {
#pragma unroll
            for (int mt = 0; mt < 2; mt++) {
                int rbase = row0 + warp_m * 32 + mt * 16 + gid;
#pragma unroll
                for (int nt = 0; nt < 8; nt++) {
                    int colL = warp_n * 64 + nt * 8 + thid * 2;
                    float b0 = sb[256 + colL], b1 = sb[256 + colL + 1];
                    float2 v0, v1;
                    v0.x = fmaxf(acc[mt][nt][0] + b0, 0.f);
                    v0.y = fmaxf(acc[mt][nt][1] + b1, 0.f);
                    v1.x = fmaxf(acc[mt][nt][2] + b0, 0.f);
                    v1.y = fmaxf(acc[mt][nt][3] + b1, 0.f);
                    if (rbase < N)     *(float2*)(Y + (size_t)rbase * 128 + colL)       = v0;
                    if (rbase + 8 < N) *(float2*)(Y + (size_t)(rbase + 8) * 128 + colL) = v1;
                }
            }
        }
    }
}

// ============ LSTM gate GEMM (R8) with fused pointwise epilogue ============
__global__ void __launch_bounds__(256, 2)
gemm_lstm(const float* __restrict__ X1, const float* __restrict__ X2,
          const float* __restrict__ W1, const float* __restrict__ W2,
          const float* __restrict__ pb,
          float* __restrict__ hout, float* __restrict__ c, int N)
{
    extern __shared__ float sm[];
    float* Xs = sm;            // 2 * 4608
    float* Ws = sm + 9216;     // 2 * 5120

    const int tid    = threadIdx.x;
    const int wid    = tid >> 5;
    const int lane   = tid & 31;
    const int warp_m = wid & 3;
    const int warp_n = wid >> 2;
    const int gid    = lane >> 2;
    const int thid   = lane & 3;
    const int row0   = blockIdx.x << 7;
    const int col0   = blockIdx.y << 7;
    const int Q      = 8;

    const uint32_t xaddr = smem_u32(Xs);
    const uint32_t waddr = smem_u32(Ws);

    float acc[2][8][4];
#pragma unroll
    for (int mt = 0; mt < 2; mt++)
#pragma unroll
        for (int nt = 0; nt < 8; nt++)
#pragma unroll
            for (int r = 0; r < 4; r++) acc[mt][nt][r] = 0.f;

    auto issue = [&](int q, int st) {
        const int kc = q << 5;
        const uint32_t xb = xaddr + (uint32_t)st * 4608u * 4u;
        const uint32_t wb = waddr + (uint32_t)st * 5120u * 4u;
#pragma unroll
        for (int it = 0; it < 4; it++) {
            int idx = it * 256 + tid;
            int r   = idx >> 3;
            int c4  = idx & 7;
            int gk  = kc + (c4 << 2);
            {
                int grow = row0 + r;
                const float* xp = X1;
                int sz = 0;
                if (grow < N) {
                    xp = (gk < 128) ? (X1 + (size_t)grow * 128 + gk)
                                    : (X2 + (size_t)grow * 128 + (gk - 128));
                    sz = 16;
                }
                cp_async16(xb + (uint32_t)(r * 36 + c4 * 4) * 4u, xp, sz);
            }
            {
                int gcol = col0 + r;
                const float* wp = (gk < 128) ? (W1 + (size_t)gcol * 128 + gk)
                                             : (W2 + (size_t)gcol * 128 + (gk - 128));
                cp_async16(wb + (uint32_t)(r * WSTR + c4 * 4) * 4u, wp, 16);
            }
        }
        cp_commit();
    };

    issue(0, 0);
    for (int q = 0; q < Q; q++) {
        if (q + 1 < Q) {
            issue(q + 1, (q + 1) & 1);
            asm volatile("cp.async.wait_group 1;" ::: "memory");
        } else {
            asm volatile("cp.async.wait_group 0;" ::: "memory");
        }
        __syncthreads();

        const float* Xb = Xs + (q & 1) * 4608;
        const float* Wb = Ws + (q & 1) * 5120;
#pragma unroll
        for (int ks = 0; ks < 4; ks++) {
            const int kb = ks * 8;
            uint32_t a[2][4];
#pragma unroll
            for (int mt = 0; mt < 2; mt++) {
                int rr = warp_m * 32 + mt * 16 + gid;
                a[mt][0] = f2tf32(Xb[rr * 36 + kb + thid]);
                a[mt][1] = f2tf32(Xb[(rr + 8) * 36 + kb + thid]);
                a[mt][2] = f2tf32(Xb[rr * 36 + kb + thid + 4]);
                a[mt][3] = f2tf32(Xb[(rr + 8) * 36 + kb + thid + 4]);
            }
#pragma unroll
            for (int nt = 0; nt < 8; nt++) {
                int cc_ = warp_n * 64 + nt * 8 + gid;
                float2 bb = *(const float2*)(Wb + cc_ * WSTR + kb + 2 * thid);
                mma_tf32(acc[0][nt], a[0], __float_as_uint(bb.x), __float_as_uint(bb.y));
                mma_tf32(acc[1][nt], a[1], __float_as_uint(bb.x), __float_as_uint(bb.y));
            }
        }
        __syncthreads();
    }

    const bool odd = (lane & 1);
    const int featbase = (col0 + warp_n * 64) >> 2;
#pragma unroll
    for (int mt = 0; mt < 2; mt++) {
        int rbase = row0 + warp_m * 32 + mt * 16 + gid;
#pragma unroll
        for (int nt = 0; nt < 8; nt++) {
            int colL = warp_n * 64 + nt * 8 + thid * 2;
            float b0 = pb[col0 + colL], b1 = pb[col0 + colL + 1];
            float v00 = acc[mt][nt][0] + b0;
            float v01 = acc[mt][nt][1] + b1;
            float v10 = acc[mt][nt][2] + b0;
            float v11 = acc[mt][nt][3] + b1;
            float s0 = odd ? v00 : v10;
            float s1 = odd ? v01 : v11;
            float t0 = __shfl_xor_sync(0xFFFFFFFFu, s0, 1);
            float t1 = __shfl_xor_sync(0xFFFFFFFFu, s1, 1);
            float gi = odd ? t0 : v00;
            float gf = odd ? t1 : v01;
            float gg = odd ? v10 : t0;
            float go = odd ? v11 : t1;
            int row  = rbase + (odd ? 8 : 0);
            int feat = featbase + nt * 2 + (thid >> 1);
            if (row < N) {
                size_t o = (size_t)row * 128 + feat;
                float cp = c[o];
                float cn = sigmoidf(gf) * cp + sigmoidf(gi) * tanhf(gg);
                hout[o] = sigmoidf(go) * tanhf(cn);
                c[o] = fmaxf(cn, 0.f);
            }
        }
    }
}

// ---------------- CSR gather: m[dst] = sum_a t_a[srcs] + sum_b t_b[srcs] ----------------
__global__ void gather2(const float* __restrict__ ta, const int* __restrict__ offa,
                        const int* __restrict__ csra,
                        const float* __restrict__ tb, const int* __restrict__ offb,
                        const int* __restrict__ csrb,
                        float* __restrict__ m, int N)
{
    int gw   = (blockIdx.x * blockDim.x + threadIdx.x) >> 5;
    int lane = threadIdx.x & 31;
    if (gw >= N) return;
    float4 acc = make_float4(0.f, 0.f, 0.f, 0.f);
    int s0 = gw ? offa[gw - 1] : 0;
    int e0 = offa[gw];
    for (int e = s0; e < e0; e++) {
        int src = csra[e];
        float4 v = *(const float4*)(ta + (size_t)src * 128 + lane * 4);
        acc.x += v.x; acc.y += v.y; acc.z += v.z; acc.w += v.w;
    }
    int s1 = gw ? offb[gw - 1] : 0;
    int e1 = offb[gw];
    for (int e = s1; e < e1; e++) {
        int src = csrb[e];
        float4 v = *(const float4*)(tb + (size_t)src * 128 + lane * 4);
        acc.x += v.x; acc.y += v.y; acc.z += v.z; acc.w += v.w;
    }
    *(float4*)(m + (size_t)gw * 128 + lane * 4) = acc;
}

// ---------------- attention pooling ----------------
__global__ void pool_reset(unsigned* maxu, float* sum, float* red) {
    if (threadIdx.x == 0) { *maxu = 0u; *sum = 0.f; }
    if (threadIdx.x < HDIM) red[threadIdx.x] = 0.f;
}

__global__ void gate_logits(const float* __restrict__ cc, const float* __restrict__ gW,
                            const float* __restrict__ gb, float* __restrict__ z,
                            unsigned* __restrict__ maxu, int n)
{
    __shared__ float smax[8];
    int gw   = (blockIdx.x * blockDim.x + threadIdx.x) >> 5;
    int lane = threadIdx.x & 31;
    int wid  = threadIdx.x >> 5;
    float myz = -1e30f;
    if (gw < n) {
        float4 a = *(const float4*)(cc + (size_t)gw * HDIM + lane * 4);
        float4 b = *(const float4*)(gW + lane * 4);
        float p = a.x * b.x + a.y * b.y + a.z * b.z + a.w * b.w;
        p += __shfl_down_sync(0xFFFFFFFFu, p, 16);
        p += __shfl_down_sync(0xFFFFFFFFu, p, 8);
        p += __shfl_down_sync(0xFFFFFFFFu, p, 4);
        p += __shfl_down_sync(0xFFFFFFFFu, p, 2);
        p += __shfl_down_sync(0xFFFFFFFFu, p, 1);
        if (lane == 0) {
            myz = p + gb[0];
            z[gw] = myz;
        }
    }
    if (lane == 0) smax[wid] = myz;
    __syncthreads();
    if (threadIdx.x == 0) {
        float mx = smax[0];
#pragma unroll
        for (int w = 1; w < 8; w++) mx = fmaxf(mx, smax[w]);
        atomicMax(maxu, f2ord(mx));
    }
}

__global__ void softmax_accum(const float* __restrict__ cc, const float* __restrict__ z,
                              const unsigned* __restrict__ maxu,
                              float* __restrict__ sum, float* __restrict__ red, int n)
{
    int t = threadIdx.x;
    float zmax = ord2f(*maxu);
    int c0 = blockIdx.x * 64;
    float acc = 0.f, wsum = 0.f;
    for (int i = 0; i < 64; i++) {
        int c = c0 + i;
        if (c >= n) break;
        float w = expf(z[c] - zmax);
        acc  += w * cc[(size_t)c * HDIM + t];
        wsum += w;
    }
    atomicAdd(&red[t], acc);
    if (t == 0) atomicAdd(sum, wsum);
}

__global__ void final_mlp(const float* __restrict__ red, const float* __restrict__ sum,
                          const float* __restrict__ mW1, const float* __restrict__ mb1,
                          const float* __restrict__ mW2, const float* __restrict__ mb2,
                          const float* __restrict__ mW3, const float* __restrict__ mb3,
                          float* __restrict__ out)
{
    __shared__ float x0[HDIM], x1[HDIM], x2[HDIM];
    int t = threadIdx.x;
    x0[t] = red[t] / (*sum);
    __syncthreads();
    {
        float a = mb1[t];
        for (int k = 0; k < HDIM; k++) a = fmaf(x0[k], mW1[t * HDIM + k], a);
        x1[t] = fmaxf(a, 0.f);
    }
    __syncthreads();
    {
        float a = mb2[t];
        for (int k = 0; k < HDIM; k++) a = fmaf(x1[k], mW2[t * HDIM + k], a);
        x2[t] = fmaxf(a, 0.f);
    }
    __syncthreads();
    if (t < 2) {
        float a = mb3[t];
        for (int k = 0; k < HDIM; k++) a = fmaf(x2[k], mW3[t * HDIM + k], a);
        out[t] = a;
    }
}

// ---------------- host orchestration ----------------
#define MLP_SMEM  (28032 * 4)    // 112128 bytes -> 2 CTAs/SM
#define LSTM_SMEM (19456 * 4)    // 77824 bytes  -> 2 CTAs/SM

static void build_csr(const int* src, const int* dst, int* off, int* csr,
                      int* cnt, int* part, int Ndst)
{
    cudaMemsetAsync(cnt, 0, (size_t)Ndst * sizeof(int));
    hist_k<<<(NEDG + 255) / 256, 256>>>(dst, cnt, NEDG);
    int NB = (Ndst + 1023) / 1024;
    scan1_k<<<NB, 1024>>>(cnt, off, part, Ndst);
    scan2_k<<<1, 512>>>(part, NB);
    scan3_k<<<NB, 1024>>>(off, part, Ndst);
    fill_k<<<(NEDG + 255) / 256, 256>>>(src, dst, off, csr, NEDG);
}

extern "C" void kernel_launch(void* const* d_in, const int* in_sizes, int n_in,
                              void* d_out, int out_size)
{
    const int*   var_x    = (const int*)  d_in[0];
    const int*   clause_x = (const int*)  d_in[1];
    const int*   pos_src  = (const int*)  d_in[2];
    const int*   pos_dst  = (const int*)  d_in[3];
    const int*   neg_src  = (const int*)  d_in[4];
    const int*   neg_dst  = (const int*)  d_in[5];
    const int*   posr_src = (const int*)  d_in[6];
    const int*   posr_dst = (const int*)  d_in[7];
    const int*   negr_src = (const int*)  d_in[8];
    const int*   negr_dst = (const int*)  d_in[9];
    const float* embed    = (const float*)d_in[10];
    const float* eW1      = (const float*)d_in[11];
    const float* eb1      = (const float*)d_in[12];
    const float* eW2      = (const float*)d_in[13];
    const float* eb2      = (const float*)d_in[14];
    const float* eW3      = (const float*)d_in[15];
    const float* eb3      = (const float*)d_in[16];
    const float* Wih      = (const float*)d_in[17];
    const float* Whh      = (const float*)d_in[18];
    const float* bih      = (const float*)d_in[19];
    const float* bhh      = (const float*)d_in[20];
    const float* gW       = (const float*)d_in[21];
    const float* gb       = (const float*)d_in[22];
    const float* mW1      = (const float*)d_in[23];
    const float* mb1      = (const float*)d_in[24];
    const float* mW2      = (const float*)d_in[25];
    const float* mb2      = (const float*)d_in[26];
    const float* mW3      = (const float*)d_in[27];
    const float* mb3      = (const float*)d_in[28];
    float* out = (float*)d_out;

    cudaFuncSetAttribute(mlp3_fused, cudaFuncAttributeMaxDynamicSharedMemorySize, MLP_SMEM);
    cudaFuncSetAttribute(gemm_lstm, cudaFuncAttributeMaxDynamicSharedMemorySize, LSTM_SMEM);

    float *hv, *hv2, *cv, *hc, *hc2, *cc, *t1, *t2, *m, *z, *red, *sum, *wr;
    unsigned* maxu;
    int *off, *csr, *cnt, *part;
    cudaGetSymbolAddress((void**)&hv,   g_hv);
    cudaGetSymbolAddress((void**)&hv2,  g_hv2);
    cudaGetSymbolAddress((void**)&cv,   g_cv);
    cudaGetSymbolAddress((void**)&hc,   g_hc);
    cudaGetSymbolAddress((void**)&hc2,  g_hc2);
    cudaGetSymbolAddress((void**)&cc,   g_cc);
    cudaGetSymbolAddress((void**)&t1,   g_t1);
    cudaGetSymbolAddress((void**)&t2,   g_t2);
    cudaGetSymbolAddress((void**)&m,    g_m);
    cudaGetSymbolAddress((void**)&z,    g_z);
    cudaGetSymbolAddress((void**)&red,  g_red);
    cudaGetSymbolAddress((void**)&sum,  g_sum);
    cudaGetSymbolAddress((void**)&maxu, g_maxu);
    cudaGetSymbolAddress((void**)&wr,   g_wr);
    cudaGetSymbolAddress((void**)&off,  g_off);
    cudaGetSymbolAddress((void**)&csr,  g_csr);
    cudaGetSymbolAddress((void**)&cnt,  g_cnt);
    cudaGetSymbolAddress((void**)&part, g_part);

    int* off_e[4] = {off, off + NCLS, off + 2 * NCLS, off + 3 * NCLS};
    int* csr_e[4] = {csr, csr + NEDG, csr + 2 * NEDG, csr + 3 * NEDG};

    const int HH = HDIM * HDIM;
    const float* E1 = wr + OFF_E1;
    const float* E2 = wr + OFF_E2;
    const float* E3 = wr + OFF_E3;
    const float* WIH = wr + OFF_WIH;
    const float* WHH = wr + OFF_WHH;
    const float* PB  = wr + OFF_PB;

    const int vgrid = (NVAR + 127) / 128;   // 782
    const int cgrid = (NCLS + 127) / 128;   // 3125

    // launch #1: fused weight prep
    prep_all<<<(PREP_N + 255) / 256, 256>>>(eW1, eW2, eW3, Wih, Whh, bih, bhh, wr);
    // launches #2-3
    init_embed<<<(NVAR * HDIM + 255) / 256, 256>>>(var_x,    embed, hv, cv, NVAR);
    init_embed<<<(NCLS * HDIM + 255) / 256, 256>>>(clause_x, embed, hc, cc, NCLS);

    float* hcs[2] = {hc, hc2};
    float* hvs[2] = {hv, hv2};
    int hci = 0, hvi = 0;

    for (int s = 0; s < NSTEPS; s++) {
        // ---- relation 0: var -> clause ----
        // launches #4, #5 on step 0 -> ncu samples mlp3_fused
        mlp3_fused<<<vgrid, 256, MLP_SMEM>>>(cv, E1 + 0 * HH, E2 + 0 * HH, E3 + 0 * HH,
                                             eb1 + 0 * HDIM, eb2 + 0 * HDIM, eb3 + 0 * HDIM,
                                             t1, NVAR);
        mlp3_fused<<<vgrid, 256, MLP_SMEM>>>(cv, E1 + 1 * HH, E2 + 1 * HH, E3 + 1 * HH,
                                             eb1 + 1 * HDIM, eb2 + 1 * HDIM, eb3 + 1 * HDIM,
                                             t2, NVAR);
        if (s == 0) {   // CSR build (independent of the MLPs; captured once in the graph)
            build_csr(pos_src,  pos_dst,  off_e[0], csr_e[0], cnt, part, NCLS);
            build_csr(neg_src,  neg_dst,  off_e[1], csr_e[1], cnt, part, NCLS);
            build_csr(posr_src, posr_dst, off_e[2], csr_e[2], cnt, part, NVAR);
            build_csr(negr_src, negr_dst, off_e[3], csr_e[3], cnt, part, NVAR);
        }
        gather2<<<(NCLS * 32 + 255) / 256, 256>>>(t1, off_e[0], csr_e[0],
                                                  t2, off_e[1], csr_e[1], m, NCLS);
        {
            dim3 grid(cgrid, 4);
            gemm_lstm<<<grid, 256, LSTM_SMEM>>>(m, hcs[hci], WIH, WHH, PB,
                                                hcs[hci ^ 1], cc, NCLS);
            hci ^= 1;
        }

        // ---- relation 1: clause -> var ----
        mlp3_fused<<<cgrid, 256, MLP_SMEM>>>(cc, E1 + 2 * HH, E2 + 2 * HH, E3 + 2 * HH,
                                             eb1 + 2 * HDIM, eb2 + 2 * HDIM, eb3 + 2 * HDIM,
                                             t1, NCLS);
        mlp3_fused<<<cgrid, 256, MLP_SMEM>>>(cc, E1 + 3 * HH, E2 + 3 * HH, E3 + 3 * HH,
                                             eb1 + 3 * HDIM, eb2 + 3 * HDIM, eb3 + 3 * HDIM,
                                             t2, NCLS);
        gather2<<<(NVAR * 32 + 255) / 256, 256>>>(t1, off_e[2], csr_e[2],
                                                  t2, off_e[3], csr_e[3], m, NVAR);
        {
            dim3 grid(vgrid, 4);
            gemm_lstm<<<grid, 256, LSTM_SMEM>>>(m, hvs[hvi], WIH + 65536, WHH + 65536,
                                                PB + 512, hvs[hvi ^ 1], cv, NVAR);
            hvi ^= 1;
        }
    }

    // ---- GlobalAttentionPooling + final MLP ----
    pool_reset<<<1, 128>>>(maxu, sum, red);
    gate_logits<<<(NCLS * 32 + 255) / 256, 256>>>(cc, gW, gb, z, maxu, NCLS);
    softmax_accum<<<(NCLS + 63) / 64, 128>>>(cc, z, maxu, sum, red, NCLS);
    final_mlp<<<1, 128>>>(red, sum, mW1, mb1, mW2, mb2, mW3, mb3, out);
}

// round 10
// speedup vs baseline: 1.1687x; 1.0441x over previous
#include <cuda_runtime.h>
#include <math.h>
#include <stdint.h>

#define NVAR   100000
#define NCLS   400000
#define NEDG   600000
#define HDIM   128
#define NSTEPS 9

// ---------------- scratch (device globals) ----------------
__device__ float g_hv [NVAR * HDIM];
__device__ float g_hv2[NVAR * HDIM];
__device__ float g_cv [NVAR * HDIM];
__device__ float g_hc [NCLS * HDIM];
__device__ float g_hc2[NCLS * HDIM];
__device__ float g_cc [NCLS * HDIM];
__device__ float g_t1 [NCLS * HDIM];
__device__ float g_t2 [NCLS * HDIM];
__device__ float g_m  [NCLS * HDIM];
__device__ float g_z  [NCLS];
__device__ float    g_red[HDIM];
__device__ float    g_sum;
__device__ unsigned g_maxu;
// tf32-rounded, FRAGMENT-MAJOR weights: eW1 | eW2 | eW3 | Wih' | Whh' | pbias
#define OFF_E1  0
#define OFF_E2  65536
#define OFF_E3  131072
#define OFF_WIH 196608
#define OFF_WHH 327680
#define OFF_PB  458752
#define PREP_N  459776
__device__ float g_wr[PREP_N];
// CSR (per etype): off becomes INCLUSIVE prefix after fill; csr holds src ids
__device__ int g_off[4][NCLS];
__device__ int g_csr[4][NEDG];
__device__ int g_cnt[NCLS];
__device__ int g_part[512];

// ---------------- helpers ----------------
__device__ __forceinline__ unsigned f2ord(float f) {
    unsigned b = __float_as_uint(f);
    return (b & 0x80000000u) ? ~b : (b | 0x80000000u);
}
__device__ __forceinline__ float ord2f(unsigned u) {
    unsigned b = (u & 0x80000000u) ? (u ^ 0x80000000u) : ~u;
    return __uint_as_float(b);
}
__device__ __forceinline__ float sigmoidf(float x) { return 1.0f / (1.0f + expf(-x)); }

__device__ __forceinline__ uint32_t f2tf32(float f) {
    uint32_t o;
    asm("cvt.rna.tf32.f32 %0, %1;" : "=r"(o) : "f"(f));
    return o;
}
__device__ __forceinline__ float rtf(float f) { return __uint_as_float(f2tf32(f)); }

__device__ __forceinline__ uint32_t smem_u32(const void* p) {
    uint32_t a;
    asm("{ .reg .u64 t; cvta.to.shared.u64 t, %1; cvt.u32.u64 %0, t; }" : "=r"(a) : "l"(p));
    return a;
}
__device__ __forceinline__ void cp_async16(uint32_t dst, const void* src, int srcbytes) {
    asm volatile("cp.async.cg.shared.global [%0], [%1], 16, %2;"
                 :: "r"(dst), "l"(src), "r"(srcbytes) : "memory");
}
__device__ __forceinline__ void cp_commit() {
    asm volatile("cp.async.commit_group;" ::: "memory");
}
__device__ __forceinline__ void mma_tf32(float* c, const uint32_t* a, uint32_t b0, uint32_t b1) {
    asm volatile(
        "mma.sync.aligned.m16n8k8.row.col.f32.tf32.tf32.f32 "
        "{%0,%1,%2,%3}, {%4,%5,%6,%7}, {%8,%9}, {%0,%1,%2,%3};"
        : "+f"(c[0]), "+f"(c[1]), "+f"(c[2]), "+f"(c[3])
        : "r"(a[0]), "r"(a[1]), "r"(a[2]), "r"(a[3]), "r"(b0), "r"(b1));
}

// ---------------- ONE fused weight-prep kernel (fragment-major layouts) ----------------
// MLP W block (per etype, 16384 floats): off = (q*16+g)*64 + gid*8 + thid*2 + khalf
//   q=k>>3, g=row>>3, gid=row&7, thid=k&3, khalf=(k>>2)&1
// LSTM W block (per rel, 65536): rows gate-permuted (r_new=4f+gate), Ng=64:
//   off = (q*64+gno)*64 + gid*8 + thid*2 + khalf
__global__ void prep_all(const float* __restrict__ eW1, const float* __restrict__ eW2,
                         const float* __restrict__ eW3, const float* __restrict__ Wih,
                         const float* __restrict__ Whh, const float* __restrict__ bih,
                         const float* __restrict__ bhh, float* __restrict__ wr)
{
    int i = blockIdx.x * blockDim.x + threadIdx.x;
    if (i >= PREP_N) return;
    if (i < 196608) {               // eW1|eW2|eW3
        const float* src = (i < 65536) ? eW1 : (i < 131072) ? eW2 : eW3;
        int base = (i < 65536) ? OFF_E1 : (i < 131072) ? OFF_E2 : OFF_E3;
        int j = i & 65535;
        int etype = j >> 14;
        int rem = j & 16383;
        int row = rem >> 7, k = rem & 127;
        int out = ((k >> 3) * 16 + (row >> 3)) * 64 + (row & 7) * 8 + (k & 3) * 2 + ((k >> 2) & 1);
        wr[base + (etype << 14) + out] = rtf(src[j]);
    } else if (i < 458752) {        // Wih' | Whh'
        int j = i - 196608;
        const float* src = (j < 131072) ? Wih : Whh;
        int base = (j < 131072) ? OFF_WIH : OFF_WHH;
        j &= 131071;
        int rel = j >> 16;
        int rem = j & 65535;
        int r_old = rem >> 7, k = rem & 127;
        int gate = r_old >> 7, f = r_old & 127;
        int r_new = (f << 2) | gate;
        int out = ((k >> 3) * 64 + (r_new >> 3)) * 64 + (r_new & 7) * 8 + (k & 3) * 2 + ((k >> 2) & 1);
        wr[base + (rel << 16) + out] = rtf(src[j]);
    } else {                        // permuted bias sum
        int j = i - 458752;
        int rel = j >> 9;
        int r_old = j & 511;
        int gate = r_old >> 7, f = r_old & 127;
        wr[OFF_PB + (rel << 9) + (f << 2) + gate] = bih[j] + bhh[j];
    }
}

// ---------------- CSR build kernels ----------------
__global__ void hist_k(const int* __restrict__ dst, int* __restrict__ cnt, int E) {
    int i = blockIdx.x * blockDim.x + threadIdx.x;
    if (i < E) atomicAdd(&cnt[dst[i]], 1);
}
__global__ void scan1_k(const int* __restrict__ cnt, int* __restrict__ off,
                        int* __restrict__ part, int N) {
    __shared__ int s[1024];
    int i = blockIdx.x * 1024 + threadIdx.x;
    int v = (i < N) ? cnt[i] : 0;
    s[threadIdx.x] = v;
    __syncthreads();
    for (int d = 1; d < 1024; d <<= 1) {
        int t = (threadIdx.x >= d) ? s[threadIdx.x - d] : 0;
        __syncthreads();
        s[threadIdx.x] += t;
        __syncthreads();
    }
    if (i < N) off[i] = s[threadIdx.x] - v;
    if (threadIdx.x == 1023) part[blockIdx.x] = s[1023];
}
__global__ void scan2_k(int* __restrict__ part, int NB) {
    __shared__ int s[512];
    int v = (threadIdx.x < NB) ? part[threadIdx.x] : 0;
    s[threadIdx.x] = v;
    __syncthreads();
    for (int d = 1; d < 512; d <<= 1) {
        int t = (threadIdx.x >= d) ? s[threadIdx.x - d] : 0;
        __syncthreads();
        s[threadIdx.x] += t;
        __syncthreads();
    }
    if (threadIdx.x < NB) part[threadIdx.x] = s[threadIdx.x] - v;
}
__global__ void scan3_k(int* __restrict__ off, const int* __restrict__ part, int N) {
    int i = blockIdx.x * 1024 + threadIdx.x;
    if (i < N) off[i] += part[blockIdx.x];
}
__global__ void fill_k(const int* __restrict__ src, const int* __restrict__ dst,
                       int* __restrict__ off, int* __restrict__ csr, int E) {
    int i = blockIdx.x * blockDim.x + threadIdx.x;
    if (i >= E) return;
    int p = atomicAdd(&off[dst[i]], 1);
    csr[p] = src[i];
}

// ---------------- init: h = rounded embed, c = embed ----------------
__global__ void init_embed(const int* __restrict__ x, const float* __restrict__ embed,
                           float* __restrict__ h, float* __restrict__ c, int n) {
    int i = blockIdx.x * blockDim.x + threadIdx.x;
    if (i >= n * HDIM) return;
    int node = i >> 7, col = i & 127;
    float v = embed[x[node] * HDIM + col];
    h[i] = rtf(v);     // h only feeds the LSTM GEMM (A operand) -> pre-round
    c[i] = v;
}

// ============ fused 3-layer MLP: fragment-major X & W ============
// Smem: Xs[16384] fragment-major w/ XOR-q swizzle | Wc[2][4096] | sb[384]
__global__ void __launch_bounds__(256, 2)
mlp3_fused(const float* __restrict__ X,
           const float* __restrict__ W1l, const float* __restrict__ W2l,
           const float* __restrict__ W3l,
           const float* __restrict__ B1, const float* __restrict__ B2,
           const float* __restrict__ B3,
           float* __restrict__ Y, int N)
{
    extern __shared__ float sm[];
    float* Xs = sm;                   // 16384
    float* Wc = sm + 16384;           // 2*4096
    float* sb = sm + 24576;           // 384

    const int tid    = threadIdx.x;
    const int wid    = tid >> 5;
    const int lane   = tid & 31;
    const int warp_m = wid & 3;
    const int warp_n = wid >> 2;
    const int gid    = lane >> 2;
    const int thid   = lane & 3;
    const int row0   = blockIdx.x << 7;

    const uint32_t wcaddr = smem_u32(Wc);
    const float* WL[3] = {W1l, W2l, W3l};

    if (tid < 128) {
        sb[tid]       = B1[tid];
        sb[128 + tid] = B2[tid];
        sb[256 + tid] = B3[tid];
    }

    auto issueW = [&](int g, int st) {
        const float* Wl = WL[g >> 2] + (g & 3) * 4096;
#pragma unroll
        for (int it = 0; it < 4; it++) {
            int idx = it * 256 + tid;      // 0..1023 float4
            cp_async16(wcaddr + (uint32_t)(st * 4096 + idx * 4) * 4u, Wl + idx * 4, 16);
        }
        cp_commit();
    };

    issueW(0, 0);
    issueW(1, 1);

    // prologue: X tile -> smem, tf32-rounded, fragment-major (+XOR-q swizzle)
#pragma unroll
    for (int it = 0; it < 16; it++) {
        int idx = it * 256 + tid;      // 0..4095
        int r   = idx >> 5;            // 0..127
        int c4  = idx & 31;            // 0..31
        int gk  = c4 << 2;
        int grow = row0 + r;
        float4 xv = make_float4(0.f, 0.f, 0.f, 0.f);
        if (grow < N) xv = *(const float4*)(X + (size_t)grow * 128 + gk);
        int q     = gk >> 3;
        int reg   = ((r >> 3) & 1) + 2 * ((gk >> 2) & 1);
        int sbase = (q * 8 + (r >> 4)) * 32;
        int sw    = q & 7;
        int lb    = (r & 7) * 4;
        Xs[(sbase + ((lb + 0) ^ sw)) * 4 + reg] = rtf(xv.x);
        Xs[(sbase + ((lb + 1) ^ sw)) * 4 + reg] = rtf(xv.y);
        Xs[(sbase + ((lb + 2) ^ sw)) * 4 + reg] = rtf(xv.z);
        Xs[(sbase + ((lb + 3) ^ sw)) * 4 + reg] = rtf(xv.w);
    }

    int gc = 0;
    for (int layer = 0; layer < 3; layer++) {
        float acc[2][8][4];
#pragma unroll
        for (int mt = 0; mt < 2; mt++)
#pragma unroll
            for (int nt = 0; nt < 8; nt++)
#pragma unroll
                for (int r = 0; r < 4; r++) acc[mt][nt][r] = 0.f;

        for (int qc = 0; qc < 4; qc++, gc++) {
            if (gc + 1 < 12) asm volatile("cp.async.wait_group 1;" ::: "memory");
            else             asm volatile("cp.async.wait_group 0;" ::: "memory");
            __syncthreads();

            const float* Wb = Wc + (gc & 1) * 4096;
#pragma unroll
            for (int ks = 0; ks < 4; ks++) {
                const int q  = qc * 4 + ks;
                const int sw = q & 7;
                uint32_t a[2][4];
#pragma unroll
                for (int mt = 0; mt < 2; mt++) {
                    float4 av = *(const float4*)(Xs +
                        ((q * 8 + warp_m * 2 + mt) * 32 + (lane ^ sw)) * 4);
                    a[mt][0] = __float_as_uint(av.x);
                    a[mt][1] = __float_as_uint(av.y);
                    a[mt][2] = __float_as_uint(av.z);
                    a[mt][3] = __float_as_uint(av.w);
                }
                const float* Bb = Wb + (ks * 16 + warp_n * 8) * 64 + lane * 2;
#pragma unroll
                for (int nt = 0; nt < 8; nt++) {
                    float2 bb = *(const float2*)(Bb + nt * 64);
                    mma_tf32(acc[0][nt], a[0], __float_as_uint(bb.x), __float_as_uint(bb.y));
                    mma_tf32(acc[1][nt], a[1], __float_as_uint(bb.x), __float_as_uint(bb.y));
                }
            }
            __syncthreads();
            if (gc + 2 < 12) issueW(gc + 2, gc & 1);
        }

        if (layer < 2) {
            // write outputs back into Xs as next layer's A: fragment-major + swizzle
            int kh = thid >> 1;            // khalf for both cols
            int t0 = 2 * (thid & 1);       // k-thid of even col
#pragma unroll
            for (int mt = 0; mt < 2; mt++) {
#pragma unroll
                for (int nt = 0; nt < 8; nt++) {
                    int q   = warp_n * 8 + nt;
                    int sw  = q & 7;
                    int mgb = (q * 8 + warp_m * 2 + mt) * 32;
                    int colL = warp_n * 64 + nt * 8 + thid * 2;
                    float b0 = sb[layer * 128 + colL], b1 = sb[layer * 128 + colL + 1];
                    float v00 = fmaxf(acc[mt][nt][0] + b0, 0.f);
                    float v01 = fmaxf(acc[mt][nt][1] + b1, 0.f);
                    float v10 = fmaxf(acc[mt][nt][2] + b0, 0.f);
                    float v11 = fmaxf(acc[mt][nt][3] + b1, 0.f);
                    int s0 = mgb + ((gid * 4 + t0) ^ sw);
                    int s1 = mgb + ((gid * 4 + t0 + 1) ^ sw);
                    Xs[s0 * 4 + 0 + 2 * kh] = rtf(v00);
                    Xs[s1 * 4 + 0 + 2 * kh] = rtf(v01);
                    Xs[s0 * 4 + 1 + 2 * kh] = rtf(v10);
                    Xs[s1 * 4 + 1 + 2 * kh] = rtf(v11);
                }
            }
        } else {
#pragma unroll
            for (int mt = 0; mt < 2; mt++) {
                int rbase = row0 + warp_m * 32 + mt * 16 + gid;
#pragma unroll
                for (int nt = 0; nt < 8; nt++) {
                    int colL = warp_n * 64 + nt * 8 + thid * 2;
                    float b0 = sb[256 + colL], b1 = sb[256 + colL + 1];
                    float2 v0, v1;
                    v0.x = fmaxf(acc[mt][nt][0] + b0, 0.f);
                    v0.y = fmaxf(acc[mt][nt][1] + b1, 0.f);
                    v1.x = fmaxf(acc[mt][nt][2] + b0, 0.f);
                    v1.y = fmaxf(acc[mt][nt][3] + b1, 0.f);
                    if (rbase < N)     *(float2*)(Y + (size_t)rbase * 128 + colL)       = v0;
                    if (rbase + 8 < N) *(float2*)(Y + (size_t)(rbase + 8) * 128 + colL) = v1;
                }
            }
        }
    }
}

// ============ LSTM gate GEMM: fragment-major W, pre-rounded A, fused epilogue ============
__global__ void __launch_bounds__(256, 2)
gemm_lstm(const float* __restrict__ X1, const float* __restrict__ X2,
          const float* __restrict__ W1, const float* __restrict__ W2,
          const float* __restrict__ pb,
          float* __restrict__ hout, float* __restrict__ c, int N)
{
    extern __shared__ float sm[];
    float* Xs = sm;            // 2 * 4608 (stride 36, natural K, pre-rounded tf32 bits)
    float* Ws = sm + 9216;     // 2 * 4096 (fragment-major)

    const int tid    = threadIdx.x;
    const int wid    = tid >> 5;
    const int lane   = tid & 31;
    const int warp_m = wid & 3;
    const int warp_n = wid >> 2;
    const int gid    = lane >> 2;
    const int thid   = lane & 3;
    const int row0   = blockIdx.x << 7;
    const int colblk = blockIdx.y;            // 0..3
    const int col0   = colblk << 7;
    const int Q      = 8;

    const uint32_t xaddr = smem_u32(Xs);
    const uint32_t waddr = smem_u32(Ws);

    float acc[2][8][4];
#pragma unroll
    for (int mt = 0; mt < 2; mt++)
#pragma unroll
        for (int nt = 0; nt < 8; nt++)
#pragma unroll
            for (int r = 0; r < 4; r++) acc[mt][nt][r] = 0.f;

    auto issue = [&](int q, int st) {
        const int kc = q << 5;
        const uint32_t xb = xaddr + (uint32_t)st * 4608u * 4u;
        const uint32_t wb = waddr + (uint32_t)st * 4096u * 4u;
        const float* Wl = (q < 4) ? W1 : W2;
        const int qa = q & 3;
#pragma unroll
        for (int it = 0; it < 4; it++) {
            int idx = it * 256 + tid;       // 0..1023 float4
            // X: [r 0..127][8 float4 of 32-K chunk]
            {
                int r  = idx >> 3;
                int c4 = idx & 7;
                int gk = kc + (c4 << 2);
                int grow = row0 + r;
                const float* xp = X1;
                int sz = 0;
                if (grow < N) {
                    xp = (gk < 128) ? (X1 + (size_t)grow * 128 + gk)
                                    : (X2 + (size_t)grow * 128 + (gk - 128));
                    sz = 16;
                }
                cp_async16(xb + (uint32_t)(r * 36 + c4 * 4) * 4u, xp, sz);
            }
            // W: 4 segments of 1024 floats (one per qq), linear copy
            {
                int qq     = idx >> 8;       // 0..3
                int within = idx & 255;      // float4 within segment
                const float* wp = Wl + (qa * 4 + qq) * 4096 + colblk * 1024 + within * 4;
                cp_async16(wb + (uint32_t)(qq * 1024 + within * 4) * 4u, wp, 16);
            }
        }
        cp_commit();
    };

    issue(0, 0);
    for (int q = 0; q < Q; q++) {
        if (q + 1 < Q) {
            issue(q + 1, (q + 1) & 1);
            asm volatile("cp.async.wait_group 1;" ::: "memory");
        } else {
            asm volatile("cp.async.wait_group 0;" ::: "memory");
        }
        __syncthreads();

        const float* Xb = Xs + (q & 1) * 4608;
        const float* Wb = Ws + (q & 1) * 4096;
#pragma unroll
        for (int ks = 0; ks < 4; ks++) {
            const int kb = ks * 8;
            uint32_t a[2][4];
#pragma unroll
            for (int mt = 0; mt < 2; mt++) {
                int rr = warp_m * 32 + mt * 16 + gid;
                a[mt][0] = __float_as_uint(Xb[rr * 36 + kb + thid]);
                a[mt][1] = __float_as_uint(Xb[(rr + 8) * 36 + kb + thid]);
                a[mt][2] = __float_as_uint(Xb[rr * 36 + kb + thid + 4]);
                a[mt][3] = __float_as_uint(Xb[(rr + 8) * 36 + kb + thid + 4]);
            }
            const float* Bb = Wb + (ks * 16 + warp_n * 8) * 64 + lane * 2;
#pragma unroll
            for (int nt = 0; nt < 8; nt++) {
                float2 bb = *(const float2*)(Bb + nt * 64);
                mma_tf32(acc[0][nt], a[0], __float_as_uint(bb.x), __float_as_uint(bb.y));
                mma_tf32(acc[1][nt], a[1], __float_as_uint(bb.x), __float_as_uint(bb.y));
            }
        }
        __syncthreads();
    }

    // ---- fused LSTM epilogue (even/odd lane pair exchange via shfl_xor(1)) ----
    const bool odd = (lane & 1);
    const int featbase = (col0 + warp_n * 64) >> 2;
#pragma unroll
    for (int mt = 0; mt < 2; mt++) {
        int rbase = row0 + warp_m * 32 + mt * 16 + gid;
#pragma unroll
        for (int nt = 0; nt < 8; nt++) {
            int colL = warp_n * 64 + nt * 8 + thid * 2;
            float b0 = pb[col0 + colL], b1 = pb[col0 + colL + 1];
            float v00 = acc[mt][nt][0] + b0;
            float v01 = acc[mt][nt][1] + b1;
            float v10 = acc[mt][nt][2] + b0;
            float v11 = acc[mt][nt][3] + b1;
            float s0 = odd ? v00 : v10;
            float s1 = odd ? v01 : v11;
            float t0 = __shfl_xor_sync(0xFFFFFFFFu, s0, 1);
            float t1 = __shfl_xor_sync(0xFFFFFFFFu, s1, 1);
            float gi = odd ? t0 : v00;
            float gf = odd ? t1 : v01;
            float gg = odd ? v10 : t0;
            float go = odd ? v11 : t1;
            int row  = rbase + (odd ? 8 : 0);
            int feat = featbase + nt * 2 + (thid >> 1);
            if (row < N) {
                size_t o = (size_t)row * 128 + feat;
                float cp = c[o];
                float cn = sigmoidf(gf) * cp + sigmoidf(gi) * tanhf(gg);
                hout[o] = rtf(sigmoidf(go) * tanhf(cn));   // pre-rounded for next GEMM
                c[o] = fmaxf(cn, 0.f);
            }
        }
    }
}

// ---------------- CSR gather: m[dst] = sum(t_a) + sum(t_b), output tf32-rounded ----------------
__global__ void gather2(const float* __restrict__ ta, const int* __restrict__ offa,
                        const int* __restrict__ csra,
                        const float* __restrict__ tb, const int* __restrict__ offb,
                        const int* __restrict__ csrb,
                        float* __restrict__ m, int N)
{
    int gw   = (blockIdx.x * blockDim.x + threadIdx.x) >> 5;
    int lane = threadIdx.x & 31;
    if (gw >= N) return;
    float4 acc = make_float4(0.f, 0.f, 0.f, 0.f);
    int s0 = gw ? offa[gw - 1] : 0;
    int e0 = offa[gw];
    for (int e = s0; e < e0; e++) {
        int src = csra[e];
        float4 v = *(const float4*)(ta + (size_t)src * 128 + lane * 4);
        acc.x += v.x; acc.y += v.y; acc.z += v.z; acc.w += v.w;
    }
    int s1 = gw ? offb[gw - 1] : 0;
    int e1 = offb[gw];
    for (int e = s1; e < e1; e++) {
        int src = csrb[e];
        float4 v = *(const float4*)(tb + (size_t)src * 128 + lane * 4);
        acc.x += v.x; acc.y += v.y; acc.z += v.z; acc.w += v.w;
    }
    float4 r;
    r.x = rtf(acc.x); r.y = rtf(acc.y); r.z = rtf(acc.z); r.w = rtf(acc.w);
    *(float4*)(m + (size_t)gw * 128 + lane * 4) = r;
}

// ---------------- attention pooling ----------------
__global__ void pool_reset(unsigned* maxu, float* sum, float* red) {
    if (threadIdx.x == 0) { *maxu = 0u; *sum = 0.f; }
    if (threadIdx.x < HDIM) red[threadIdx.x] = 0.f;
}

__global__ void gate_logits(const float* __restrict__ cc, const float* __restrict__ gW,
                            const float* __restrict__ gb, float* __restrict__ z,
                            unsigned* __restrict__ maxu, int n)
{
    __shared__ float smax[8];
    int gw   = (blockIdx.x * blockDim.x + threadIdx.x) >> 5;
    int lane = threadIdx.x & 31;
    int wid  = threadIdx.x >> 5;
    float myz = -1e30f;
    if (gw < n) {
        float4 a = *(const float4*)(cc + (size_t)gw * HDIM + lane * 4);
        float4 b = *(const float4*)(gW + lane * 4);
        float p = a.x * b.x + a.y * b.y + a.z * b.z + a.w * b.w;
        p += __shfl_down_sync(0xFFFFFFFFu, p, 16);
        p += __shfl_down_sync(0xFFFFFFFFu, p, 8);
        p += __shfl_down_sync(0xFFFFFFFFu, p, 4);
        p += __shfl_down_sync(0xFFFFFFFFu, p, 2);
        p += __shfl_down_sync(0xFFFFFFFFu, p, 1);
        if (lane == 0) {
            myz = p + gb[0];
            z[gw] = myz;
        }
    }
    if (lane == 0) smax[wid] = myz;
    __syncthreads();
    if (threadIdx.x == 0) {
        float mx = smax[0];
#pragma unroll
        for (int w = 1; w < 8; w++) mx = fmaxf(mx, smax[w]);
        atomicMax(maxu, f2ord(mx));
    }
}

__global__ void softmax_accum(const float* __restrict__ cc, const float* __restrict__ z,
                              const unsigned* __restrict__ maxu,
                              float* __restrict__ sum, float* __restrict__ red, int n)
{
    int t = threadIdx.x;
    float zmax = ord2f(*maxu);
    int c0 = blockIdx.x * 64;
    float acc = 0.f, wsum = 0.f;
    for (int i = 0; i < 64; i++) {
        int c = c0 + i;
        if (c >= n) break;
        float w = expf(z[c] - zmax);
        acc  += w * cc[(size_t)c * HDIM + t];
        wsum += w;
    }
    atomicAdd(&red[t], acc);
    if (t == 0) atomicAdd(sum, wsum);
}

__global__ void final_mlp(const float* __restrict__ red, const float* __restrict__ sum,
                          const float* __restrict__ mW1, const float* __restrict__ mb1,
                          const float* __restrict__ mW2, const float* __restrict__ mb2,
                          const float* __restrict__ mW3, const float* __restrict__ mb3,
                          float* __restrict__ out)
{
    __shared__ float x0[HDIM], x1[HDIM], x2[HDIM];
    int t = threadIdx.x;
    x0[t] = red[t] / (*sum);
    __syncthreads();
    {
        float a = mb1[t];
        for (int k = 0; k < HDIM; k++) a = fmaf(x0[k], mW1[t * HDIM + k], a);
        x1[t] = fmaxf(a, 0.f);
    }
    __syncthreads();
    {
        float a = mb2[t];
        for (int k = 0; k < HDIM; k++) a = fmaf(x1[k], mW2[t * HDIM + k], a);
        x2[t] = fmaxf(a, 0.f);
    }
    __syncthreads();
    if (t < 2) {
        float a = mb3[t];
        for (int k = 0; k < HDIM; k++) a = fmaf(x2[k], mW3[t * HDIM + k], a);
        out[t] = a;
    }
}

// ---------------- host orchestration ----------------
#define MLP_SMEM  (24960 * 4)    // 99840 bytes  -> 2 CTAs/SM
#define LSTM_SMEM (17408 * 4)    // 69632 bytes  -> 2 CTAs/SM

static void build_csr(const int* src, const int* dst, int* off, int* csr,
                      int* cnt, int* part, int Ndst)
{
    cudaMemsetAsync(cnt, 0, (size_t)Ndst * sizeof(int));
    hist_k<<<(NEDG + 255) / 256, 256>>>(dst, cnt, NEDG);
    int NB = (Ndst + 1023) / 1024;
    scan1_k<<<NB, 1024>>>(cnt, off, part, Ndst);
    scan2_k<<<1, 512>>>(part, NB);
    scan3_k<<<NB, 1024>>>(off, part, Ndst);
    fill_k<<<(NEDG + 255) / 256, 256>>>(src, dst, off, csr, NEDG);
}

extern "C" void kernel_launch(void* const* d_in, const int* in_sizes, int n_in,
                              void* d_out, int out_size)
{
    const int*   var_x    = (const int*)  d_in[0];
    const int*   clause_x = (const int*)  d_in[1];
    const int*   pos_src  = (const int*)  d_in[2];
    const int*   pos_dst  = (const int*)  d_in[3];
    const int*   neg_src  = (const int*)  d_in[4];
    const int*   neg_dst  = (const int*)  d_in[5];
    const int*   posr_src = (const int*)  d_in[6];
    const int*   posr_dst = (const int*)  d_in[7];
    const int*   negr_src = (const int*)  d_in[8];
    const int*   negr_dst = (const int*)  d_in[9];
    const float* embed    = (const float*)d_in[10];
    const float* eW1      = (const float*)d_in[11];
    const float* eb1      = (const float*)d_in[12];
    const float* eW2      = (const float*)d_in[13];
    const float* eb2      = (const float*)d_in[14];
    const float* eW3      = (const float*)d_in[15];
    const float* eb3      = (const float*)d_in[16];
    const float* Wih      = (const float*)d_in[17];
    const float* Whh      = (const float*)d_in[18];
    const float* bih      = (const float*)d_in[19];
    const float* bhh      = (const float*)d_in[20];
    const float* gW       = (const float*)d_in[21];
    const float* gb       = (const float*)d_in[22];
    const float* mW1      = (const float*)d_in[23];
    const float* mb1      = (const float*)d_in[24];
    const float* mW2      = (const float*)d_in[25];
    const float* mb2      = (const float*)d_in[26];
    const float* mW3      = (const float*)d_in[27];
    const float* mb3      = (const float*)d_in[28];
    float* out = (float*)d_out;

    cudaFuncSetAttribute(mlp3_fused, cudaFuncAttributeMaxDynamicSharedMemorySize, MLP_SMEM);
    cudaFuncSetAttribute(gemm_lstm, cudaFuncAttributeMaxDynamicSharedMemorySize, LSTM_SMEM);

    float *hv, *hv2, *cv, *hc, *hc2, *cc, *t1, *t2, *m, *z, *red, *sum, *wr;
    unsigned* maxu;
    int *off, *csr, *cnt, *part;
    cudaGetSymbolAddress((void**)&hv,   g_hv);
    cudaGetSymbolAddress((void**)&hv2,  g_hv2);
    cudaGetSymbolAddress((void**)&cv,   g_cv);
    cudaGetSymbolAddress((void**)&hc,   g_hc);
    cudaGetSymbolAddress((void**)&hc2,  g_hc2);
    cudaGetSymbolAddress((void**)&cc,   g_cc);
    cudaGetSymbolAddress((void**)&t1,   g_t1);
    cudaGetSymbolAddress((void**)&t2,   g_t2);
    cudaGetSymbolAddress((void**)&m,    g_m);
    cudaGetSymbolAddress((void**)&z,    g_z);
    cudaGetSymbolAddress((void**)&red,  g_red);
    cudaGetSymbolAddress((void**)&sum,  g_sum);
    cudaGetSymbolAddress((void**)&maxu, g_maxu);
    cudaGetSymbolAddress((void**)&wr,   g_wr);
    cudaGetSymbolAddress((void**)&off,  g_off);
    cudaGetSymbolAddress((void**)&csr,  g_csr);
    cudaGetSymbolAddress((void**)&cnt,  g_cnt);
    cudaGetSymbolAddress((void**)&part, g_part);

    int* off_e[4] = {off, off + NCLS, off + 2 * NCLS, off + 3 * NCLS};
    int* csr_e[4] = {csr, csr + NEDG, csr + 2 * NEDG, csr + 3 * NEDG};

    const float* E1 = wr + OFF_E1;
    const float* E2 = wr + OFF_E2;
    const float* E3 = wr + OFF_E3;
    const float* WIH = wr + OFF_WIH;
    const float* WHH = wr + OFF_WHH;
    const float* PB  = wr + OFF_PB;

    const int vgrid = (NVAR + 127) / 128;   // 782
    const int cgrid = (NCLS + 127) / 128;   // 3125
    const int EB = 16384;                    // per-etype weight block (floats)

    prep_all<<<(PREP_N + 255) / 256, 256>>>(eW1, eW2, eW3, Wih, Whh, bih, bhh, wr);
    init_embed<<<(NVAR * HDIM + 255) / 256, 256>>>(var_x,    embed, hv, cv, NVAR);
    init_embed<<<(NCLS * HDIM + 255) / 256, 256>>>(clause_x, embed, hc, cc, NCLS);

    float* hcs[2] = {hc, hc2};
    float* hvs[2] = {hv, hv2};
    int hci = 0, hvi = 0;

    for (int s = 0; s < NSTEPS; s++) {
        // ---- relation 0: var -> clause ----
        mlp3_fused<<<vgrid, 256, MLP_SMEM>>>(cv, E1 + 0 * EB, E2 + 0 * EB, E3 + 0 * EB,
                                             eb1 + 0 * HDIM, eb2 + 0 * HDIM, eb3 + 0 * HDIM,
                                             t1, NVAR);
        mlp3_fused<<<vgrid, 256, MLP_SMEM>>>(cv, E1 + 1 * EB, E2 + 1 * EB, E3 + 1 * EB,
                                             eb1 + 1 * HDIM, eb2 + 1 * HDIM, eb3 + 1 * HDIM,
                                             t2, NVAR);
        if (s == 0) {
            build_csr(pos_src,  pos_dst,  off_e[0], csr_e[0], cnt, part, NCLS);
            build_csr(neg_src,  neg_dst,  off_e[1], csr_e[1], cnt, part, NCLS);
            build_csr(posr_src, posr_dst, off_e[2], csr_e[2], cnt, part, NVAR);
            build_csr(negr_src, negr_dst, off_e[3], csr_e[3], cnt, part, NVAR);
        }
        gather2<<<(NCLS * 32 + 255) / 256, 256>>>(t1, off_e[0], csr_e[0],
                                                  t2, off_e[1], csr_e[1], m, NCLS);
        {
            dim3 grid(cgrid, 4);
            gemm_lstm<<<grid, 256, LSTM_SMEM>>>(m, hcs[hci], WIH, WHH, PB,
                                                hcs[hci ^ 1], cc, NCLS);
            hci ^= 1;
        }

        // ---- relation 1: clause -> var ----
        mlp3_fused<<<cgrid, 256, MLP_SMEM>>>(cc, E1 + 2 * EB, E2 + 2 * EB, E3 + 2 * EB,
                                             eb1 + 2 * HDIM, eb2 + 2 * HDIM, eb3 + 2 * HDIM,
                                             t1, NCLS);
        mlp3_fused<<<cgrid, 256, MLP_SMEM>>>(cc, E1 + 3 * EB, E2 + 3 * EB, E3 + 3 * EB,
                                             eb1 + 3 * HDIM, eb2 + 3 * HDIM, eb3 + 3 * HDIM,
                                             t2, NCLS);
        gather2<<<(NVAR * 32 + 255) / 256, 256>>>(t1, off_e[2], csr_e[2],
                                                  t2, off_e[3], csr_e[3], m, NVAR);
        {
            dim3 grid(vgrid, 4);
            gemm_lstm<<<grid, 256, LSTM_SMEM>>>(m, hvs[hvi], WIH + 65536, WHH + 65536,
                                                PB + 512, hvs[hvi ^ 1], cv, NVAR);
            hvi ^= 1;
        }
    }

    // ---- GlobalAttentionPooling + final MLP ----
    pool_reset<<<1, 128>>>(maxu, sum, red);
    gate_logits<<<(NCLS * 32 + 255) / 256, 256>>>(cc, gW, gb, z, maxu, NCLS);
    softmax_accum<<<(NCLS + 63) / 64, 128>>>(cc, z, maxu, sum, red, NCLS);
    final_mlp<<<1, 128>>>(red, sum, mW1, mb1, mW2, mb2, mW3, mb3, out);
}

// round 11
// speedup vs baseline: 1.2199x; 1.0438x over previous
#include <cuda_runtime.h>
#include <math.h>
#include <stdint.h>

#define NVAR   100000
#define NCLS   400000
#define NEDG   600000
#define HDIM   128
#define NSTEPS 9

// ---------------- scratch (device globals) ----------------
__device__ float g_hv [NVAR * HDIM];
__device__ float g_hv2[NVAR * HDIM];
__device__ float g_cv [NVAR * HDIM];
__device__ float g_hc [NCLS * HDIM];
__device__ float g_hc2[NCLS * HDIM];
__device__ float g_cc [NCLS * HDIM];
__device__ float g_t1 [NCLS * HDIM];
__device__ float g_t2 [NCLS * HDIM];
__device__ float g_m  [NCLS * HDIM];
__device__ float g_z  [NCLS];
__device__ float    g_red[HDIM];
__device__ float    g_sum;
__device__ unsigned g_maxu;
// tf32-rounded, FRAGMENT-MAJOR weights: eW1 | eW2 | eW3 | Wih' | Whh' | pbias
#define OFF_E1  0
#define OFF_E2  65536
#define OFF_E3  131072
#define OFF_WIH 196608
#define OFF_WHH 327680
#define OFF_PB  458752
#define PREP_N  459776
__device__ float g_wr[PREP_N];
// CSR (per etype): off becomes INCLUSIVE prefix after fill; csr holds src ids
__device__ int g_off[4][NCLS];
__device__ int g_csr[4][NEDG];
__device__ int g_cnt[NCLS];
__device__ int g_part[512];

// ---------------- helpers ----------------
__device__ __forceinline__ unsigned f2ord(float f) {
    unsigned b = __float_as_uint(f);
    return (b & 0x80000000u) ? ~b : (b | 0x80000000u);
}
__device__ __forceinline__ float ord2f(unsigned u) {
    unsigned b = (u & 0x80000000u) ? (u ^ 0x80000000u) : ~u;
    return __uint_as_float(b);
}
__device__ __forceinline__ float sigmoidf(float x) { return 1.0f / (1.0f + expf(-x)); }

__device__ __forceinline__ uint32_t f2tf32(float f) {
    uint32_t o;
    asm("cvt.rna.tf32.f32 %0, %1;" : "=r"(o) : "f"(f));
    return o;
}
__device__ __forceinline__ float rtf(float f) { return __uint_as_float(f2tf32(f)); }

__device__ __forceinline__ uint32_t smem_u32(const void* p) {
    uint32_t a;
    asm("{ .reg .u64 t; cvta.to.shared.u64 t, %1; cvt.u32.u64 %0, t; }" : "=r"(a) : "l"(p));
    return a;
}
__device__ __forceinline__ void cp_async16(uint32_t dst, const void* src, int srcbytes) {
    asm volatile("cp.async.cg.shared.global [%0], [%1], 16, %2;"
                 :: "r"(dst), "l"(src), "r"(srcbytes) : "memory");
}
__device__ __forceinline__ void cp_commit() {
    asm volatile("cp.async.commit_group;" ::: "memory");
}
__device__ __forceinline__ void mma_tf32(float* c, const uint32_t* a, uint32_t b0, uint32_t b1) {
    asm volatile(
        "mma.sync.aligned.m16n8k8.row.col.f32.tf32.tf32.f32 "
        "{%0,%1,%2,%3}, {%4,%5,%6,%7}, {%8,%9}, {%0,%1,%2,%3};"
        : "+f"(c[0]), "+f"(c[1]), "+f"(c[2]), "+f"(c[3])
        : "r"(a[0]), "r"(a[1]), "r"(a[2]), "r"(a[3]), "r"(b0), "r"(b1));
}

// ---------------- ONE fused weight-prep kernel (fragment-major layouts) ----------------
__global__ void prep_all(const float* __restrict__ eW1, const float* __restrict__ eW2,
                         const float* __restrict__ eW3, const float* __restrict__ Wih,
                         const float* __restrict__ Whh, const float* __restrict__ bih,
                         const float* __restrict__ bhh, float* __restrict__ wr)
{
    int i = blockIdx.x * blockDim.x + threadIdx.x;
    if (i >= PREP_N) return;
    if (i < 196608) {               // eW1|eW2|eW3
        const float* src = (i < 65536) ? eW1 : (i < 131072) ? eW2 : eW3;
        int base = (i < 65536) ? OFF_E1 : (i < 131072) ? OFF_E2 : OFF_E3;
        int j = i & 65535;
        int etype = j >> 14;
        int rem = j & 16383;
        int row = rem >> 7, k = rem & 127;
        int out = ((k >> 3) * 16 + (row >> 3)) * 64 + (row & 7) * 8 + (k & 3) * 2 + ((k >> 2) & 1);
        wr[base + (etype << 14) + out] = rtf(src[j]);
    } else if (i < 458752) {        // Wih' | Whh'
        int j = i - 196608;
        const float* src = (j < 131072) ? Wih : Whh;
        int base = (j < 131072) ? OFF_WIH : OFF_WHH;
        j &= 131071;
        int rel = j >> 16;
        int rem = j & 65535;
        int r_old = rem >> 7, k = rem & 127;
        int gate = r_old >> 7, f = r_old & 127;
        int r_new = (f << 2) | gate;
        int out = ((k >> 3) * 64 + (r_new >> 3)) * 64 + (r_new & 7) * 8 + (k & 3) * 2 + ((k >> 2) & 1);
        wr[base + (rel << 16) + out] = rtf(src[j]);
    } else {                        // permuted bias sum
        int j = i - 458752;
        int rel = j >> 9;
        int r_old = j & 511;
        int gate = r_old >> 7, f = r_old & 127;
        wr[OFF_PB + (rel << 9) + (f << 2) + gate] = bih[j] + bhh[j];
    }
}

// ---------------- CSR build kernels ----------------
__global__ void hist_k(const int* __restrict__ dst, int* __restrict__ cnt, int E) {
    int i = blockIdx.x * blockDim.x + threadIdx.x;
    if (i < E) atomicAdd(&cnt[dst[i]], 1);
}
__global__ void scan1_k(const int* __restrict__ cnt, int* __restrict__ off,
                        int* __restrict__ part, int N) {
    __shared__ int s[1024];
    int i = blockIdx.x * 1024 + threadIdx.x;
    int v = (i < N) ? cnt[i] : 0;
    s[threadIdx.x] = v;
    __syncthreads();
    for (int d = 1; d < 1024; d <<= 1) {
        int t = (threadIdx.x >= d) ? s[threadIdx.x - d] : 0;
        __syncthreads();
        s[threadIdx.x] += t;
        __syncthreads();
    }
    if (i < N) off[i] = s[threadIdx.x] - v;
    if (threadIdx.x == 1023) part[blockIdx.x] = s[1023];
}
__global__ void scan2_k(int* __restrict__ part, int NB) {
    __shared__ int s[512];
    int v = (threadIdx.x < NB) ? part[threadIdx.x] : 0;
    s[threadIdx.x] = v;
    __syncthreads();
    for (int d = 1; d < 512; d <<= 1) {
        int t = (threadIdx.x >= d) ? s[threadIdx.x - d] : 0;
        __syncthreads();
        s[threadIdx.x] += t;
        __syncthreads();
    }
    if (threadIdx.x < NB) part[threadIdx.x] = s[threadIdx.x] - v;
}
__global__ void scan3_k(int* __restrict__ off, const int* __restrict__ part, int N) {
    int i = blockIdx.x * 1024 + threadIdx.x;
    if (i < N) off[i] += part[blockIdx.x];
}
__global__ void fill_k(const int* __restrict__ src, const int* __restrict__ dst,
                       int* __restrict__ off, int* __restrict__ csr, int E) {
    int i = blockIdx.x * blockDim.x + threadIdx.x;
    if (i >= E) return;
    int p = atomicAdd(&off[dst[i]], 1);
    csr[p] = src[i];
}

// ---------------- init: h = rounded embed, c = embed ----------------
__global__ void init_embed(const int* __restrict__ x, const float* __restrict__ embed,
                           float* __restrict__ h, float* __restrict__ c, int n) {
    int i = blockIdx.x * blockDim.x + threadIdx.x;
    if (i >= n * HDIM) return;
    int node = i >> 7, col = i & 127;
    float v = embed[x[node] * HDIM + col];
    h[i] = rtf(v);
    c[i] = v;
}

// ============ fused 3-layer MLP: fragment-major X & W ============
__global__ void __launch_bounds__(256, 2)
mlp3_fused(const float* __restrict__ X,
           const float* __restrict__ W1l, const float* __restrict__ W2l,
           const float* __restrict__ W3l,
           const float* __restrict__ B1, const float* __restrict__ B2,
           const float* __restrict__ B3,
           float* __restrict__ Y, int N)
{
    extern __shared__ float sm[];
    float* Xs = sm;                   // 16384
    float* Wc = sm + 16384;           // 2*4096
    float* sb = sm + 24576;           // 384

    const int tid    = threadIdx.x;
    const int wid    = tid >> 5;
    const int lane   = tid & 31;
    const int warp_m = wid & 3;
    const int warp_n = wid >> 2;
    const int gid    = lane >> 2;
    const int thid   = lane & 3;
    const int row0   = blockIdx.x << 7;

    const uint32_t wcaddr = smem_u32(Wc);
    const float* WL[3] = {W1l, W2l, W3l};

    if (tid < 128) {
        sb[tid]       = B1[tid];
        sb[128 + tid] = B2[tid];
        sb[256 + tid] = B3[tid];
    }

    auto issueW = [&](int g, int st) {
        const float* Wl = WL[g >> 2] + (g & 3) * 4096;
#pragma unroll
        for (int it = 0; it < 4; it++) {
            int idx = it * 256 + tid;
            cp_async16(wcaddr + (uint32_t)(st * 4096 + idx * 4) * 4u, Wl + idx * 4, 16);
        }
        cp_commit();
    };

    issueW(0, 0);
    issueW(1, 1);

    // prologue: X tile -> smem, tf32-rounded, fragment-major (+XOR-q swizzle)
#pragma unroll
    for (int it = 0; it < 16; it++) {
        int idx = it * 256 + tid;
        int r   = idx >> 5;
        int c4  = idx & 31;
        int gk  = c4 << 2;
        int grow = row0 + r;
        float4 xv = make_float4(0.f, 0.f, 0.f, 0.f);
        if (grow < N) xv = *(const float4*)(X + (size_t)grow * 128 + gk);
        int q     = gk >> 3;
        int reg   = ((r >> 3) & 1) + 2 * ((gk >> 2) & 1);
        int sbase = (q * 8 + (r >> 4)) * 32;
        int sw    = q & 7;
        int lb    = (r & 7) * 4;
        Xs[(sbase + ((lb + 0) ^ sw)) * 4 + reg] = rtf(xv.x);
        Xs[(sbase + ((lb + 1) ^ sw)) * 4 + reg] = rtf(xv.y);
        Xs[(sbase + ((lb + 2) ^ sw)) * 4 + reg] = rtf(xv.z);
        Xs[(sbase + ((lb + 3) ^ sw)) * 4 + reg] = rtf(xv.w);
    }

    int gc = 0;
    for (int layer = 0; layer < 3; layer++) {
        float acc[2][8][4];
#pragma unroll
        for (int mt = 0; mt < 2; mt++)
#pragma unroll
            for (int nt = 0; nt < 8; nt++)
#pragma unroll
                for (int r = 0; r < 4; r++) acc[mt][nt][r] = 0.f;

        for (int qc = 0; qc < 4; qc++, gc++) {
            if (gc + 1 < 12) asm volatile("cp.async.wait_group 1;" ::: "memory");
            else             asm volatile("cp.async.wait_group 0;" ::: "memory");
            __syncthreads();

            const float* Wb = Wc + (gc & 1) * 4096;
#pragma unroll
            for (int ks = 0; ks < 4; ks++) {
                const int q  = qc * 4 + ks;
                const int sw = q & 7;
                uint32_t a[2][4];
#pragma unroll
                for (int mt = 0; mt < 2; mt++) {
                    float4 av = *(const float4*)(Xs +
                        ((q * 8 + warp_m * 2 + mt) * 32 + (lane ^ sw)) * 4);
                    a[mt][0] = __float_as_uint(av.x);
                    a[mt][1] = __float_as_uint(av.y);
                    a[mt][2] = __float_as_uint(av.z);
                    a[mt][3] = __float_as_uint(av.w);
                }
                const float* Bb = Wb + (ks * 16 + warp_n * 8) * 64 + lane * 2;
#pragma unroll
                for (int nt = 0; nt < 8; nt++) {
                    float2 bb = *(const float2*)(Bb + nt * 64);
                    mma_tf32(acc[0][nt], a[0], __float_as_uint(bb.x), __float_as_uint(bb.y));
                    mma_tf32(acc[1][nt], a[1], __float_as_uint(bb.x), __float_as_uint(bb.y));
                }
            }
            __syncthreads();
            if (gc + 2 < 12) issueW(gc + 2, gc & 1);
        }

        if (layer < 2) {
            int kh = thid >> 1;
            int t0 = 2 * (thid & 1);
#pragma unroll
            for (int mt = 0; mt < 2; mt++) {
#pragma unroll
                for (int nt = 0; nt < 8; nt++) {
                    int q   = warp_n * 8 + nt;
                    int sw  = q & 7;
                    int mgb = (q * 8 + warp_m * 2 + mt) * 32;
                    int colL = warp_n * 64 + nt * 8 + thid * 2;
                    float b0 = sb[layer * 128 + colL], b1 = sb[layer * 128 + colL + 1];
                    float v00 = fmaxf(acc[mt][nt][0] + b0, 0.f);
                    float v01 = fmaxf(acc[mt][nt][1] + b1, 0.f);
                    float v10 = fmaxf(acc[mt][nt][2] + b0, 0.f);
                    float v11 = fmaxf(acc[mt][nt][3] + b1, 0.f);
                    int s0 = mgb + ((gid * 4 + t0) ^ sw);
                    int s1 = mgb + ((gid * 4 + t0 + 1) ^ sw);
                    Xs[s0 * 4 + 0 + 2 * kh] = rtf(v00);
                    Xs[s1 * 4 + 0 + 2 * kh] = rtf(v01);
                    Xs[s0 * 4 + 1 + 2 * kh] = rtf(v10);
                    Xs[s1 * 4 + 1 + 2 * kh] = rtf(v11);
                }
            }
        } else {
#pragma unroll
            for (int mt = 0; mt < 2; mt++) {
                int rbase = row0 + warp_m * 32 + mt * 16 + gid;
#pragma unroll
                for (int nt = 0; nt < 8; nt++) {
                    int colL = warp_n * 64 + nt * 8 + thid * 2;
                    float b0 = sb[256 + colL], b1 = sb[256 + colL + 1];
                    float2 v0, v1;
                    v0.x = fmaxf(acc[mt][nt][0] + b0, 0.f);
                    v0.y = fmaxf(acc[mt][nt][1] + b1, 0.f);
                    v1.x = fmaxf(acc[mt][nt][2] + b0, 0.f);
                    v1.y = fmaxf(acc[mt][nt][3] + b1, 0.f);
                    if (rbase < N)     *(float2*)(Y + (size_t)rbase * 128 + colL)       = v0;
                    if (rbase + 8 < N) *(float2*)(Y + (size_t)(rbase + 8) * 128 + colL) = v1;
                }
            }
        }
    }
}

// ============ LSTM gate GEMM: L2-shared X (colblk = fast grid dim) ============
// grid = (4, row_tiles): the 4 col-block CTAs over the SAME X rows are launch-adjacent,
// so 3 of 4 X reads hit L2 instead of DRAM.
__global__ void __launch_bounds__(256, 2)
gemm_lstm(const float* __restrict__ X1, const float* __restrict__ X2,
          const float* __restrict__ W1, const float* __restrict__ W2,
          const float* __restrict__ pb,
          float* __restrict__ hout, float* __restrict__ c, int N)
{
    extern __shared__ float sm[];
    float* Xs = sm;            // 2 * 4608 (stride 36, natural K, pre-rounded tf32 bits)
    float* Ws = sm + 9216;     // 2 * 4096 (fragment-major)

    const int tid    = threadIdx.x;
    const int wid    = tid >> 5;
    const int lane   = tid & 31;
    const int warp_m = wid & 3;
    const int warp_n = wid >> 2;
    const int gid    = lane >> 2;
    const int thid   = lane & 3;
    const int colblk = blockIdx.x;            // 0..3  (FAST dim -> L2 sharing)
    const int row0   = blockIdx.y << 7;
    const int col0   = colblk << 7;
    const int Q      = 8;

    const uint32_t xaddr = smem_u32(Xs);
    const uint32_t waddr = smem_u32(Ws);

    float acc[2][8][4];
#pragma unroll
    for (int mt = 0; mt < 2; mt++)
#pragma unroll
        for (int nt = 0; nt < 8; nt++)
#pragma unroll
            for (int r = 0; r < 4; r++) acc[mt][nt][r] = 0.f;

    auto issue = [&](int q, int st) {
        const int kc = q << 5;
        const uint32_t xb = xaddr + (uint32_t)st * 4608u * 4u;
        const uint32_t wb = waddr + (uint32_t)st * 4096u * 4u;
        const float* Wl = (q < 4) ? W1 : W2;
        const int qa = q & 3;
#pragma unroll
        for (int it = 0; it < 4; it++) {
            int idx = it * 256 + tid;
            {
                int r  = idx >> 3;
                int c4 = idx & 7;
                int gk = kc + (c4 << 2);
                int grow = row0 + r;
                const float* xp = X1;
                int sz = 0;
                if (grow < N) {
                    xp = (gk < 128) ? (X1 + (size_t)grow * 128 + gk)
                                    : (X2 + (size_t)grow * 128 + (gk - 128));
                    sz = 16;
                }
                cp_async16(xb + (uint32_t)(r * 36 + c4 * 4) * 4u, xp, sz);
            }
            {
                int qq     = idx >> 8;
                int within = idx & 255;
                const float* wp = Wl + (qa * 4 + qq) * 4096 + colblk * 1024 + within * 4;
                cp_async16(wb + (uint32_t)(qq * 1024 + within * 4) * 4u, wp, 16);
            }
        }
        cp_commit();
    };

    issue(0, 0);
    for (int q = 0; q < Q; q++) {
        if (q + 1 < Q) {
            issue(q + 1, (q + 1) & 1);
            asm volatile("cp.async.wait_group 1;" ::: "memory");
        } else {
            asm volatile("cp.async.wait_group 0;" ::: "memory");
        }
        __syncthreads();

        const float* Xb = Xs + (q & 1) * 4608;
        const float* Wb = Ws + (q & 1) * 4096;
#pragma unroll
        for (int ks = 0; ks < 4; ks++) {
            const int kb = ks * 8;
            uint32_t a[2][4];
#pragma unroll
            for (int mt = 0; mt < 2; mt++) {
                int rr = warp_m * 32 + mt * 16 + gid;
                a[mt][0] = __float_as_uint(Xb[rr * 36 + kb + thid]);
                a[mt][1] = __float_as_uint(Xb[(rr + 8) * 36 + kb + thid]);
                a[mt][2] = __float_as_uint(Xb[rr * 36 + kb + thid + 4]);
                a[mt][3] = __float_as_uint(Xb[(rr + 8) * 36 + kb + thid + 4]);
            }
            const float* Bb = Wb + (ks * 16 + warp_n * 8) * 64 + lane * 2;
#pragma unroll
            for (int nt = 0; nt < 8; nt++) {
                float2 bb = *(const float2*)(Bb + nt * 64);
                mma_tf32(acc[0][nt], a[0], __float_as_uint(bb.x), __float_as_uint(bb.y));
                mma_tf32(acc[1][nt], a[1], __float_as_uint(bb.x), __float_as_uint(bb.y));
            }
        }
        __syncthreads();
    }

    // ---- fused LSTM epilogue (even/odd lane pair exchange via shfl_xor(1)) ----
    const bool odd = (lane & 1);
    const int featbase = (col0 + warp_n * 64) >> 2;
#pragma unroll
    for (int mt = 0; mt < 2; mt++) {
        int rbase = row0 + warp_m * 32 + mt * 16 + gid;
#pragma unroll
        for (int nt = 0; nt < 8; nt++) {
            int colL = warp_n * 64 + nt * 8 + thid * 2;
            float b0 = pb[col0 + colL], b1 = pb[col0 + colL + 1];
            float v00 = acc[mt][nt][0] + b0;
            float v01 = acc[mt][nt][1] + b1;
            float v10 = acc[mt][nt][2] + b0;
            float v11 = acc[mt][nt][3] + b1;
            float s0 = odd ? v00 : v10;
            float s1 = odd ? v01 : v11;
            float t0 = __shfl_xor_sync(0xFFFFFFFFu, s0, 1);
            float t1 = __shfl_xor_sync(0xFFFFFFFFu, s1, 1);
            float gi = odd ? t0 : v00;
            float gf = odd ? t1 : v01;
            float gg = odd ? v10 : t0;
            float go = odd ? v11 : t1;
            int row  = rbase + (odd ? 8 : 0);
            int feat = featbase + nt * 2 + (thid >> 1);
            if (row < N) {
                size_t o = (size_t)row * 128 + feat;
                float cp = c[o];
                float cn = sigmoidf(gf) * cp + sigmoidf(gi) * tanhf(gg);
                hout[o] = rtf(sigmoidf(go) * tanhf(cn));
                c[o] = fmaxf(cn, 0.f);
            }
        }
    }
}

// ---------------- CSR gather: m[dst] = sum(t_a) + sum(t_b), output tf32-rounded ----------------
__global__ void gather2(const float* __restrict__ ta, const int* __restrict__ offa,
                        const int* __restrict__ csra,
                        const float* __restrict__ tb, const int* __restrict__ offb,
                        const int* __restrict__ csrb,
                        float* __restrict__ m, int N)
{
    int gw   = (blockIdx.x * blockDim.x + threadIdx.x) >> 5;
    int lane = threadIdx.x & 31;
    if (gw >= N) return;
    float4 acc = make_float4(0.f, 0.f, 0.f, 0.f);
    int s0 = gw ? offa[gw - 1] : 0;
    int e0 = offa[gw];
    for (int e = s0; e < e0; e++) {
        int src = csra[e];
        float4 v = *(const float4*)(ta + (size_t)src * 128 + lane * 4);
        acc.x += v.x; acc.y += v.y; acc.z += v.z; acc.w += v.w;
    }
    int s1 = gw ? offb[gw - 1] : 0;
    int e1 = offb[gw];
    for (int e = s1; e < e1; e++) {
        int src = csrb[e];
        float4 v = *(const float4*)(tb + (size_t)src * 128 + lane * 4);
        acc.x += v.x; acc.y += v.y; acc.z += v.z; acc.w += v.w;
    }
    float4 r;
    r.x = rtf(acc.x); r.y = rtf(acc.y); r.z = rtf(acc.z); r.w = rtf(acc.w);
    *(float4*)(m + (size_t)gw * 128 + lane * 4) = r;
}

// ---------------- attention pooling ----------------
__global__ void pool_reset(unsigned* maxu, float* sum, float* red) {
    if (threadIdx.x == 0) { *maxu = 0u; *sum = 0.f; }
    if (threadIdx.x < HDIM) red[threadIdx.x] = 0.f;
}

__global__ void gate_logits(const float* __restrict__ cc, const float* __restrict__ gW,
                            const float* __restrict__ gb, float* __restrict__ z,
                            unsigned* __restrict__ maxu, int n)
{
    __shared__ float smax[8];
    int gw   = (blockIdx.x * blockDim.x + threadIdx.x) >> 5;
    int lane = threadIdx.x & 31;
    int wid  = threadIdx.x >> 5;
    float myz = -1e30f;
    if (gw < n) {
        float4 a = *(const float4*)(cc + (size_t)gw * HDIM + lane * 4);
        float4 b = *(const float4*)(gW + lane * 4);
        float p = a.x * b.x + a.y * b.y + a.z * b.z + a.w * b.w;
        p += __shfl_down_sync(0xFFFFFFFFu, p, 16);
        p += __shfl_down_sync(0xFFFFFFFFu, p, 8);
        p += __shfl_down_sync(0xFFFFFFFFu, p, 4);
        p += __shfl_down_sync(0xFFFFFFFFu, p, 2);
        p += __shfl_down_sync(0xFFFFFFFFu, p, 1);
        if (lane == 0) {
            myz = p + gb[0];
            z[gw] = myz;
        }
    }
    if (lane == 0) smax[wid] = myz;
    __syncthreads();
    if (threadIdx.x == 0) {
        float mx = smax[0];
#pragma unroll
        for (int w = 1; w < 8; w++) mx = fmaxf(mx, smax[w]);
        atomicMax(maxu, f2ord(mx));
    }
}

__global__ void softmax_accum(const float* __restrict__ cc, const float* __restrict__ z,
                              const unsigned* __restrict__ maxu,
                              float* __restrict__ sum, float* __restrict__ red, int n)
{
    int t = threadIdx.x;
    float zmax = ord2f(*maxu);
    int c0 = blockIdx.x * 64;
    float acc = 0.f, wsum = 0.f;
    for (int i = 0; i < 64; i++) {
        int c = c0 + i;
        if (c >= n) break;
        float w = expf(z[c] - zmax);
        acc  += w * cc[(size_t)c * HDIM + t];
        wsum += w;
    }
    atomicAdd(&red[t], acc);
    if (t == 0) atomicAdd(sum, wsum);
}

__global__ void final_mlp(const float* __restrict__ red, const float* __restrict__ sum,
                          const float* __restrict__ mW1, const float* __restrict__ mb1,
                          const float* __restrict__ mW2, const float* __restrict__ mb2,
                          const float* __restrict__ mW3, const float* __restrict__ mb3,
                          float* __restrict__ out)
{
    __shared__ float x0[HDIM], x1[HDIM], x2[HDIM];
    int t = threadIdx.x;
    x0[t] = red[t] / (*sum);
    __syncthreads();
    {
        float a = mb1[t];
        for (int k = 0; k < HDIM; k++) a = fmaf(x0[k], mW1[t * HDIM + k], a);
        x1[t] = fmaxf(a, 0.f);
    }
    __syncthreads();
    {
        float a = mb2[t];
        for (int k = 0; k < HDIM; k++) a = fmaf(x1[k], mW2[t * HDIM + k], a);
        x2[t] = fmaxf(a, 0.f);
    }
    __syncthreads();
    if (t < 2) {
        float a = mb3[t];
        for (int k = 0; k < HDIM; k++) a = fmaf(x2[k], mW3[t * HDIM + k], a);
        out[t] = a;
    }
}

// ---------------- host orchestration ----------------
#define MLP_SMEM  (24960 * 4)    // 99840 bytes  -> 2 CTAs/SM
#define LSTM_SMEM (17408 * 4)    // 69632 bytes  -> 2 CTAs/SM

static void build_csr(const int* src, const int* dst, int* off, int* csr,
                      int* cnt, int* part, int Ndst)
{
    cudaMemsetAsync(cnt, 0, (size_t)Ndst * sizeof(int));
    hist_k<<<(NEDG + 255) / 256, 256>>>(dst, cnt, NEDG);
    int NB = (Ndst + 1023) / 1024;
    scan1_k<<<NB, 1024>>>(cnt, off, part, Ndst);
    scan2_k<<<1, 512>>>(part, NB);
    scan3_k<<<NB, 1024>>>(off, part, Ndst);
    fill_k<<<(NEDG + 255) / 256, 256>>>(src, dst, off, csr, NEDG);
}

extern "C" void kernel_launch(void* const* d_in, const int* in_sizes, int n_in,
                              void* d_out, int out_size)
{
    const int*   var_x    = (const int*)  d_in[0];
    const int*   clause_x = (const int*)  d_in[1];
    const int*   pos_src  = (const int*)  d_in[2];
    const int*   pos_dst  = (const int*)  d_in[3];
    const int*   neg_src  = (const int*)  d_in[4];
    const int*   neg_dst  = (const int*)  d_in[5];
    const int*   posr_src = (const int*)  d_in[6];
    const int*   posr_dst = (const int*)  d_in[7];
    const int*   negr_src = (const int*)  d_in[8];
    const int*   negr_dst = (const int*)  d_in[9];
    const float* embed    = (const float*)d_in[10];
    const float* eW1      = (const float*)d_in[11];
    const float* eb1      = (const float*)d_in[12];
    const float* eW2      = (const float*)d_in[13];
    const float* eb2      = (const float*)d_in[14];
    const float* eW3      = (const float*)d_in[15];
    const float* eb3      = (const float*)d_in[16];
    const float* Wih      = (const float*)d_in[17];
    const float* Whh      = (const float*)d_in[18];
    const float* bih      = (const float*)d_in[19];
    const float* bhh      = (const float*)d_in[20];
    const float* gW       = (const float*)d_in[21];
    const float* gb       = (const float*)d_in[22];
    const float* mW1      = (const float*)d_in[23];
    const float* mb1      = (const float*)d_in[24];
    const float* mW2      = (const float*)d_in[25];
    const float* mb2      = (const float*)d_in[26];
    const float* mW3      = (const float*)d_in[27];
    const float* mb3      = (const float*)d_in[28];
    float* out = (float*)d_out;

    cudaFuncSetAttribute(mlp3_fused, cudaFuncAttributeMaxDynamicSharedMemorySize, MLP_SMEM);
    cudaFuncSetAttribute(gemm_lstm, cudaFuncAttributeMaxDynamicSharedMemorySize, LSTM_SMEM);

    float *hv, *hv2, *cv, *hc, *hc2, *cc, *t1, *t2, *m, *z, *red, *sum, *wr;
    unsigned* maxu;
    int *off, *csr, *cnt, *part;
    cudaGetSymbolAddress((void**)&hv,   g_hv);
    cudaGetSymbolAddress((void**)&hv2,  g_hv2);
    cudaGetSymbolAddress((void**)&cv,   g_cv);
    cudaGetSymbolAddress((void**)&hc,   g_hc);
    cudaGetSymbolAddress((void**)&hc2,  g_hc2);
    cudaGetSymbolAddress((void**)&cc,   g_cc);
    cudaGetSymbolAddress((void**)&t1,   g_t1);
    cudaGetSymbolAddress((void**)&t2,   g_t2);
    cudaGetSymbolAddress((void**)&m,    g_m);
    cudaGetSymbolAddress((void**)&z,    g_z);
    cudaGetSymbolAddress((void**)&red,  g_red);
    cudaGetSymbolAddress((void**)&sum,  g_sum);
    cudaGetSymbolAddress((void**)&maxu, g_maxu);
    cudaGetSymbolAddress((void**)&wr,   g_wr);
    cudaGetSymbolAddress((void**)&off,  g_off);
    cudaGetSymbolAddress((void**)&csr,  g_csr);
    cudaGetSymbolAddress((void**)&cnt,  g_cnt);
    cudaGetSymbolAddress((void**)&part, g_part);

    int* off_e[4] = {off, off + NCLS, off + 2 * NCLS, off + 3 * NCLS};
    int* csr_e[4] = {csr, csr + NEDG, csr + 2 * NEDG, csr + 3 * NEDG};

    const float* E1 = wr + OFF_E1;
    const float* E2 = wr + OFF_E2;
    const float* E3 = wr + OFF_E3;
    const float* WIH = wr + OFF_WIH;
    const float* WHH = wr + OFF_WHH;
    const float* PB  = wr + OFF_PB;

    const int vgrid = (NVAR + 127) / 128;   // 782
    const int cgrid = (NCLS + 127) / 128;   // 3125
    const int EB = 16384;                    // per-etype weight block (floats)

    prep_all<<<(PREP_N + 255) / 256, 256>>>(eW1, eW2, eW3, Wih, Whh, bih, bhh, wr);
    init_embed<<<(NVAR * HDIM + 255) / 256, 256>>>(var_x,    embed, hv, cv, NVAR);
    init_embed<<<(NCLS * HDIM + 255) / 256, 256>>>(clause_x, embed, hc, cc, NCLS);

    float* hcs[2] = {hc, hc2};
    float* hvs[2] = {hv, hv2};
    int hci = 0, hvi = 0;

    for (int s = 0; s < NSTEPS; s++) {
        // ---- relation 0: var -> clause ----
        mlp3_fused<<<vgrid, 256, MLP_SMEM>>>(cv, E1 + 0 * EB, E2 + 0 * EB, E3 + 0 * EB,
                                             eb1 + 0 * HDIM, eb2 + 0 * HDIM, eb3 + 0 * HDIM,
                                             t1, NVAR);
        mlp3_fused<<<vgrid, 256, MLP_SMEM>>>(cv, E1 + 1 * EB, E2 + 1 * EB, E3 + 1 * EB,
                                             eb1 + 1 * HDIM, eb2 + 1 * HDIM, eb3 + 1 * HDIM,
                                             t2, NVAR);
        if (s == 0) {
            build_csr(pos_src,  pos_dst,  off_e[0], csr_e[0], cnt, part, NCLS);
            build_csr(neg_src,  neg_dst,  off_e[1], csr_e[1], cnt, part, NCLS);
            build_csr(posr_src, posr_dst, off_e[2], csr_e[2], cnt, part, NVAR);
            build_csr(negr_src, negr_dst, off_e[3], csr_e[3], cnt, part, NVAR);
        }
        gather2<<<(NCLS * 32 + 255) / 256, 256>>>(t1, off_e[0], csr_e[0],
                                                  t2, off_e[1], csr_e[1], m, NCLS);
        {   // clause LSTM: colblk fast dim -> L2-shared X rows
            dim3 grid(4, cgrid);
            gemm_lstm<<<grid, 256, LSTM_SMEM>>>(m, hcs[hci], WIH, WHH, PB,
                                                hcs[hci ^ 1], cc, NCLS);
            hci ^= 1;
        }

        // ---- relation 1: clause -> var ----
        mlp3_fused<<<cgrid, 256, MLP_SMEM>>>(cc, E1 + 2 * EB, E2 + 2 * EB, E3 + 2 * EB,
                                             eb1 + 2 * HDIM, eb2 + 2 * HDIM, eb3 + 2 * HDIM,
                                             t1, NCLS);
        mlp3_fused<<<cgrid, 256, MLP_SMEM>>>(cc, E1 + 3 * EB, E2 + 3 * EB, E3 + 3 * EB,
                                             eb1 + 3 * HDIM, eb2 + 3 * HDIM, eb3 + 3 * HDIM,
                                             t2, NCLS);
        gather2<<<(NVAR * 32 + 255) / 256, 256>>>(t1, off_e[2], csr_e[2],
                                                  t2, off_e[3], csr_e[3], m, NVAR);
        {   // var LSTM: colblk fast dim
            dim3 grid(4, vgrid);
            gemm_lstm<<<grid, 256, LSTM_SMEM>>>(m, hvs[hvi], WIH + 65536, WHH + 65536,
                                                PB + 512, hvs[hvi ^ 1], cv, NVAR);
            hvi ^= 1;
        }
    }

    // ---- GlobalAttentionPooling + final MLP ----
    pool_reset<<<1, 128>>>(maxu, sum, red);
    gate_logits<<<(NCLS * 32 + 255) / 256, 256>>>(cc, gW, gb, z, maxu, NCLS);
    softmax_accum<<<(NCLS + 63) / 64, 128>>>(cc, z, maxu, sum, red, NCLS);
    final_mlp<<<1, 128>>>(red, sum, mW1, mb1, mW2, mb2, mW3, mb3, out);
}

// round 12
// speedup vs baseline: 1.5464x; 1.2677x over previous
#include <cuda_runtime.h>
#include <cuda_fp16.h>
#include <math.h>
#include <stdint.h>

#define NVAR   100000
#define NCLS   400000
#define NEDG   600000
#define HDIM   128
#define NSTEPS 9

// ---------------- scratch (device globals) ----------------
__device__ __align__(16) __half g_hv [NVAR * HDIM];
__device__ __align__(16) __half g_hv2[NVAR * HDIM];
__device__ __align__(16) __half g_hc [NCLS * HDIM];
__device__ __align__(16) __half g_hc2[NCLS * HDIM];
__device__ __align__(16) __half g_t1 [NCLS * HDIM];
__device__ __align__(16) __half g_t2 [NCLS * HDIM];
__device__ __align__(16) __half g_m  [NCLS * HDIM];
__device__ float g_cv [NVAR * HDIM];
__device__ float g_cc [NCLS * HDIM];
__device__ float g_z  [NCLS];
__device__ float    g_red[HDIM];
__device__ float    g_sum;
__device__ unsigned g_maxu;
// fp16 fragment-major weights: eW1 | eW2 | eW3 | Wih' | Whh'
#define OFFH_E1  0
#define OFFH_E2  65536
#define OFFH_E3  131072
#define OFFH_WIH 196608
#define OFFH_WHH 327680
#define WH_N     458752
__device__ __align__(16) __half g_wh[WH_N];
__device__ float g_pb[1024];
#define PREP_N  459776
// CSR
__device__ int g_off[4][NCLS];
__device__ int g_csr[4][NEDG];
__device__ int g_cnt[NCLS];
__device__ int g_part[512];

// ---------------- helpers ----------------
__device__ __forceinline__ unsigned f2ord(float f) {
    unsigned b = __float_as_uint(f);
    return (b & 0x80000000u) ? ~b : (b | 0x80000000u);
}
__device__ __forceinline__ float ord2f(unsigned u) {
    unsigned b = (u & 0x80000000u) ? (u ^ 0x80000000u) : ~u;
    return __uint_as_float(b);
}
__device__ __forceinline__ float sigmoidf(float x) { return 1.0f / (1.0f + expf(-x)); }

__device__ __forceinline__ uint32_t pk2h(float a, float b) {
    __half2 h = __floats2half2_rn(a, b);
    return *(uint32_t*)&h;
}
__device__ __forceinline__ uint32_t smem_u32(const void* p) {
    uint32_t a;
    asm("{ .reg .u64 t; cvta.to.shared.u64 t, %1; cvt.u32.u64 %0, t; }" : "=r"(a) : "l"(p));
    return a;
}
__device__ __forceinline__ void cp_async16(uint32_t dst, const void* src, int srcbytes) {
    asm volatile("cp.async.cg.shared.global [%0], [%1], 16, %2;"
                 :: "r"(dst), "l"(src), "r"(srcbytes) : "memory");
}
__device__ __forceinline__ void cp_commit() {
    asm volatile("cp.async.commit_group;" ::: "memory");
}
__device__ __forceinline__ void mma_f16(float* c, const uint32_t* a, uint32_t b0, uint32_t b1) {
    asm volatile(
        "mma.sync.aligned.m16n8k16.row.col.f32.f16.f16.f32 "
        "{%0,%1,%2,%3}, {%4,%5,%6,%7}, {%8,%9}, {%0,%1,%2,%3};"
        : "+f"(c[0]), "+f"(c[1]), "+f"(c[2]), "+f"(c[3])
        : "r"(a[0]), "r"(a[1]), "r"(a[2]), "r"(a[3]), "r"(b0), "r"(b1));
}

// ---------------- fused weight prep: fp16 fragment-major ----------------
// MLP block (16384 halfs):  hidx = ((k>>4)*16 + (n>>3))*128 + ((n&7)*4 + ((k&7)>>1))*4
//                                  + ((k>>3)&1)*2 + (k&1)
// LSTM block (65536/rel):   rows gate-permuted (r' = 4f+gate), ng 0..63:
//                           hidx = ((k>>4)*64 + (r'>>3))*128 + ((r'&7)*4 + ((k&7)>>1))*4
//                                  + ((k>>3)&1)*2 + (k&1)
__global__ void prep_all(const float* __restrict__ eW1, const float* __restrict__ eW2,
                         const float* __restrict__ eW3, const float* __restrict__ Wih,
                         const float* __restrict__ Whh, const float* __restrict__ bih,
                         const float* __restrict__ bhh,
                         __half* __restrict__ wh, float* __restrict__ pbo)
{
    int i = blockIdx.x * blockDim.x + threadIdx.x;
    if (i >= PREP_N) return;
    if (i < 196608) {               // eW1|eW2|eW3
        const float* src = (i < 65536) ? eW1 : (i < 131072) ? eW2 : eW3;
        int base = (i < 65536) ? OFFH_E1 : (i < 131072) ? OFFH_E2 : OFFH_E3;
        int j = i & 65535;
        int etype = j >> 14;
        int rem = j & 16383;
        int n = rem >> 7, k = rem & 127;
        int hidx = ((k >> 4) * 16 + (n >> 3)) * 128 + ((n & 7) * 4 + ((k & 7) >> 1)) * 4
                   + ((k >> 3) & 1) * 2 + (k & 1);
        wh[base + (etype << 14) + hidx] = __float2half_rn(src[j]);
    } else if (i < 458752) {        // Wih' | Whh'
        int j = i - 196608;
        const float* src = (j < 131072) ? Wih : Whh;
        int base = (j < 131072) ? OFFH_WIH : OFFH_WHH;
        j &= 131071;
        int rel = j >> 16;
        int rem = j & 65535;
        int r_old = rem >> 7, k = rem & 127;
        int gate = r_old >> 7, f = r_old & 127;
        int rn = (f << 2) | gate;
        int hidx = ((k >> 4) * 64 + (rn >> 3)) * 128 + ((rn & 7) * 4 + ((k & 7) >> 1)) * 4
                   + ((k >> 3) & 1) * 2 + (k & 1);
        wh[base + (rel << 16) + hidx] = __float2half_rn(src[j]);
    } else {                        // permuted bias sum (fp32)
        int j = i - 458752;
        int rel = j >> 9;
        int r_old = j & 511;
        int gate = r_old >> 7, f = r_old & 127;
        pbo[(rel << 9) + (f << 2) + gate] = bih[j] + bhh[j];
    }
}

// ---------------- CSR build kernels ----------------
__global__ void hist_k(const int* __restrict__ dst, int* __restrict__ cnt, int E) {
    int i = blockIdx.x * blockDim.x + threadIdx.x;
    if (i < E) atomicAdd(&cnt[dst[i]], 1);
}
__global__ void scan1_k(const int* __restrict__ cnt, int* __restrict__ off,
                        int* __restrict__ part, int N) {
    __shared__ int s[1024];
    int i = blockIdx.x * 1024 + threadIdx.x;
    int v = (i < N) ? cnt[i] : 0;
    s[threadIdx.x] = v;
    __syncthreads();
    for (int d = 1; d < 1024; d <<= 1) {
        int t = (threadIdx.x >= d) ? s[threadIdx.x - d] : 0;
        __syncthreads();
        s[threadIdx.x] += t;
        __syncthreads();
    }
    if (i < N) off[i] = s[threadIdx.x] - v;
    if (threadIdx.x == 1023) part[blockIdx.x] = s[1023];
}
__global__ void scan2_k(int* __restrict__ part, int NB) {
    __shared__ int s[512];
    int v = (threadIdx.x < NB) ? part[threadIdx.x] : 0;
    s[threadIdx.x] = v;
    __syncthreads();
    for (int d = 1; d < 512; d <<= 1) {
        int t = (threadIdx.x >= d) ? s[threadIdx.x - d] : 0;
        __syncthreads();
        s[threadIdx.x] += t;
        __syncthreads();
    }
    if (threadIdx.x < NB) part[threadIdx.x] = s[threadIdx.x] - v;
}
__global__ void scan3_k(int* __restrict__ off, const int* __restrict__ part, int N) {
    int i = blockIdx.x * 1024 + threadIdx.x;
    if (i < N) off[i] += part[blockIdx.x];
}
__global__ void fill_k(const int* __restrict__ src, const int* __restrict__ dst,
                       int* __restrict__ off, int* __restrict__ csr, int E) {
    int i = blockIdx.x * blockDim.x + threadIdx.x;
    if (i >= E) return;
    int p = atomicAdd(&off[dst[i]], 1);
    csr[p] = src[i];
}

// ---------------- init: h(half) = embed, c(float) = embed ----------------
__global__ void init_embed(const int* __restrict__ x, const float* __restrict__ embed,
                           __half* __restrict__ h, float* __restrict__ c, int n) {
    int i = blockIdx.x * blockDim.x + threadIdx.x;
    if (i >= n * HDIM) return;
    int node = i >> 7, col = i & 127;
    float v = embed[x[node] * HDIM + col];
    h[i] = __float2half_rn(v);
    c[i] = v;
}

// ============ fused 3-layer MLP, fp16 fragment-major ============
// Smem (uints): Xs[8192] = [q16][grp][lane][reg] | Wc[2][2048] | sb[384 floats]
__global__ void __launch_bounds__(256, 2)
mlp3_fused(const float* __restrict__ X,
           const __half* __restrict__ W1l, const __half* __restrict__ W2l,
           const __half* __restrict__ W3l,
           const float* __restrict__ B1, const float* __restrict__ B2,
           const float* __restrict__ B3,
           __half* __restrict__ Y, int N)
{
    extern __shared__ uint32_t smu[];
    uint32_t* Xs = smu;                 // 8192
    uint32_t* Wc = smu + 8192;          // 2*2048
    float*    sb = (float*)(smu + 12288); // 384

    const int tid    = threadIdx.x;
    const int wid    = tid >> 5;
    const int lane   = tid & 31;
    const int warp_m = wid & 3;
    const int warp_n = wid >> 2;
    const int gid    = lane >> 2;
    const int thid   = lane & 3;
    const int row0   = blockIdx.x << 7;

    const uint32_t wcaddr = smem_u32(Wc);
    const __half* WL[3] = {W1l, W2l, W3l};

    if (tid < 128) {
        sb[tid]       = B1[tid];
        sb[128 + tid] = B2[tid];
        sb[256 + tid] = B3[tid];
    }

    auto issueW = [&](int g, int st) {
        const __half* Wl = WL[g >> 2] + (size_t)(g & 3) * 4096;   // 4096 halfs per chunk
#pragma unroll
        for (int it = 0; it < 2; it++) {
            int idx = it * 256 + tid;    // 0..511 (16B units)
            cp_async16(wcaddr + (uint32_t)(st * 2048 + idx * 4) * 4u, Wl + idx * 8, 16);
        }
        cp_commit();
    };

    issueW(0, 0);
    issueW(1, 1);

    // prologue: X (fp32) -> half2 fragments
#pragma unroll
    for (int it = 0; it < 16; it++) {
        int idx = it * 256 + tid;      // 0..4095
        int r   = idx & 127;
        int c4  = idx >> 7;            // 0..31
        int gk  = c4 << 2;
        int grow = row0 + r;
        float4 xv = make_float4(0.f, 0.f, 0.f, 0.f);
        if (grow < N) xv = *(const float4*)(X + (size_t)grow * 128 + gk);
        int q16 = gk >> 4;
        int grp = r >> 4;
        int gd  = r & 7;
        int mh  = (r >> 3) & 1;
        int kh8 = (gk >> 3) & 1;
        int t0  = (gk & 7) >> 1;       // 0 or 2
        int reg = mh + 2 * kh8;
        int base = ((q16 * 8 + grp) * 32 + gd * 4) * 4 + reg;
        Xs[base + t0 * 4]       = pk2h(xv.x, xv.y);
        Xs[base + (t0 + 1) * 4] = pk2h(xv.z, xv.w);
    }

    int gc = 0;
    for (int layer = 0; layer < 3; layer++) {
        float acc[2][8][4];
#pragma unroll
        for (int mt = 0; mt < 2; mt++)
#pragma unroll
            for (int nt = 0; nt < 8; nt++)
#pragma unroll
                for (int r = 0; r < 4; r++) acc[mt][nt][r] = 0.f;

        for (int qc = 0; qc < 4; qc++, gc++) {
            if (gc + 1 < 12) asm volatile("cp.async.wait_group 1;" ::: "memory");
            else             asm volatile("cp.async.wait_group 0;" ::: "memory");
            __syncthreads();

            const uint32_t* Wb = Wc + (gc & 1) * 2048;
#pragma unroll
            for (int s = 0; s < 2; s++) {
                const int q16 = qc * 2 + s;
                uint32_t a[2][4];
#pragma unroll
                for (int mt = 0; mt < 2; mt++) {
                    uint4 av = *(const uint4*)(Xs +
                        ((q16 * 8 + warp_m * 2 + mt) * 32 + lane) * 4);
                    a[mt][0] = av.x; a[mt][1] = av.y; a[mt][2] = av.z; a[mt][3] = av.w;
                }
                const uint32_t* Bb = Wb + ((s * 16 + warp_n * 8) * 32 + lane) * 2;
#pragma unroll
                for (int nt = 0; nt < 8; nt++) {
                    uint2 bb = *(const uint2*)(Bb + nt * 64);
                    mma_f16(acc[0][nt], a[0], bb.x, bb.y);
                    mma_f16(acc[1][nt], a[1], bb.x, bb.y);
                }
            }
            __syncthreads();
            if (gc + 2 < 12) issueW(gc + 2, gc & 1);
        }

        if (layer < 2) {
            // write back as next layer's A fragments (half2)
#pragma unroll
            for (int mt = 0; mt < 2; mt++) {
#pragma unroll
                for (int nt = 0; nt < 8; nt++) {
                    int colL = warp_n * 64 + nt * 8 + thid * 2;
                    float b0 = sb[layer * 128 + colL], b1 = sb[layer * 128 + colL + 1];
                    float v00 = fmaxf(acc[mt][nt][0] + b0, 0.f);
                    float v01 = fmaxf(acc[mt][nt][1] + b1, 0.f);
                    float v10 = fmaxf(acc[mt][nt][2] + b0, 0.f);
                    float v11 = fmaxf(acc[mt][nt][3] + b1, 0.f);
                    int nq  = warp_n * 4 + (nt >> 1);
                    int kh8 = nt & 1;
                    int ngr = warp_m * 2 + mt;
                    int uidx = ((nq * 8 + ngr) * 32 + gid * 4 + thid) * 4;
                    Xs[uidx + 2 * kh8]     = pk2h(v00, v01);   // row gid (mh=0)
                    Xs[uidx + 1 + 2 * kh8] = pk2h(v10, v11);   // row gid+8 (mh=1)
                }
            }
        } else {
#pragma unroll
            for (int mt = 0; mt < 2; mt++) {
                int rbase = row0 + warp_m * 32 + mt * 16 + gid;
#pragma unroll
                for (int nt = 0; nt < 8; nt++) {
                    int colL = warp_n * 64 + nt * 8 + thid * 2;
                    float b0 = sb[256 + colL], b1 = sb[256 + colL + 1];
                    uint32_t h01 = pk2h(fmaxf(acc[mt][nt][0] + b0, 0.f),
                                        fmaxf(acc[mt][nt][1] + b1, 0.f));
                    uint32_t h23 = pk2h(fmaxf(acc[mt][nt][2] + b0, 0.f),
                                        fmaxf(acc[mt][nt][3] + b1, 0.f));
                    if (rbase < N)     *(uint32_t*)(Y + (size_t)rbase * 128 + colL)       = h01;
                    if (rbase + 8 < N) *(uint32_t*)(Y + (size_t)(rbase + 8) * 128 + colL) = h23;
                }
            }
        }
    }
}

// ============ LSTM gate GEMM fp16 ============
// Xs: row-major half, stride 40 halfs (20 uints), 2 stages. Ws: fragment-major, 2 stages.
__global__ void __launch_bounds__(256, 2)
gemm_lstm(const __half* __restrict__ X1, const __half* __restrict__ X2,
          const __half* __restrict__ W1, const __half* __restrict__ W2,
          const float* __restrict__ pb,
          __half* __restrict__ hout, float* __restrict__ c, int N)
{
    extern __shared__ uint32_t smu[];
    uint32_t* Xs = smu;            // 2 * 2560 uints
    uint32_t* Ws = smu + 5120;     // 2 * 2048 uints

    const int tid    = threadIdx.x;
    const int wid    = tid >> 5;
    const int lane   = tid & 31;
    const int warp_m = wid & 3;
    const int warp_n = wid >> 2;
    const int gid    = lane >> 2;
    const int thid   = lane & 3;
    const int colblk = blockIdx.x;            // 0..3 (fast dim -> L2-shared X)
    const int row0   = blockIdx.y << 7;
    const int col0   = colblk << 7;
    const int Q      = 8;

    const uint32_t xaddr = smem_u32(Xs);
    const uint32_t waddr = smem_u32(Ws);

    float acc[2][8][4];
#pragma unroll
    for (int mt = 0; mt < 2; mt++)
#pragma unroll
        for (int nt = 0; nt < 8; nt++)
#pragma unroll
            for (int r = 0; r < 4; r++) acc[mt][nt][r] = 0.f;

    auto issue = [&](int q, int st) {
        const int kc = q << 5;
        const uint32_t xb = xaddr + (uint32_t)st * 2560u * 4u;
        const uint32_t wb = waddr + (uint32_t)st * 2048u * 4u;
        const __half* Wl = (q < 4) ? W1 : W2;
        const int qa = q & 3;
#pragma unroll
        for (int it = 0; it < 4; it++) {
            int idx = it * 256 + tid;       // 0..1023
            if (idx < 512) {                // X: r = idx>>2, c8 = idx&3 (8 halfs each)
                int r  = idx >> 2;
                int c8 = idx & 3;
                int gk = kc + c8 * 8;
                int grow = row0 + r;
                const __half* xp = X1;
                int sz = 0;
                if (grow < N) {
                    xp = (gk < 128) ? (X1 + (size_t)grow * 128 + gk)
                                    : (X2 + (size_t)grow * 128 + (gk - 128));
                    sz = 16;
                }
                cp_async16(xb + (uint32_t)(r * 20 + c8 * 4) * 4u, xp, sz);
            } else {                         // W: 2 q16 pieces of 1024 uints
                int j  = idx - 512;
                int s  = j >> 8;
                int j4 = j & 255;
                int q16 = qa * 2 + s;
                const __half* wp = Wl + ((size_t)(q16 * 64 + colblk * 16) * 64 + j4 * 4) * 2;
                cp_async16(wb + (uint32_t)(s * 1024 + j4 * 4) * 4u, wp, 16);
            }
        }
        cp_commit();
    };

    issue(0, 0);
    for (int q = 0; q < Q; q++) {
        if (q + 1 < Q) {
            issue(q + 1, (q + 1) & 1);
            asm volatile("cp.async.wait_group 1;" ::: "memory");
        } else {
            asm volatile("cp.async.wait_group 0;" ::: "memory");
        }
        __syncthreads();

        const uint32_t* Xb = Xs + (q & 1) * 2560;
        const uint32_t* Wb = Ws + (q & 1) * 2048;
#pragma unroll
        for (int s = 0; s < 2; s++) {
            const int kbu = s * 8;          // uint offset of K16 base within row
            uint32_t a[2][4];
#pragma unroll
            for (int mt = 0; mt < 2; mt++) {
                int rr = warp_m * 32 + mt * 16 + gid;
                a[mt][0] = Xb[rr * 20 + kbu + thid];
                a[mt][1] = Xb[(rr + 8) * 20 + kbu + thid];
                a[mt][2] = Xb[rr * 20 + kbu + 4 + thid];
                a[mt][3] = Xb[(rr + 8) * 20 + kbu + 4 + thid];
            }
            const uint32_t* Bb = Wb + ((s * 16 + warp_n * 8) * 32 + lane) * 2;
#pragma unroll
            for (int nt = 0; nt < 8; nt++) {
                uint2 bb = *(const uint2*)(Bb + nt * 64);
                mma_f16(acc[0][nt], a[0], bb.x, bb.y);
                mma_f16(acc[1][nt], a[1], bb.x, bb.y);
            }
        }
        __syncthreads();
    }

    // ---- fused LSTM epilogue ----
    const bool odd = (lane & 1);
    const int featbase = (col0 + warp_n * 64) >> 2;
#pragma unroll
    for (int mt = 0; mt < 2; mt++) {
        int rbase = row0 + warp_m * 32 + mt * 16 + gid;
#pragma unroll
        for (int nt = 0; nt < 8; nt++) {
            int colL = warp_n * 64 + nt * 8 + thid * 2;
            float b0 = pb[col0 + colL], b1 = pb[col0 + colL + 1];
            float v00 = acc[mt][nt][0] + b0;
            float v01 = acc[mt][nt][1] + b1;
            float v10 = acc[mt][nt][2] + b0;
            float v11 = acc[mt][nt][3] + b1;
            float s0 = odd ? v00 : v10;
            float s1 = odd ? v01 : v11;
            float t0 = __shfl_xor_sync(0xFFFFFFFFu, s0, 1);
            float t1 = __shfl_xor_sync(0xFFFFFFFFu, s1, 1);
            float gi = odd ? t0 : v00;
            float gf = odd ? t1 : v01;
            float gg = odd ? v10 : t0;
            float go = odd ? v11 : t1;
            int row  = rbase + (odd ? 8 : 0);
            int feat = featbase + nt * 2 + (thid >> 1);
            if (row < N) {
                size_t o = (size_t)row * 128 + feat;
                float cp = c[o];
                float cn = sigmoidf(gf) * cp + sigmoidf(gi) * tanhf(gg);
                hout[o] = __float2half_rn(sigmoidf(go) * tanhf(cn));
                c[o] = fmaxf(cn, 0.f);
            }
        }
    }
}

// ---------------- CSR gather (half in, half out, fp32 accumulate) ----------------
__global__ void gather2(const __half* __restrict__ ta, const int* __restrict__ offa,
                        const int* __restrict__ csra,
                        const __half* __restrict__ tb, const int* __restrict__ offb,
                        const int* __restrict__ csrb,
                        __half* __restrict__ m, int N)
{
    int gw   = (blockIdx.x * blockDim.x + threadIdx.x) >> 5;
    int lane = threadIdx.x & 31;
    if (gw >= N) return;
    float4 acc = make_float4(0.f, 0.f, 0.f, 0.f);
    int s0 = gw ? offa[gw - 1] : 0;
    int e0 = offa[gw];
    for (int e = s0; e < e0; e++) {
        int src = csra[e];
        uint2 raw = *(const uint2*)(ta + (size_t)src * 128 + lane * 4);
        float2 f0 = __half22float2(*(__half2*)&raw.x);
        float2 f1 = __half22float2(*(__half2*)&raw.y);
        acc.x += f0.x; acc.y += f0.y; acc.z += f1.x; acc.w += f1.y;
    }
    int s1 = gw ? offb[gw - 1] : 0;
    int e1 = offb[gw];
    for (int e = s1; e < e1; e++) {
        int src = csrb[e];
        uint2 raw = *(const uint2*)(tb + (size_t)src * 128 + lane * 4);
        float2 f0 = __half22float2(*(__half2*)&raw.x);
        float2 f1 = __half22float2(*(__half2*)&raw.y);
        acc.x += f0.x; acc.y += f0.y; acc.z += f1.x; acc.w += f1.y;
    }
    uint2 outv;
    outv.x = pk2h(acc.x, acc.y);
    outv.y = pk2h(acc.z, acc.w);
    *(uint2*)(m + (size_t)gw * 128 + lane * 4) = outv;
}

// ---------------- attention pooling ----------------
__global__ void pool_reset(unsigned* maxu, float* sum, float* red) {
    if (threadIdx.x == 0) { *maxu = 0u; *sum = 0.f; }
    if (threadIdx.x < HDIM) red[threadIdx.x] = 0.f;
}

__global__ void gate_logits(const float* __restrict__ cc, const float* __restrict__ gW,
                            const float* __restrict__ gb, float* __restrict__ z,
                            unsigned* __restrict__ maxu, int n)
{
    __shared__ float smax[8];
    int gw   = (blockIdx.x * blockDim.x + threadIdx.x) >> 5;
    int lane = threadIdx.x & 31;
    int wid  = threadIdx.x >> 5;
    float myz = -1e30f;
    if (gw < n) {
        float4 a = *(const float4*)(cc + (size_t)gw * HDIM + lane * 4);
        float4 b = *(const float4*)(gW + lane * 4);
        float p = a.x * b.x + a.y * b.y + a.z * b.z + a.w * b.w;
        p += __shfl_down_sync(0xFFFFFFFFu, p, 16);
        p += __shfl_down_sync(0xFFFFFFFFu, p, 8);
        p += __shfl_down_sync(0xFFFFFFFFu, p, 4);
        p += __shfl_down_sync(0xFFFFFFFFu, p, 2);
        p += __shfl_down_sync(0xFFFFFFFFu, p, 1);
        if (lane == 0) {
            myz = p + gb[0];
            z[gw] = myz;
        }
    }
    if (lane == 0) smax[wid] = myz;
    __syncthreads();
    if (threadIdx.x == 0) {
        float mx = smax[0];
#pragma unroll
        for (int w = 1; w < 8; w++) mx = fmaxf(mx, smax[w]);
        atomicMax(maxu, f2ord(mx));
    }
}

__global__ void softmax_accum(const float* __restrict__ cc, const float* __restrict__ z,
                              const unsigned* __restrict__ maxu,
                              float* __restrict__ sum, float* __restrict__ red, int n)
{
    int t = threadIdx.x;
    float zmax = ord2f(*maxu);
    int c0 = blockIdx.x * 64;
    float acc = 0.f, wsum = 0.f;
    for (int i = 0; i < 64; i++) {
        int c = c0 + i;
        if (c >= n) break;
        float w = expf(z[c] - zmax);
        acc  += w * cc[(size_t)c * HDIM + t];
        wsum += w;
    }
    atomicAdd(&red[t], acc);
    if (t == 0) atomicAdd(sum, wsum);
}

__global__ void final_mlp(const float* __restrict__ red, const float* __restrict__ sum,
                          const float* __restrict__ mW1, const float* __restrict__ mb1,
                          const float* __restrict__ mW2, const float* __restrict__ mb2,
                          const float* __restrict__ mW3, const float* __restrict__ mb3,
                          float* __restrict__ out)
{
    __shared__ float x0[HDIM], x1[HDIM], x2[HDIM];
    int t = threadIdx.x;
    x0[t] = red[t] / (*sum);
    __syncthreads();
    {
        float a = mb1[t];
        for (int k = 0; k < HDIM; k++) a = fmaf(x0[k], mW1[t * HDIM + k], a);
        x1[t] = fmaxf(a, 0.f);
    }
    __syncthreads();
    {
        float a = mb2[t];
        for (int k = 0; k < HDIM; k++) a = fmaf(x1[k], mW2[t * HDIM + k], a);
        x2[t] = fmaxf(a, 0.f);
    }
    __syncthreads();
    if (t < 2) {
        float a = mb3[t];
        for (int k = 0; k < HDIM; k++) a = fmaf(x2[k], mW3[t * HDIM + k], a);
        out[t] = a;
    }
}

// ---------------- host orchestration ----------------
#define MLP_SMEM  (12672 * 4)    // 50688 bytes
#define LSTM_SMEM (9216 * 4)     // 36864 bytes

static void build_csr(const int* src, const int* dst, int* off, int* csr,
                      int* cnt, int* part, int Ndst)
{
    cudaMemsetAsync(cnt, 0, (size_t)Ndst * sizeof(int));
    hist_k<<<(NEDG + 255) / 256, 256>>>(dst, cnt, NEDG);
    int NB = (Ndst + 1023) / 1024;
    scan1_k<<<NB, 1024>>>(cnt, off, part, Ndst);
    scan2_k<<<1, 512>>>(part, NB);
    scan3_k<<<NB, 1024>>>(off, part, Ndst);
    fill_k<<<(NEDG + 255) / 256, 256>>>(src, dst, off, csr, NEDG);
}

extern "C" void kernel_launch(void* const* d_in, const int* in_sizes, int n_in,
                              void* d_out, int out_size)
{
    const int*   var_x    = (const int*)  d_in[0];
    const int*   clause_x = (const int*)  d_in[1];
    const int*   pos_src  = (const int*)  d_in[2];
    const int*   pos_dst  = (const int*)  d_in[3];
    const int*   neg_src  = (const int*)  d_in[4];
    const int*   neg_dst  = (const int*)  d_in[5];
    const int*   posr_src = (const int*)  d_in[6];
    const int*   posr_dst = (const int*)  d_in[7];
    const int*   negr_src = (const int*)  d_in[8];
    const int*   negr_dst = (const int*)  d_in[9];
    const float* embed    = (const float*)d_in[10];
    const float* eW1      = (const float*)d_in[11];
    const float* eb1      = (const float*)d_in[12];
    const float* eW2      = (const float*)d_in[13];
    const float* eb2      = (const float*)d_in[14];
    const float* eW3      = (const float*)d_in[15];
    const float* eb3      = (const float*)d_in[16];
    const float* Wih      = (const float*)d_in[17];
    const float* Whh      = (const float*)d_in[18];
    const float* bih      = (const float*)d_in[19];
    const float* bhh      = (const float*)d_in[20];
    const float* gW       = (const float*)d_in[21];
    const float* gb       = (const float*)d_in[22];
    const float* mW1      = (const float*)d_in[23];
    const float* mb1      = (const float*)d_in[24];
    const float* mW2      = (const float*)d_in[25];
    const float* mb2      = (const float*)d_in[26];
    const float* mW3      = (const float*)d_in[27];
    const float* mb3      = (const float*)d_in[28];
    float* out = (float*)d_out;

    cudaFuncSetAttribute(mlp3_fused, cudaFuncAttributeMaxDynamicSharedMemorySize, MLP_SMEM);
    cudaFuncSetAttribute(gemm_lstm, cudaFuncAttributeMaxDynamicSharedMemorySize, LSTM_SMEM);

    __half *hv, *hv2, *hc, *hc2, *t1, *t2, *m, *wh;
    float *cv, *cc, *z, *red, *sum, *pb;
    unsigned* maxu;
    int *off, *csr, *cnt, *part;
    cudaGetSymbolAddress((void**)&hv,   g_hv);
    cudaGetSymbolAddress((void**)&hv2,  g_hv2);
    cudaGetSymbolAddress((void**)&hc,   g_hc);
    cudaGetSymbolAddress((void**)&hc2,  g_hc2);
    cudaGetSymbolAddress((void**)&t1,   g_t1);
    cudaGetSymbolAddress((void**)&t2,   g_t2);
    cudaGetSymbolAddress((void**)&m,    g_m);
    cudaGetSymbolAddress((void**)&cv,   g_cv);
    cudaGetSymbolAddress((void**)&cc,   g_cc);
    cudaGetSymbolAddress((void**)&z,    g_z);
    cudaGetSymbolAddress((void**)&red,  g_red);
    cudaGetSymbolAddress((void**)&sum,  g_sum);
    cudaGetSymbolAddress((void**)&maxu, g_maxu);
    cudaGetSymbolAddress((void**)&wh,   g_wh);
    cudaGetSymbolAddress((void**)&pb,   g_pb);
    cudaGetSymbolAddress((void**)&off,  g_off);
    cudaGetSymbolAddress((void**)&csr,  g_csr);
    cudaGetSymbolAddress((void**)&cnt,  g_cnt);
    cudaGetSymbolAddress((void**)&part, g_part);

    int* off_e[4] = {off, off + NCLS, off + 2 * NCLS, off + 3 * NCLS};
    int* csr_e[4] = {csr, csr + NEDG, csr + 2 * NEDG, csr + 3 * NEDG};

    const __half* E1 = wh + OFFH_E1;
    const __half* E2 = wh + OFFH_E2;
    const __half* E3 = wh + OFFH_E3;
    const __half* WIH = wh + OFFH_WIH;
    const __half* WHH = wh + OFFH_WHH;

    const int vgrid = (NVAR + 127) / 128;   // 782
    const int cgrid = (NCLS + 127) / 128;   // 3125
    const int EB = 16384;                    // per-etype weight block (halfs)

    prep_all<<<(PREP_N + 255) / 256, 256>>>(eW1, eW2, eW3, Wih, Whh, bih, bhh, wh, pb);
    init_embed<<<(NVAR * HDIM + 255) / 256, 256>>>(var_x,    embed, hv, cv, NVAR);
    init_embed<<<(NCLS * HDIM + 255) / 256, 256>>>(clause_x, embed, hc, cc, NCLS);

    __half* hcs[2] = {hc, hc2};
    __half* hvs[2] = {hv, hv2};
    int hci = 0, hvi = 0;

    for (int s = 0; s < NSTEPS; s++) {
        // ---- relation 0: var -> clause ----
        mlp3_fused<<<vgrid, 256, MLP_SMEM>>>(cv, E1 + 0 * EB, E2 + 0 * EB, E3 + 0 * EB,
                                             eb1 + 0 * HDIM, eb2 + 0 * HDIM, eb3 + 0 * HDIM,
                                             t1, NVAR);
        mlp3_fused<<<vgrid, 256, MLP_SMEM>>>(cv, E1 + 1 * EB, E2 + 1 * EB, E3 + 1 * EB,
                                             eb1 + 1 * HDIM, eb2 + 1 * HDIM, eb3 + 1 * HDIM,
                                             t2, NVAR);
        if (s == 0) {
            build_csr(pos_src,  pos_dst,  off_e[0], csr_e[0], cnt, part, NCLS);
            build_csr(neg_src,  neg_dst,  off_e[1], csr_e[1], cnt, part, NCLS);
            build_csr(posr_src, posr_dst, off_e[2], csr_e[2], cnt, part, NVAR);
            build_csr(negr_src, negr_dst, off_e[3], csr_e[3], cnt, part, NVAR);
        }
        gather2<<<(NCLS * 32 + 255) / 256, 256>>>(t1, off_e[0], csr_e[0],
                                                  t2, off_e[1], csr_e[1], m, NCLS);
        {   // clause LSTM
            dim3 grid(4, cgrid);
            gemm_lstm<<<grid, 256, LSTM_SMEM>>>(m, hcs[hci], WIH, WHH, pb,
                                                hcs[hci ^ 1], cc, NCLS);
            hci ^= 1;
        }

        // ---- relation 1: clause -> var ----
        mlp3_fused<<<cgrid, 256, MLP_SMEM>>>(cc, E1 + 2 * EB, E2 + 2 * EB, E3 + 2 * EB,
                                             eb1 + 2 * HDIM, eb2 + 2 * HDIM, eb3 + 2 * HDIM,
                                             t1, NCLS);
        mlp3_fused<<<cgrid, 256, MLP_SMEM>>>(cc, E1 + 3 * EB, E2 + 3 * EB, E3 + 3 * EB,
                                             eb1 + 3 * HDIM, eb2 + 3 * HDIM, eb3 + 3 * HDIM,
                                             t2, NCLS);
        gather2<<<(NVAR * 32 + 255) / 256, 256>>>(t1, off_e[2], csr_e[2],
                                                  t2, off_e[3], csr_e[3], m, NVAR);
        {   // var LSTM
            dim3 grid(4, vgrid);
            gemm_lstm<<<grid, 256, LSTM_SMEM>>>(m, hvs[hvi], WIH + 65536, WHH + 65536,
                                                pb + 512, hvs[hvi ^ 1], cv, NVAR);
            hvi ^= 1;
        }
    }

    // ---- GlobalAttentionPooling + final MLP ----
    pool_reset<<<1, 128>>>(maxu, sum, red);
    gate_logits<<<(NCLS * 32 + 255) / 256, 256>>>(cc, gW, gb, z, maxu, NCLS);
    softmax_accum<<<(NCLS + 63) / 64, 128>>>(cc, z, maxu, sum, red, NCLS);
    final_mlp<<<1, 128>>>(red, sum, mW1, mb1, mW2, mb2, mW3, mb3, out);
}

// round 13
// speedup vs baseline: 1.6219x; 1.0488x over previous
#include <cuda_runtime.h>
#include <cuda_fp16.h>
#include <math.h>
#include <stdint.h>

#define NVAR   100000
#define NCLS   400000
#define NEDG   600000
#define HDIM   128
#define NSTEPS 9

// ---------------- scratch (device globals) ----------------
__device__ __align__(16) __half g_hv [NVAR * HDIM];
__device__ __align__(16) __half g_hv2[NVAR * HDIM];
__device__ __align__(16) __half g_hc [NCLS * HDIM];
__device__ __align__(16) __half g_hc2[NCLS * HDIM];
__device__ __align__(16) __half g_t1 [NCLS * HDIM];
__device__ __align__(16) __half g_t2 [NCLS * HDIM];
__device__ __align__(16) __half g_m  [NCLS * HDIM];
__device__ float g_cv [NVAR * HDIM];
__device__ float g_cc [NCLS * HDIM];
__device__ float g_z  [NCLS];
__device__ float    g_red[HDIM];
__device__ float    g_sum;
__device__ unsigned g_maxu;
// fp16 fragment-major weights: eW1 | eW2 | eW3 | Wih' | Whh'
#define OFFH_E1  0
#define OFFH_E2  65536
#define OFFH_E3  131072
#define OFFH_WIH 196608
#define OFFH_WHH 327680
#define WH_N     458752
__device__ __align__(16) __half g_wh[WH_N];
__device__ float g_pb[1024];
#define PREP_N  459776
// CSR
__device__ int g_off[4][NCLS];
__device__ int g_csr[4][NEDG];
__device__ int g_cnt[NCLS];
__device__ int g_part[512];

// ---------------- helpers ----------------
__device__ __forceinline__ unsigned f2ord(float f) {
    unsigned b = __float_as_uint(f);
    return (b & 0x80000000u) ? ~b : (b | 0x80000000u);
}
__device__ __forceinline__ float ord2f(unsigned u) {
    unsigned b = (u & 0x80000000u) ? (u ^ 0x80000000u) : ~u;
    return __uint_as_float(b);
}
__device__ __forceinline__ float sigmoidf(float x) { return 1.0f / (1.0f + expf(-x)); }

__device__ __forceinline__ uint32_t pk2h(float a, float b) {
    __half2 h = __floats2half2_rn(a, b);
    return *(uint32_t*)&h;
}
__device__ __forceinline__ uint32_t smem_u32(const void* p) {
    uint32_t a;
    asm("{ .reg .u64 t; cvta.to.shared.u64 t, %1; cvt.u32.u64 %0, t; }" : "=r"(a) : "l"(p));
    return a;
}
__device__ __forceinline__ void cp_async16(uint32_t dst, const void* src, int srcbytes) {
    asm volatile("cp.async.cg.shared.global [%0], [%1], 16, %2;"
                 :: "r"(dst), "l"(src), "r"(srcbytes) : "memory");
}
__device__ __forceinline__ void cp_commit() {
    asm volatile("cp.async.commit_group;" ::: "memory");
}
__device__ __forceinline__ void cp_wait(int rem) {
    if (rem >= 1) asm volatile("cp.async.wait_group 1;" ::: "memory");
    else          asm volatile("cp.async.wait_group 0;" ::: "memory");
}
__device__ __forceinline__ void mma_f16(float* c, const uint32_t* a, uint32_t b0, uint32_t b1) {
    asm volatile(
        "mma.sync.aligned.m16n8k16.row.col.f32.f16.f16.f32 "
        "{%0,%1,%2,%3}, {%4,%5,%6,%7}, {%8,%9}, {%0,%1,%2,%3};"
        : "+f"(c[0]), "+f"(c[1]), "+f"(c[2]), "+f"(c[3])
        : "r"(a[0]), "r"(a[1]), "r"(a[2]), "r"(a[3]), "r"(b0), "r"(b1));
}

// ---------------- fused weight prep: fp16 fragment-major ----------------
__global__ void prep_all(const float* __restrict__ eW1, const float* __restrict__ eW2,
                         const float* __restrict__ eW3, const float* __restrict__ Wih,
                         const float* __restrict__ Whh, const float* __restrict__ bih,
                         const float* __restrict__ bhh,
                         __half* __restrict__ wh, float* __restrict__ pbo)
{
    int i = blockIdx.x * blockDim.x + threadIdx.x;
    if (i >= PREP_N) return;
    if (i < 196608) {               // eW1|eW2|eW3
        const float* src = (i < 65536) ? eW1 : (i < 131072) ? eW2 : eW3;
        int base = (i < 65536) ? OFFH_E1 : (i < 131072) ? OFFH_E2 : OFFH_E3;
        int j = i & 65535;
        int etype = j >> 14;
        int rem = j & 16383;
        int n = rem >> 7, k = rem & 127;
        int hidx = ((k >> 4) * 16 + (n >> 3)) * 128 + ((n & 7) * 4 + ((k & 7) >> 1)) * 4
                   + ((k >> 3) & 1) * 2 + (k & 1);
        wh[base + (etype << 14) + hidx] = __float2half_rn(src[j]);
    } else if (i < 458752) {        // Wih' | Whh'
        int j = i - 196608;
        const float* src = (j < 131072) ? Wih : Whh;
        int base = (j < 131072) ? OFFH_WIH : OFFH_WHH;
        j &= 131071;
        int rel = j >> 16;
        int rem = j & 65535;
        int r_old = rem >> 7, k = rem & 127;
        int gate = r_old >> 7, f = r_old & 127;
        int rn = (f << 2) | gate;
        int hidx = ((k >> 4) * 64 + (rn >> 3)) * 128 + ((rn & 7) * 4 + ((k & 7) >> 1)) * 4
                   + ((k >> 3) & 1) * 2 + (k & 1);
        wh[base + (rel << 16) + hidx] = __float2half_rn(src[j]);
    } else {                        // permuted bias sum (fp32)
        int j = i - 458752;
        int rel = j >> 9;
        int r_old = j & 511;
        int gate = r_old >> 7, f = r_old & 127;
        pbo[(rel << 9) + (f << 2) + gate] = bih[j] + bhh[j];
    }
}

// ---------------- CSR build kernels ----------------
__global__ void hist_k(const int* __restrict__ dst, int* __restrict__ cnt, int E) {
    int i = blockIdx.x * blockDim.x + threadIdx.x;
    if (i < E) atomicAdd(&cnt[dst[i]], 1);
}
__global__ void scan1_k(const int* __restrict__ cnt, int* __restrict__ off,
                        int* __restrict__ part, int N) {
    __shared__ int s[1024];
    int i = blockIdx.x * 1024 + threadIdx.x;
    int v = (i < N) ? cnt[i] : 0;
    s[threadIdx.x] = v;
    __syncthreads();
    for (int d = 1; d < 1024; d <<= 1) {
        int t = (threadIdx.x >= d) ? s[threadIdx.x - d] : 0;
        __syncthreads();
        s[threadIdx.x] += t;
        __syncthreads();
    }
    if (i < N) off[i] = s[threadIdx.x] - v;
    if (threadIdx.x == 1023) part[blockIdx.x] = s[1023];
}
__global__ void scan2_k(int* __restrict__ part, int NB) {
    __shared__ int s[512];
    int v = (threadIdx.x < NB) ? part[threadIdx.x] : 0;
    s[threadIdx.x] = v;
    __syncthreads();
    for (int d = 1; d < 512; d <<= 1) {
        int t = (threadIdx.x >= d) ? s[threadIdx.x - d] : 0;
        __syncthreads();
        s[threadIdx.x] += t;
        __syncthreads();
    }
    if (threadIdx.x < NB) part[threadIdx.x] = s[threadIdx.x] - v;
}
__global__ void scan3_k(int* __restrict__ off, const int* __restrict__ part, int N) {
    int i = blockIdx.x * 1024 + threadIdx.x;
    if (i < N) off[i] += part[blockIdx.x];
}
__global__ void fill_k(const int* __restrict__ src, const int* __restrict__ dst,
                       int* __restrict__ off, int* __restrict__ csr, int E) {
    int i = blockIdx.x * blockDim.x + threadIdx.x;
    if (i >= E) return;
    int p = atomicAdd(&off[dst[i]], 1);
    csr[p] = src[i];
}

// ---------------- init ----------------
__global__ void init_embed(const int* __restrict__ x, const float* __restrict__ embed,
                           __half* __restrict__ h, float* __restrict__ c, int n) {
    int i = blockIdx.x * blockDim.x + threadIdx.x;
    if (i >= n * HDIM) return;
    int node = i >> 7, col = i & 127;
    float v = embed[x[node] * HDIM + col];
    h[i] = __float2half_rn(v);
    c[i] = v;
}

// ============ DUAL-etype fused 3-layer MLP, fp16, 3-stage W pipeline ============
// Smem (uints): Xs0[8192] input frags (read-only) | Xs1[8192] | Wc[3*2048] | sb[768 floats]
__global__ void __launch_bounds__(256, 2)
mlp3_dual(const float* __restrict__ X,
          const __half* __restrict__ Wa1, const __half* __restrict__ Wa2,
          const __half* __restrict__ Wa3,
          const __half* __restrict__ Wb1, const __half* __restrict__ Wb2,
          const __half* __restrict__ Wb3,
          const float* __restrict__ Ba1, const float* __restrict__ Ba2,
          const float* __restrict__ Ba3,
          const float* __restrict__ Bb1, const float* __restrict__ Bb2,
          const float* __restrict__ Bb3,
          __half* __restrict__ Ya, __half* __restrict__ Yb, int N)
{
    extern __shared__ uint32_t smu[];
    uint32_t* Xs0 = smu;                  // 8192
    uint32_t* Xs1 = smu + 8192;           // 8192
    uint32_t* Wc  = smu + 16384;          // 3*2048
    float*    sb  = (float*)(smu + 22528); // 768

    const int tid    = threadIdx.x;
    const int wid    = tid >> 5;
    const int lane   = tid & 31;
    const int warp_m = wid & 3;
    const int warp_n = wid >> 2;
    const int gid    = lane >> 2;
    const int thid   = lane & 3;
    const int row0   = blockIdx.x << 7;

    const uint32_t wcaddr = smem_u32(Wc);

    if (tid < 128) {
        sb[tid]       = Ba1[tid];
        sb[128 + tid] = Ba2[tid];
        sb[256 + tid] = Ba3[tid];
        sb[384 + tid] = Bb1[tid];
        sb[512 + tid] = Bb2[tid];
        sb[640 + tid] = Bb3[tid];
    }

    auto issueW = [&](int g, int st) {
        const __half* Wl =
            (g < 12) ? ((g < 4) ? Wa1 : (g < 8) ? Wa2 : Wa3)
                     : ((g < 16) ? Wb1 : (g < 20) ? Wb2 : Wb3);
        Wl += (size_t)(g & 3) * 4096;
#pragma unroll
        for (int it = 0; it < 2; it++) {
            int idx = it * 256 + tid;
            cp_async16(wcaddr + (uint32_t)(st * 2048 + idx * 4) * 4u, Wl + idx * 8, 16);
        }
        cp_commit();
    };

    issueW(0, 0);
    issueW(1, 1);

    // prologue: X (fp32) -> half2 fragments in Xs0
#pragma unroll
    for (int it = 0; it < 16; it++) {
        int idx = it * 256 + tid;
        int r   = idx & 127;
        int c4  = idx >> 7;
        int gk  = c4 << 2;
        int grow = row0 + r;
        float4 xv = make_float4(0.f, 0.f, 0.f, 0.f);
        if (grow < N) xv = *(const float4*)(X + (size_t)grow * 128 + gk);
        int q16 = gk >> 4;
        int grp = r >> 4;
        int gd  = r & 7;
        int mh  = (r >> 3) & 1;
        int kh8 = (gk >> 3) & 1;
        int t0  = (gk & 7) >> 1;
        int reg = mh + 2 * kh8;
        int base = ((q16 * 8 + grp) * 32 + gd * 4) * 4 + reg;
        Xs0[base + t0 * 4]       = pk2h(xv.x, xv.y);
        Xs0[base + (t0 + 1) * 4] = pk2h(xv.z, xv.w);
    }

    int gc = 0;
    for (int L = 0; L < 6; L++) {
        const int sl = (L >= 3) ? (L - 3) : L;     // sub-layer 0..2
        const uint32_t* XsIn = (sl == 0) ? Xs0 : Xs1;
        __half* Y = (L < 3) ? Ya : Yb;

        float acc[2][8][4];
#pragma unroll
        for (int mt = 0; mt < 2; mt++)
#pragma unroll
            for (int nt = 0; nt < 8; nt++)
#pragma unroll
                for (int r = 0; r < 4; r++) acc[mt][nt][r] = 0.f;

        for (int qc = 0; qc < 4; qc++, gc++) {
            cp_wait(23 - gc);
            __syncthreads();
            if (gc + 2 <= 23) {
                int nx = gc + 2;
                issueW(nx, nx % 3);
            }
            const uint32_t* Wb = Wc + (gc % 3) * 2048;
#pragma unroll
            for (int s = 0; s < 2; s++) {
                const int q16 = qc * 2 + s;
                uint32_t a[2][4];
#pragma unroll
                for (int mt = 0; mt < 2; mt++) {
                    uint4 av = *(const uint4*)(XsIn +
                        ((q16 * 8 + warp_m * 2 + mt) * 32 + lane) * 4);
                    a[mt][0] = av.x; a[mt][1] = av.y; a[mt][2] = av.z; a[mt][3] = av.w;
                }
                const uint32_t* Bb = Wb + ((s * 16 + warp_n * 8) * 32 + lane) * 2;
#pragma unroll
                for (int nt = 0; nt < 8; nt++) {
                    uint2 bb = *(const uint2*)(Bb + nt * 64);
                    mma_f16(acc[0][nt], a[0], bb.x, bb.y);
                    mma_f16(acc[1][nt], a[1], bb.x, bb.y);
                }
            }
        }

        if (sl < 2) {
            if (sl == 1) __syncthreads();   // in-place on Xs1: reads must drain
#pragma unroll
            for (int mt = 0; mt < 2; mt++) {
#pragma unroll
                for (int nt = 0; nt < 8; nt++) {
                    int colL = warp_n * 64 + nt * 8 + thid * 2;
                    float b0 = sb[L * 128 + colL], b1 = sb[L * 128 + colL + 1];
                    float v00 = fmaxf(acc[mt][nt][0] + b0, 0.f);
                    float v01 = fmaxf(acc[mt][nt][1] + b1, 0.f);
                    float v10 = fmaxf(acc[mt][nt][2] + b0, 0.f);
                    float v11 = fmaxf(acc[mt][nt][3] + b1, 0.f);
                    int nq  = warp_n * 4 + (nt >> 1);
                    int kh8 = nt & 1;
                    int ngr = warp_m * 2 + mt;
                    int uidx = ((nq * 8 + ngr) * 32 + gid * 4 + thid) * 4;
                    Xs1[uidx + 2 * kh8]     = pk2h(v00, v01);
                    Xs1[uidx + 1 + 2 * kh8] = pk2h(v10, v11);
                }
            }
        } else {
#pragma unroll
            for (int mt = 0; mt < 2; mt++) {
                int rbase = row0 + warp_m * 32 + mt * 16 + gid;
#pragma unroll
                for (int nt = 0; nt < 8; nt++) {
                    int colL = warp_n * 64 + nt * 8 + thid * 2;
                    float b0 = sb[L * 128 + colL], b1 = sb[L * 128 + colL + 1];
                    uint32_t h01 = pk2h(fmaxf(acc[mt][nt][0] + b0, 0.f),
                                        fmaxf(acc[mt][nt][1] + b1, 0.f));
                    uint32_t h23 = pk2h(fmaxf(acc[mt][nt][2] + b0, 0.f),
                                        fmaxf(acc[mt][nt][3] + b1, 0.f));
                    if (rbase < N)     *(uint32_t*)(Y + (size_t)rbase * 128 + colL)       = h01;
                    if (rbase + 8 < N) *(uint32_t*)(Y + (size_t)(rbase + 8) * 128 + colL) = h23;
                }
            }
        }
    }
}

// ============ LSTM gate GEMM fp16, 3-stage pipeline ============
__global__ void __launch_bounds__(256, 2)
gemm_lstm(const __half* __restrict__ X1, const __half* __restrict__ X2,
          const __half* __restrict__ W1, const __half* __restrict__ W2,
          const float* __restrict__ pb,
          __half* __restrict__ hout, float* __restrict__ c, int N)
{
    extern __shared__ uint32_t smu[];
    // per stage: X 2560 uints | W 2048 uints; 3 stages
    uint32_t* Xs = smu;
    uint32_t* Ws = smu + 3 * 2560;

    const int tid    = threadIdx.x;
    const int wid    = tid >> 5;
    const int lane   = tid & 31;
    const int warp_m = wid & 3;
    const int warp_n = wid >> 2;
    const int gid    = lane >> 2;
    const int thid   = lane & 3;
    const int colblk = blockIdx.x;            // 0..3 (fast dim -> L2-shared X)
    const int row0   = blockIdx.y << 7;
    const int col0   = colblk << 7;
    const int Q      = 8;

    const uint32_t xaddr = smem_u32(Xs);
    const uint32_t waddr = smem_u32(Ws);

    float acc[2][8][4];
#pragma unroll
    for (int mt = 0; mt < 2; mt++)
#pragma unroll
        for (int nt = 0; nt < 8; nt++)
#pragma unroll
            for (int r = 0; r < 4; r++) acc[mt][nt][r] = 0.f;

    auto issue = [&](int q, int st) {
        const int kc = q << 5;
        const uint32_t xb = xaddr + (uint32_t)st * 2560u * 4u;
        const uint32_t wb = waddr + (uint32_t)st * 2048u * 4u;
        const __half* Wl = (q < 4) ? W1 : W2;
        const int qa = q & 3;
#pragma unroll
        for (int it = 0; it < 4; it++) {
            int idx = it * 256 + tid;
            if (idx < 512) {
                int r  = idx >> 2;
                int c8 = idx & 3;
                int gk = kc + c8 * 8;
                int grow = row0 + r;
                const __half* xp = X1;
                int sz = 0;
                if (grow < N) {
                    xp = (gk < 128) ? (X1 + (size_t)grow * 128 + gk)
                                    : (X2 + (size_t)grow * 128 + (gk - 128));
                    sz = 16;
                }
                cp_async16(xb + (uint32_t)(r * 20 + c8 * 4) * 4u, xp, sz);
            } else {
                int j  = idx - 512;
                int s  = j >> 8;
                int j4 = j & 255;
                int q16 = qa * 2 + s;
                const __half* wp = Wl + ((size_t)(q16 * 64 + colblk * 16) * 64 + j4 * 4) * 2;
                cp_async16(wb + (uint32_t)(s * 1024 + j4 * 4) * 4u, wp, 16);
            }
        }
        cp_commit();
    };

    issue(0, 0);
    issue(1, 1);
    for (int q = 0; q < Q; q++) {
        cp_wait(Q - 1 - q);
        __syncthreads();
        if (q + 2 < Q) issue(q + 2, (q + 2) % 3);

        const uint32_t* Xb = Xs + (q % 3) * 2560;
        const uint32_t* Wb = Ws + (q % 3) * 2048;
#pragma unroll
        for (int s = 0; s < 2; s++) {
            const int kbu = s * 8;
            uint32_t a[2][4];
#pragma unroll
            for (int mt = 0; mt < 2; mt++) {
                int rr = warp_m * 32 + mt * 16 + gid;
                a[mt][0] = Xb[rr * 20 + kbu + thid];
                a[mt][1] = Xb[(rr + 8) * 20 + kbu + thid];
                a[mt][2] = Xb[rr * 20 + kbu + 4 + thid];
                a[mt][3] = Xb[(rr + 8) * 20 + kbu + 4 + thid];
            }
            const uint32_t* Bb = Wb + ((s * 16 + warp_n * 8) * 32 + lane) * 2;
#pragma unroll
            for (int nt = 0; nt < 8; nt++) {
                uint2 bb = *(const uint2*)(Bb + nt * 64);
                mma_f16(acc[0][nt], a[0], bb.x, bb.y);
                mma_f16(acc[1][nt], a[1], bb.x, bb.y);
            }
        }
    }

    // ---- fused LSTM epilogue ----
    const bool odd = (lane & 1);
    const int featbase = (col0 + warp_n * 64) >> 2;
#pragma unroll
    for (int mt = 0; mt < 2; mt++) {
        int rbase = row0 + warp_m * 32 + mt * 16 + gid;
#pragma unroll
        for (int nt = 0; nt < 8; nt++) {
            int colL = warp_n * 64 + nt * 8 + thid * 2;
            float b0 = pb[col0 + colL], b1 = pb[col0 + colL + 1];
            float v00 = acc[mt][nt][0] + b0;
            float v01 = acc[mt][nt][1] + b1;
            float v10 = acc[mt][nt][2] + b0;
            float v11 = acc[mt][nt][3] + b1;
            float s0 = odd ? v00 : v10;
            float s1 = odd ? v01 : v11;
            float t0 = __shfl_xor_sync(0xFFFFFFFFu, s0, 1);
            float t1 = __shfl_xor_sync(0xFFFFFFFFu, s1, 1);
            float gi = odd ? t0 : v00;
            float gf = odd ? t1 : v01;
            float gg = odd ? v10 : t0;
            float go = odd ? v11 : t1;
            int row  = rbase + (odd ? 8 : 0);
            int feat = featbase + nt * 2 + (thid >> 1);
            if (row < N) {
                size_t o = (size_t)row * 128 + feat;
                float cp = c[o];
                float cn = sigmoidf(gf) * cp + sigmoidf(gi) * tanhf(gg);
                hout[o] = __float2half_rn(sigmoidf(go) * tanhf(cn));
                c[o] = fmaxf(cn, 0.f);
            }
        }
    }
}

// ---------------- CSR gather (half in/out, fp32 accumulate) ----------------
__global__ void gather2(const __half* __restrict__ ta, const int* __restrict__ offa,
                        const int* __restrict__ csra,
                        const __half* __restrict__ tb, const int* __restrict__ offb,
                        const int* __restrict__ csrb,
                        __half* __restrict__ m, int N)
{
    int gw   = (blockIdx.x * blockDim.x + threadIdx.x) >> 5;
    int lane = threadIdx.x & 31;
    if (gw >= N) return;
    float4 acc = make_float4(0.f, 0.f, 0.f, 0.f);
    int s0 = gw ? offa[gw - 1] : 0;
    int e0 = offa[gw];
    for (int e = s0; e < e0; e++) {
        int src = csra[e];
        uint2 raw = *(const uint2*)(ta + (size_t)src * 128 + lane * 4);
        float2 f0 = __half22float2(*(__half2*)&raw.x);
        float2 f1 = __half22float2(*(__half2*)&raw.y);
        acc.x += f0.x; acc.y += f0.y; acc.z += f1.x; acc.w += f1.y;
    }
    int s1 = gw ? offb[gw - 1] : 0;
    int e1 = offb[gw];
    for (int e = s1; e < e1; e++) {
        int src = csrb[e];
        uint2 raw = *(const uint2*)(tb + (size_t)src * 128 + lane * 4);
        float2 f0 = __half22float2(*(__half2*)&raw.x);
        float2 f1 = __half22float2(*(__half2*)&raw.y);
        acc.x += f0.x; acc.y += f0.y; acc.z += f1.x; acc.w += f1.y;
    }
    uint2 outv;
    outv.x = pk2h(acc.x, acc.y);
    outv.y = pk2h(acc.z, acc.w);
    *(uint2*)(m + (size_t)gw * 128 + lane * 4) = outv;
}

// ---------------- attention pooling ----------------
__global__ void pool_reset(unsigned* maxu, float* sum, float* red) {
    if (threadIdx.x == 0) { *maxu = 0u; *sum = 0.f; }
    if (threadIdx.x < HDIM) red[threadIdx.x] = 0.f;
}

__global__ void gate_logits(const float* __restrict__ cc, const float* __restrict__ gW,
                            const float* __restrict__ gb, float* __restrict__ z,
                            unsigned* __restrict__ maxu, int n)
{
    __shared__ float smax[8];
    int gw   = (blockIdx.x * blockDim.x + threadIdx.x) >> 5;
    int lane = threadIdx.x & 31;
    int wid  = threadIdx.x >> 5;
    float myz = -1e30f;
    if (gw < n) {
        float4 a = *(const float4*)(cc + (size_t)gw * HDIM + lane * 4);
        float4 b = *(const float4*)(gW + lane * 4);
        float p = a.x * b.x + a.y * b.y + a.z * b.z + a.w * b.w;
        p += __shfl_down_sync(0xFFFFFFFFu, p, 16);
        p += __shfl_down_sync(0xFFFFFFFFu, p, 8);
        p += __shfl_down_sync(0xFFFFFFFFu, p, 4);
        p += __shfl_down_sync(0xFFFFFFFFu, p, 2);
        p += __shfl_down_sync(0xFFFFFFFFu, p, 1);
        if (lane == 0) {
            myz = p + gb[0];
            z[gw] = myz;
        }
    }
    if (lane == 0) smax[wid] = myz;
    __syncthreads();
    if (threadIdx.x == 0) {
        float mx = smax[0];
#pragma unroll
        for (int w = 1; w < 8; w++) mx = fmaxf(mx, smax[w]);
        atomicMax(maxu, f2ord(mx));
    }
}

__global__ void softmax_accum(const float* __restrict__ cc, const float* __restrict__ z,
                              const unsigned* __restrict__ maxu,
                              float* __restrict__ sum, float* __restrict__ red, int n)
{
    int t = threadIdx.x;
    float zmax = ord2f(*maxu);
    int c0 = blockIdx.x * 64;
    float acc = 0.f, wsum = 0.f;
    for (int i = 0; i < 64; i++) {
        int c = c0 + i;
        if (c >= n) break;
        float w = expf(z[c] - zmax);
        acc  += w * cc[(size_t)c * HDIM + t];
        wsum += w;
    }
    atomicAdd(&red[t], acc);
    if (t == 0) atomicAdd(sum, wsum);
}

__global__ void final_mlp(const float* __restrict__ red, const float* __restrict__ sum,
                          const float* __restrict__ mW1, const float* __restrict__ mb1,
                          const float* __restrict__ mW2, const float* __restrict__ mb2,
                          const float* __restrict__ mW3, const float* __restrict__ mb3,
                          float* __restrict__ out)
{
    __shared__ float x0[HDIM], x1[HDIM], x2[HDIM];
    int t = threadIdx.x;
    x0[t] = red[t] / (*sum);
    __syncthreads();
    {
        float a = mb1[t];
        for (int k = 0; k < HDIM; k++) a = fmaf(x0[k], mW1[t * HDIM + k], a);
        x1[t] = fmaxf(a, 0.f);
    }
    __syncthreads();
    {
        float a = mb2[t];
        for (int k = 0; k < HDIM; k++) a = fmaf(x1[k], mW2[t * HDIM + k], a);
        x2[t] = fmaxf(a, 0.f);
    }
    __syncthreads();
    if (t < 2) {
        float a = mb3[t];
        for (int k = 0; k < HDIM; k++) a = fmaf(x2[k], mW3[t * HDIM + k], a);
        out[t] = a;
    }
}

// ---------------- host orchestration ----------------
#define MLP_SMEM  (23296 * 4)    // 93184 bytes  -> 2 CTAs/SM
#define LSTM_SMEM (13824 * 4)    // 55296 bytes  -> 2 CTAs/SM

static void build_csr(const int* src, const int* dst, int* off, int* csr,
                      int* cnt, int* part, int Ndst)
{
    cudaMemsetAsync(cnt, 0, (size_t)Ndst * sizeof(int));
    hist_k<<<(NEDG + 255) / 256, 256>>>(dst, cnt, NEDG);
    int NB = (Ndst + 1023) / 1024;
    scan1_k<<<NB, 1024>>>(cnt, off, part, Ndst);
    scan2_k<<<1, 512>>>(part, NB);
    scan3_k<<<NB, 1024>>>(off, part, Ndst);
    fill_k<<<(NEDG + 255) / 256, 256>>>(src, dst, off, csr, NEDG);
}

extern "C" void kernel_launch(void* const* d_in, const int* in_sizes, int n_in,
                              void* d_out, int out_size)
{
    const int*   var_x    = (const int*)  d_in[0];
    const int*   clause_x = (const int*)  d_in[1];
    const int*   pos_src  = (const int*)  d_in[2];
    const int*   pos_dst  = (const int*)  d_in[3];
    const int*   neg_src  = (const int*)  d_in[4];
    const int*   neg_dst  = (const int*)  d_in[5];
    const int*   posr_src = (const int*)  d_in[6];
    const int*   posr_dst = (const int*)  d_in[7];
    const int*   negr_src = (const int*)  d_in[8];
    const int*   negr_dst = (const int*)  d_in[9];
    const float* embed    = (const float*)d_in[10];
    const float* eW1      = (const float*)d_in[11];
    const float* eb1      = (const float*)d_in[12];
    const float* eW2      = (const float*)d_in[13];
    const float* eb2      = (const float*)d_in[14];
    const float* eW3      = (const float*)d_in[15];
    const float* eb3      = (const float*)d_in[16];
    const float* Wih      = (const float*)d_in[17];
    const float* Whh      = (const float*)d_in[18];
    const float* bih      = (const float*)d_in[19];
    const float* bhh      = (const float*)d_in[20];
    const float* gW       = (const float*)d_in[21];
    const float* gb       = (const float*)d_in[22];
    const float* mW1      = (const float*)d_in[23];
    const float* mb1      = (const float*)d_in[24];
    const float* mW2      = (const float*)d_in[25];
    const float* mb2      = (const float*)d_in[26];
    const float* mW3      = (const float*)d_in[27];
    const float* mb3      = (const float*)d_in[28];
    float* out = (float*)d_out;

    cudaFuncSetAttribute(mlp3_dual, cudaFuncAttributeMaxDynamicSharedMemorySize, MLP_SMEM);
    cudaFuncSetAttribute(gemm_lstm, cudaFuncAttributeMaxDynamicSharedMemorySize, LSTM_SMEM);

    __half *hv, *hv2, *hc, *hc2, *t1, *t2, *m, *wh;
    float *cv, *cc, *z, *red, *sum, *pb;
    unsigned* maxu;
    int *off, *csr, *cnt, *part;
    cudaGetSymbolAddress((void**)&hv,   g_hv);
    cudaGetSymbolAddress((void**)&hv2,  g_hv2);
    cudaGetSymbolAddress((void**)&hc,   g_hc);
    cudaGetSymbolAddress((void**)&hc2,  g_hc2);
    cudaGetSymbolAddress((void**)&t1,   g_t1);
    cudaGetSymbolAddress((void**)&t2,   g_t2);
    cudaGetSymbolAddress((void**)&m,    g_m);
    cudaGetSymbolAddress((void**)&cv,   g_cv);
    cudaGetSymbolAddress((void**)&cc,   g_cc);
    cudaGetSymbolAddress((void**)&z,    g_z);
    cudaGetSymbolAddress((void**)&red,  g_red);
    cudaGetSymbolAddress((void**)&sum,  g_sum);
    cudaGetSymbolAddress((void**)&maxu, g_maxu);
    cudaGetSymbolAddress((void**)&wh,   g_wh);
    cudaGetSymbolAddress((void**)&pb,   g_pb);
    cudaGetSymbolAddress((void**)&off,  g_off);
    cudaGetSymbolAddress((void**)&csr,  g_csr);
    cudaGetSymbolAddress((void**)&cnt,  g_cnt);
    cudaGetSymbolAddress((void**)&part, g_part);

    int* off_e[4] = {off, off + NCLS, off + 2 * NCLS, off + 3 * NCLS};
    int* csr_e[4] = {csr, csr + NEDG, csr + 2 * NEDG, csr + 3 * NEDG};

    const __half* E1 = wh + OFFH_E1;
    const __half* E2 = wh + OFFH_E2;
    const __half* E3 = wh + OFFH_E3;
    const __half* WIH = wh + OFFH_WIH;
    const __half* WHH = wh + OFFH_WHH;

    const int vgrid = (NVAR + 127) / 128;   // 782
    const int cgrid = (NCLS + 127) / 128;   // 3125
    const int EB = 16384;                    // per-etype weight block (halfs)

    prep_all<<<(PREP_N + 255) / 256, 256>>>(eW1, eW2, eW3, Wih, Whh, bih, bhh, wh, pb);
    init_embed<<<(NVAR * HDIM + 255) / 256, 256>>>(var_x,    embed, hv, cv, NVAR);
    init_embed<<<(NCLS * HDIM + 255) / 256, 256>>>(clause_x, embed, hc, cc, NCLS);

    __half* hcs[2] = {hc, hc2};
    __half* hvs[2] = {hv, hv2};
    int hci = 0, hvi = 0;

    for (int s = 0; s < NSTEPS; s++) {
        // ---- relation 0: var -> clause (etypes 0,1 fused) ----
        mlp3_dual<<<vgrid, 256, MLP_SMEM>>>(cv,
            E1 + 0 * EB, E2 + 0 * EB, E3 + 0 * EB,
            E1 + 1 * EB, E2 + 1 * EB, E3 + 1 * EB,
            eb1 + 0 * HDIM, eb2 + 0 * HDIM, eb3 + 0 * HDIM,
            eb1 + 1 * HDIM, eb2 + 1 * HDIM, eb3 + 1 * HDIM,
            t1, t2, NVAR);
        if (s == 0) {
            build_csr(pos_src,  pos_dst,  off_e[0], csr_e[0], cnt, part, NCLS);
            build_csr(neg_src,  neg_dst,  off_e[1], csr_e[1], cnt, part, NCLS);
            build_csr(posr_src, posr_dst, off_e[2], csr_e[2], cnt, part, NVAR);
            build_csr(negr_src, negr_dst, off_e[3], csr_e[3], cnt, part, NVAR);
        }
        gather2<<<(NCLS * 32 + 255) / 256, 256>>>(t1, off_e[0], csr_e[0],
                                                  t2, off_e[1], csr_e[1], m, NCLS);
        {
            dim3 grid(4, cgrid);
            gemm_lstm<<<grid, 256, LSTM_SMEM>>>(m, hcs[hci], WIH, WHH, pb,
                                                hcs[hci ^ 1], cc, NCLS);
            hci ^= 1;
        }

        // ---- relation 1: clause -> var (etypes 2,3 fused) ----
        mlp3_dual<<<cgrid, 256, MLP_SMEM>>>(cc,
            E1 + 2 * EB, E2 + 2 * EB, E3 + 2 * EB,
            E1 + 3 * EB, E2 + 3 * EB, E3 + 3 * EB,
            eb1 + 2 * HDIM, eb2 + 2 * HDIM, eb3 + 2 * HDIM,
            eb1 + 3 * HDIM, eb2 + 3 * HDIM, eb3 + 3 * HDIM,
            t1, t2, NCLS);
        gather2<<<(NVAR * 32 + 255) / 256, 256>>>(t1, off_e[2], csr_e[2],
                                                  t2, off_e[3], csr_e[3], m, NVAR);
        {
            dim3 grid(4, vgrid);
            gemm_lstm<<<grid, 256, LSTM_SMEM>>>(m, hvs[hvi], WIH + 65536, WHH + 65536,
                                                pb + 512, hvs[hvi ^ 1], cv, NVAR);
            hvi ^= 1;
        }
    }

    // ---- GlobalAttentionPooling + final MLP ----
    pool_reset<<<1, 128>>>(maxu, sum, red);
    gate_logits<<<(NCLS * 32 + 255) / 256, 256>>>(cc, gW, gb, z, maxu, NCLS);
    softmax_accum<<<(NCLS + 63) / 64, 128>>>(cc, z, maxu, sum, red, NCLS);
    final_mlp<<<1, 128>>>(red, sum, mW1, mb1, mW2, mb2, mW3, mb3, out);
}

// round 14
// speedup vs baseline: 1.7045x; 1.0509x over previous
#include <cuda_runtime.h>
#include <cuda_fp16.h>
#include <math.h>
#include <stdint.h>

#define NVAR   100000
#define NCLS   400000
#define NEDG   600000
#define HDIM   128
#define NSTEPS 9

// ---------------- scratch (device globals) ----------------
__device__ __align__(16) __half g_hv [NVAR * HDIM];
__device__ __align__(16) __half g_hv2[NVAR * HDIM];
__device__ __align__(16) __half g_hc [NCLS * HDIM];
__device__ __align__(16) __half g_hc2[NCLS * HDIM];
__device__ __align__(16) __half g_t1 [NCLS * HDIM];
__device__ __align__(16) __half g_t2 [NCLS * HDIM];
__device__ __align__(16) __half g_m  [NCLS * HDIM];
__device__ float g_cv [NVAR * HDIM];
__device__ float g_cc [NCLS * HDIM];
__device__ float g_z  [NCLS];
__device__ float    g_red[HDIM];
__device__ float    g_sum;
__device__ unsigned g_maxu;
// fp16 PAIRED fragment-major weights: eW1 | eW2 | eW3 | Wih' | Whh'
#define OFFH_E1  0
#define OFFH_E2  65536
#define OFFH_E3  131072
#define OFFH_WIH 196608
#define OFFH_WHH 327680
#define WH_N     458752
__device__ __align__(16) __half g_wh[WH_N];
__device__ float g_pb[1024];
#define PREP_N  459776
// CSR
__device__ int g_off[4][NCLS];
__device__ int g_csr[4][NEDG];
__device__ int g_cnt[NCLS];
__device__ int g_part[512];

// ---------------- helpers ----------------
__device__ __forceinline__ unsigned f2ord(float f) {
    unsigned b = __float_as_uint(f);
    return (b & 0x80000000u) ? ~b : (b | 0x80000000u);
}
__device__ __forceinline__ float ord2f(unsigned u) {
    unsigned b = (u & 0x80000000u) ? (u ^ 0x80000000u) : ~u;
    return __uint_as_float(b);
}
__device__ __forceinline__ float sigmoidf(float x) { return 1.0f / (1.0f + expf(-x)); }

__device__ __forceinline__ uint32_t pk2h(float a, float b) {
    __half2 h = __floats2half2_rn(a, b);
    return *(uint32_t*)&h;
}
__device__ __forceinline__ uint32_t smem_u32(const void* p) {
    uint32_t a;
    asm("{ .reg .u64 t; cvta.to.shared.u64 t, %1; cvt.u32.u64 %0, t; }" : "=r"(a) : "l"(p));
    return a;
}
__device__ __forceinline__ void cp_async16(uint32_t dst, const void* src, int srcbytes) {
    asm volatile("cp.async.cg.shared.global [%0], [%1], 16, %2;"
                 :: "r"(dst), "l"(src), "r"(srcbytes) : "memory");
}
__device__ __forceinline__ void cp_commit() {
    asm volatile("cp.async.commit_group;" ::: "memory");
}
__device__ __forceinline__ void cp_wait(int rem) {
    if (rem >= 1) asm volatile("cp.async.wait_group 1;" ::: "memory");
    else          asm volatile("cp.async.wait_group 0;" ::: "memory");
}
__device__ __forceinline__ void mma_f16(float* c, const uint32_t* a, uint32_t b0, uint32_t b1) {
    asm volatile(
        "mma.sync.aligned.m16n8k16.row.col.f32.f16.f16.f32 "
        "{%0,%1,%2,%3}, {%4,%5,%6,%7}, {%8,%9}, {%0,%1,%2,%3};"
        : "+f"(c[0]), "+f"(c[1]), "+f"(c[2]), "+f"(c[3])
        : "r"(a[0]), "r"(a[1]), "r"(a[2]), "r"(a[3]), "r"(b0), "r"(b1));
}

// ---------------- fused weight prep: fp16 PAIRED fragment-major ----------------
// Paired layout (uints): uidx = ((k>>4)*NP + (n>>4))*128 + ((n&7)*4 + ((k&7)>>1))*4
//                               + ((n>>3)&1)*2 + ((k>>3)&1);   half = uidx*2 + (k&1)
// NP = n-pairs per q16: 8 for MLP (128 cols), 32 for LSTM (512 rows).
__global__ void prep_all(const float* __restrict__ eW1, const float* __restrict__ eW2,
                         const float* __restrict__ eW3, const float* __restrict__ Wih,
                         const float* __restrict__ Whh, const float* __restrict__ bih,
                         const float* __restrict__ bhh,
                         __half* __restrict__ wh, float* __restrict__ pbo)
{
    int i = blockIdx.x * blockDim.x + threadIdx.x;
    if (i >= PREP_N) return;
    if (i < 196608) {               // eW1|eW2|eW3
        const float* src = (i < 65536) ? eW1 : (i < 131072) ? eW2 : eW3;
        int base = (i < 65536) ? OFFH_E1 : (i < 131072) ? OFFH_E2 : OFFH_E3;
        int j = i & 65535;
        int etype = j >> 14;
        int rem = j & 16383;
        int n = rem >> 7, k = rem & 127;
        int uidx = ((k >> 4) * 8 + (n >> 4)) * 128 + ((n & 7) * 4 + ((k & 7) >> 1)) * 4
                   + ((n >> 3) & 1) * 2 + ((k >> 3) & 1);
        wh[base + (etype << 14) + uidx * 2 + (k & 1)] = __float2half_rn(src[j]);
    } else if (i < 458752) {        // Wih' | Whh'
        int j = i - 196608;
        const float* src = (j < 131072) ? Wih : Whh;
        int base = (j < 131072) ? OFFH_WIH : OFFH_WHH;
        j &= 131071;
        int rel = j >> 16;
        int rem = j & 65535;
        int r_old = rem >> 7, k = rem & 127;
        int gate = r_old >> 7, f = r_old & 127;
        int rn = (f << 2) | gate;
        int uidx = ((k >> 4) * 32 + (rn >> 4)) * 128 + ((rn & 7) * 4 + ((k & 7) >> 1)) * 4
                   + ((rn >> 3) & 1) * 2 + ((k >> 3) & 1);
        wh[base + (rel << 16) + uidx * 2 + (k & 1)] = __float2half_rn(src[j]);
    } else {                        // permuted bias sum (fp32)
        int j = i - 458752;
        int rel = j >> 9;
        int r_old = j & 511;
        int gate = r_old >> 7, f = r_old & 127;
        pbo[(rel << 9) + (f << 2) + gate] = bih[j] + bhh[j];
    }
}

// ---------------- CSR build kernels ----------------
__global__ void hist_k(const int* __restrict__ dst, int* __restrict__ cnt, int E) {
    int i = blockIdx.x * blockDim.x + threadIdx.x;
    if (i < E) atomicAdd(&cnt[dst[i]], 1);
}
__global__ void scan1_k(const int* __restrict__ cnt, int* __restrict__ off,
                        int* __restrict__ part, int N) {
    __shared__ int s[1024];
    int i = blockIdx.x * 1024 + threadIdx.x;
    int v = (i < N) ? cnt[i] : 0;
    s[threadIdx.x] = v;
    __syncthreads();
    for (int d = 1; d < 1024; d <<= 1) {
        int t = (threadIdx.x >= d) ? s[threadIdx.x - d] : 0;
        __syncthreads();
        s[threadIdx.x] += t;
        __syncthreads();
    }
    if (i < N) off[i] = s[threadIdx.x] - v;
    if (threadIdx.x == 1023) part[blockIdx.x] = s[1023];
}
__global__ void scan2_k(int* __restrict__ part, int NB) {
    __shared__ int s[512];
    int v = (threadIdx.x < NB) ? part[threadIdx.x] : 0;
    s[threadIdx.x] = v;
    __syncthreads();
    for (int d = 1; d < 512; d <<= 1) {
        int t = (threadIdx.x >= d) ? s[threadIdx.x - d] : 0;
        __syncthreads();
        s[threadIdx.x] += t;
        __syncthreads();
    }
    if (threadIdx.x < NB) part[threadIdx.x] = s[threadIdx.x] - v;
}
__global__ void scan3_k(int* __restrict__ off, const int* __restrict__ part, int N) {
    int i = blockIdx.x * 1024 + threadIdx.x;
    if (i < N) off[i] += part[blockIdx.x];
}
__global__ void fill_k(const int* __restrict__ src, const int* __restrict__ dst,
                       int* __restrict__ off, int* __restrict__ csr, int E) {
    int i = blockIdx.x * blockDim.x + threadIdx.x;
    if (i >= E) return;
    int p = atomicAdd(&off[dst[i]], 1);
    csr[p] = src[i];
}

// ---------------- init ----------------
__global__ void init_embed(const int* __restrict__ x, const float* __restrict__ embed,
                           __half* __restrict__ h, float* __restrict__ c, int n) {
    int i = blockIdx.x * blockDim.x + threadIdx.x;
    if (i >= n * HDIM) return;
    int node = i >> 7, col = i & 127;
    float v = embed[x[node] * HDIM + col];
    h[i] = __float2half_rn(v);
    c[i] = v;
}

// ============ DUAL-etype fused 3-layer MLP, fp16, paired-B, 3-stage pipeline ============
__global__ void __launch_bounds__(256, 2)
mlp3_dual(const float* __restrict__ X,
          const __half* __restrict__ Wa1, const __half* __restrict__ Wa2,
          const __half* __restrict__ Wa3,
          const __half* __restrict__ Wb1, const __half* __restrict__ Wb2,
          const __half* __restrict__ Wb3,
          const float* __restrict__ Ba1, const float* __restrict__ Ba2,
          const float* __restrict__ Ba3,
          const float* __restrict__ Bb1, const float* __restrict__ Bb2,
          const float* __restrict__ Bb3,
          __half* __restrict__ Ya, __half* __restrict__ Yb, int N)
{
    extern __shared__ uint32_t smu[];
    uint32_t* Xs0 = smu;                  // 8192
    uint32_t* Xs1 = smu + 8192;           // 8192
    uint32_t* Wc  = smu + 16384;          // 3*2048
    float*    sb  = (float*)(smu + 22528); // 768

    const int tid    = threadIdx.x;
    const int wid    = tid >> 5;
    const int lane   = tid & 31;
    const int warp_m = wid & 3;
    const int warp_n = wid >> 2;
    const int gid    = lane >> 2;
    const int thid   = lane & 3;
    const int row0   = blockIdx.x << 7;

    const uint32_t wcaddr = smem_u32(Wc);

    if (tid < 128) {
        sb[tid]       = Ba1[tid];
        sb[128 + tid] = Ba2[tid];
        sb[256 + tid] = Ba3[tid];
        sb[384 + tid] = Bb1[tid];
        sb[512 + tid] = Bb2[tid];
        sb[640 + tid] = Bb3[tid];
    }

    auto issueW = [&](int g, int st) {
        const __half* Wl =
            (g < 12) ? ((g < 4) ? Wa1 : (g < 8) ? Wa2 : Wa3)
                     : ((g < 16) ? Wb1 : (g < 20) ? Wb2 : Wb3);
        Wl += (size_t)(g & 3) * 4096;
#pragma unroll
        for (int it = 0; it < 2; it++) {
            int idx = it * 256 + tid;
            cp_async16(wcaddr + (uint32_t)(st * 2048 + idx * 4) * 4u, Wl + idx * 8, 16);
        }
        cp_commit();
    };

    issueW(0, 0);
    issueW(1, 1);

    // prologue: X (fp32) -> half2 fragments in Xs0
#pragma unroll
    for (int it = 0; it < 16; it++) {
        int idx = it * 256 + tid;
        int r   = idx & 127;
        int c4  = idx >> 7;
        int gk  = c4 << 2;
        int grow = row0 + r;
        float4 xv = make_float4(0.f, 0.f, 0.f, 0.f);
        if (grow < N) xv = *(const float4*)(X + (size_t)grow * 128 + gk);
        int q16 = gk >> 4;
        int grp = r >> 4;
        int gd  = r & 7;
        int mh  = (r >> 3) & 1;
        int kh8 = (gk >> 3) & 1;
        int t0  = (gk & 7) >> 1;
        int reg = mh + 2 * kh8;
        int base = ((q16 * 8 + grp) * 32 + gd * 4) * 4 + reg;
        Xs0[base + t0 * 4]       = pk2h(xv.x, xv.y);
        Xs0[base + (t0 + 1) * 4] = pk2h(xv.z, xv.w);
    }

    int gc = 0;
    for (int L = 0; L < 6; L++) {
        const int sl = (L >= 3) ? (L - 3) : L;
        const uint32_t* XsIn = (sl == 0) ? Xs0 : Xs1;
        __half* Y = (L < 3) ? Ya : Yb;

        float acc[2][8][4];
#pragma unroll
        for (int mt = 0; mt < 2; mt++)
#pragma unroll
            for (int nt = 0; nt < 8; nt++)
#pragma unroll
                for (int r = 0; r < 4; r++) acc[mt][nt][r] = 0.f;

        for (int qc = 0; qc < 4; qc++, gc++) {
            cp_wait(23 - gc);
            __syncthreads();
            if (gc + 2 <= 23) {
                int nx = gc + 2;
                issueW(nx, nx % 3);
            }
            const uint32_t* Wb = Wc + (gc % 3) * 2048;
#pragma unroll
            for (int s = 0; s < 2; s++) {
                const int q16 = qc * 2 + s;
                uint32_t a[2][4];
#pragma unroll
                for (int mt = 0; mt < 2; mt++) {
                    uint4 av = *(const uint4*)(XsIn +
                        ((q16 * 8 + warp_m * 2 + mt) * 32 + lane) * 4);
                    a[mt][0] = av.x; a[mt][1] = av.y; a[mt][2] = av.z; a[mt][3] = av.w;
                }
                const uint32_t* Bb = Wb + s * 1024 + (warp_n * 4) * 128 + lane * 4;
#pragma unroll
                for (int ntp = 0; ntp < 4; ntp++) {
                    uint4 bb = *(const uint4*)(Bb + ntp * 128);
                    mma_f16(acc[0][2 * ntp],     a[0], bb.x, bb.y);
                    mma_f16(acc[0][2 * ntp + 1], a[0], bb.z, bb.w);
                    mma_f16(acc[1][2 * ntp],     a[1], bb.x, bb.y);
                    mma_f16(acc[1][2 * ntp + 1], a[1], bb.z, bb.w);
                }
            }
        }

        if (sl < 2) {
            if (sl == 1) __syncthreads();   // in-place on Xs1
#pragma unroll
            for (int mt = 0; mt < 2; mt++) {
#pragma unroll
                for (int nt = 0; nt < 8; nt++) {
                    int colL = warp_n * 64 + nt * 8 + thid * 2;
                    float b0 = sb[L * 128 + colL], b1 = sb[L * 128 + colL + 1];
                    float v00 = fmaxf(acc[mt][nt][0] + b0, 0.f);
                    float v01 = fmaxf(acc[mt][nt][1] + b1, 0.f);
                    float v10 = fmaxf(acc[mt][nt][2] + b0, 0.f);
                    float v11 = fmaxf(acc[mt][nt][3] + b1, 0.f);
                    int nq  = warp_n * 4 + (nt >> 1);
                    int kh8 = nt & 1;
                    int ngr = warp_m * 2 + mt;
                    int uidx = ((nq * 8 + ngr) * 32 + gid * 4 + thid) * 4;
                    Xs1[uidx + 2 * kh8]     = pk2h(v00, v01);
                    Xs1[uidx + 1 + 2 * kh8] = pk2h(v10, v11);
                }
            }
        } else {
#pragma unroll
            for (int mt = 0; mt < 2; mt++) {
                int rbase = row0 + warp_m * 32 + mt * 16 + gid;
#pragma unroll
                for (int nt = 0; nt < 8; nt++) {
                    int colL = warp_n * 64 + nt * 8 + thid * 2;
                    float b0 = sb[L * 128 + colL], b1 = sb[L * 128 + colL + 1];
                    uint32_t h01 = pk2h(fmaxf(acc[mt][nt][0] + b0, 0.f),
                                        fmaxf(acc[mt][nt][1] + b1, 0.f));
                    uint32_t h23 = pk2h(fmaxf(acc[mt][nt][2] + b0, 0.f),
                                        fmaxf(acc[mt][nt][3] + b1, 0.f));
                    if (rbase < N)     *(uint32_t*)(Y + (size_t)rbase * 128 + colL)       = h01;
                    if (rbase + 8 < N) *(uint32_t*)(Y + (size_t)(rbase + 8) * 128 + colL) = h23;
                }
            }
        }
    }
}

// ============ LSTM gate GEMM fp16, paired-B, 3-stage pipeline ============
__global__ void __launch_bounds__(256, 2)
gemm_lstm(const __half* __restrict__ X1, const __half* __restrict__ X2,
          const __half* __restrict__ W1, const __half* __restrict__ W2,
          const float* __restrict__ pb,
          __half* __restrict__ hout, float* __restrict__ c, int N)
{
    extern __shared__ uint32_t smu[];
    uint32_t* Xs = smu;            // 3 * 2560
    uint32_t* Ws = smu + 3 * 2560; // 3 * 2048

    const int tid    = threadIdx.x;
    const int wid    = tid >> 5;
    const int lane   = tid & 31;
    const int warp_m = wid & 3;
    const int warp_n = wid >> 2;
    const int gid    = lane >> 2;
    const int thid   = lane & 3;
    const int colblk = blockIdx.x;            // 0..3 (fast dim -> L2-shared X)
    const int row0   = blockIdx.y << 7;
    const int col0   = colblk << 7;
    const int Q      = 8;

    const uint32_t xaddr = smem_u32(Xs);
    const uint32_t waddr = smem_u32(Ws);

    float acc[2][8][4];
#pragma unroll
    for (int mt = 0; mt < 2; mt++)
#pragma unroll
        for (int nt = 0; nt < 8; nt++)
#pragma unroll
            for (int r = 0; r < 4; r++) acc[mt][nt][r] = 0.f;

    auto issue = [&](int q, int st) {
        const int kc = q << 5;
        const uint32_t xb = xaddr + (uint32_t)st * 2560u * 4u;
        const uint32_t wb = waddr + (uint32_t)st * 2048u * 4u;
        const __half* Wl = (q < 4) ? W1 : W2;
        const int qa = q & 3;
#pragma unroll
        for (int it = 0; it < 4; it++) {
            int idx = it * 256 + tid;
            if (idx < 512) {
                int r  = idx >> 2;
                int c8 = idx & 3;
                int gk = kc + c8 * 8;
                int grow = row0 + r;
                const __half* xp = X1;
                int sz = 0;
                if (grow < N) {
                    xp = (gk < 128) ? (X1 + (size_t)grow * 128 + gk)
                                    : (X2 + (size_t)grow * 128 + (gk - 128));
                    sz = 16;
                }
                cp_async16(xb + (uint32_t)(r * 20 + c8 * 4) * 4u, xp, sz);
            } else {
                int j  = idx - 512;
                int s  = j >> 8;
                int j4 = j & 255;
                int q16 = qa * 2 + s;
                // paired layout: q16 region 4096 uints; colblk slice 1024 uints contiguous
                const __half* wp = Wl + (size_t)(q16 * 4096 + colblk * 1024 + j4 * 4) * 2;
                cp_async16(wb + (uint32_t)(s * 1024 + j4 * 4) * 4u, wp, 16);
            }
        }
        cp_commit();
    };

    issue(0, 0);
    issue(1, 1);
    for (int q = 0; q < Q; q++) {
        cp_wait(Q - 1 - q);
        __syncthreads();
        if (q + 2 < Q) issue(q + 2, (q + 2) % 3);

        const uint32_t* Xb = Xs + (q % 3) * 2560;
        const uint32_t* Wb = Ws + (q % 3) * 2048;
#pragma unroll
        for (int s = 0; s < 2; s++) {
            const int kbu = s * 8;
            uint32_t a[2][4];
#pragma unroll
            for (int mt = 0; mt < 2; mt++) {
                int rr = warp_m * 32 + mt * 16 + gid;
                a[mt][0] = Xb[rr * 20 + kbu + thid];
                a[mt][1] = Xb[(rr + 8) * 20 + kbu + thid];
                a[mt][2] = Xb[rr * 20 + kbu + 4 + thid];
                a[mt][3] = Xb[(rr + 8) * 20 + kbu + 4 + thid];
            }
            const uint32_t* Bb = Wb + s * 1024 + (warp_n * 4) * 128 + lane * 4;
#pragma unroll
            for (int ntp = 0; ntp < 4; ntp++) {
                uint4 bb = *(const uint4*)(Bb + ntp * 128);
                mma_f16(acc[0][2 * ntp],     a[0], bb.x, bb.y);
                mma_f16(acc[0][2 * ntp + 1], a[0], bb.z, bb.w);
                mma_f16(acc[1][2 * ntp],     a[1], bb.x, bb.y);
                mma_f16(acc[1][2 * ntp + 1], a[1], bb.z, bb.w);
            }
        }
    }

    // ---- fused LSTM epilogue ----
    const bool odd = (lane & 1);
    const int featbase = (col0 + warp_n * 64) >> 2;
#pragma unroll
    for (int mt = 0; mt < 2; mt++) {
        int rbase = row0 + warp_m * 32 + mt * 16 + gid;
#pragma unroll
        for (int nt = 0; nt < 8; nt++) {
            int colL = warp_n * 64 + nt * 8 + thid * 2;
            float b0 = pb[col0 + colL], b1 = pb[col0 + colL + 1];
            float v00 = acc[mt][nt][0] + b0;
            float v01 = acc[mt][nt][1] + b1;
            float v10 = acc[mt][nt][2] + b0;
            float v11 = acc[mt][nt][3] + b1;
            float s0 = odd ? v00 : v10;
            float s1 = odd ? v01 : v11;
            float t0 = __shfl_xor_sync(0xFFFFFFFFu, s0, 1);
            float t1 = __shfl_xor_sync(0xFFFFFFFFu, s1, 1);
            float gi = odd ? t0 : v00;
            float gf = odd ? t1 : v01;
            float gg = odd ? v10 : t0;
            float go = odd ? v11 : t1;
            int row  = rbase + (odd ? 8 : 0);
            int feat = featbase + nt * 2 + (thid >> 1);
            if (row < N) {
                size_t o = (size_t)row * 128 + feat;
                float cp = c[o];
                float cn = sigmoidf(gf) * cp + sigmoidf(gi) * tanhf(gg);
                hout[o] = __float2half_rn(sigmoidf(go) * tanhf(cn));
                c[o] = fmaxf(cn, 0.f);
            }
        }
    }
}

// ---------------- CSR gather (half in/out, fp32 accumulate) ----------------
__global__ void gather2(const __half* __restrict__ ta, const int* __restrict__ offa,
                        const int* __restrict__ csra,
                        const __half* __restrict__ tb, const int* __restrict__ offb,
                        const int* __restrict__ csrb,
                        __half* __restrict__ m, int N)
{
    int gw   = (blockIdx.x * blockDim.x + threadIdx.x) >> 5;
    int lane = threadIdx.x & 31;
    if (gw >= N) return;
    float4 acc = make_float4(0.f, 0.f, 0.f, 0.f);
    int s0 = gw ? offa[gw - 1] : 0;
    int e0 = offa[gw];
    for (int e = s0; e < e0; e++) {
        int src = csra[e];
        uint2 raw = *(const uint2*)(ta + (size_t)src * 128 + lane * 4);
        float2 f0 = __half22float2(*(__half2*)&raw.x);
        float2 f1 = __half22float2(*(__half2*)&raw.y);
        acc.x += f0.x; acc.y += f0.y; acc.z += f1.x; acc.w += f1.y;
    }
    int s1 = gw ? offb[gw - 1] : 0;
    int e1 = offb[gw];
    for (int e = s1; e < e1; e++) {
        int src = csrb[e];
        uint2 raw = *(const uint2*)(tb + (size_t)src * 128 + lane * 4);
        float2 f0 = __half22float2(*(__half2*)&raw.x);
        float2 f1 = __half22float2(*(__half2*)&raw.y);
        acc.x += f0.x; acc.y += f0.y; acc.z += f1.x; acc.w += f1.y;
    }
    uint2 outv;
    outv.x = pk2h(acc.x, acc.y);
    outv.y = pk2h(acc.z, acc.w);
    *(uint2*)(m + (size_t)gw * 128 + lane * 4) = outv;
}

// ---------------- attention pooling ----------------
__global__ void pool_reset(unsigned* maxu, float* sum, float* red) {
    if (threadIdx.x == 0) { *maxu = 0u; *sum = 0.f; }
    if (threadIdx.x < HDIM) red[threadIdx.x] = 0.f;
}

__global__ void gate_logits(const float* __restrict__ cc, const float* __restrict__ gW,
                            const float* __restrict__ gb, float* __restrict__ z,
                            unsigned* __restrict__ maxu, int n)
{
    __shared__ float smax[8];
    int gw   = (blockIdx.x * blockDim.x + threadIdx.x) >> 5;
    int lane = threadIdx.x & 31;
    int wid  = threadIdx.x >> 5;
    float myz = -1e30f;
    if (gw < n) {
        float4 a = *(const float4*)(cc + (size_t)gw * HDIM + lane * 4);
        float4 b = *(const float4*)(gW + lane * 4);
        float p = a.x * b.x + a.y * b.y + a.z * b.z + a.w * b.w;
        p += __shfl_down_sync(0xFFFFFFFFu, p, 16);
        p += __shfl_down_sync(0xFFFFFFFFu, p, 8);
        p += __shfl_down_sync(0xFFFFFFFFu, p, 4);
        p += __shfl_down_sync(0xFFFFFFFFu, p, 2);
        p += __shfl_down_sync(0xFFFFFFFFu, p, 1);
        if (lane == 0) {
            myz = p + gb[0];
            z[gw] = myz;
        }
    }
    if (lane == 0) smax[wid] = myz;
    __syncthreads();
    if (threadIdx.x == 0) {
        float mx = smax[0];
#pragma unroll
        for (int w = 1; w < 8; w++) mx = fmaxf(mx, smax[w]);
        atomicMax(maxu, f2ord(mx));
    }
}

__global__ void softmax_accum(const float* __restrict__ cc, const float* __restrict__ z,
                              const unsigned* __restrict__ maxu,
                              float* __restrict__ sum, float* __restrict__ red, int n)
{
    int t = threadIdx.x;
    float zmax = ord2f(*maxu);
    int c0 = blockIdx.x * 64;
    float acc = 0.f, wsum = 0.f;
    for (int i = 0; i < 64; i++) {
        int c = c0 + i;
        if (c >= n) break;
        float w = expf(z[c] - zmax);
        acc  += w * cc[(size_t)c * HDIM + t];
        wsum += w;
    }
    atomicAdd(&red[t], acc);
    if (t == 0) atomicAdd(sum, wsum);
}

__global__ void final_mlp(const float* __restrict__ red, const float* __restrict__ sum,
                          const float* __restrict__ mW1, const float* __restrict__ mb1,
                          const float* __restrict__ mW2, const float* __restrict__ mb2,
                          const float* __restrict__ mW3, const float* __restrict__ mb3,
                          float* __restrict__ out)
{
    __shared__ float x0[HDIM], x1[HDIM], x2[HDIM];
    int t = threadIdx.x;
    x0[t] = red[t] / (*sum);
    __syncthreads();
    {
        float a = mb1[t];
        for (int k = 0; k < HDIM; k++) a = fmaf(x0[k], mW1[t * HDIM + k], a);
        x1[t] = fmaxf(a, 0.f);
    }
    __syncthreads();
    {
        float a = mb2[t];
        for (int k = 0; k < HDIM; k++) a = fmaf(x1[k], mW2[t * HDIM + k], a);
        x2[t] = fmaxf(a, 0.f);
    }
    __syncthreads();
    if (t < 2) {
        float a = mb3[t];
        for (int k = 0; k < HDIM; k++) a = fmaf(x2[k], mW3[t * HDIM + k], a);
        out[t] = a;
    }
}

// ---------------- host orchestration ----------------
#define MLP_SMEM  (23296 * 4)    // 93184 bytes  -> 2 CTAs/SM
#define LSTM_SMEM (13824 * 4)    // 55296 bytes  -> 2 CTAs/SM

static void build_csr(const int* src, const int* dst, int* off, int* csr,
                      int* cnt, int* part, int Ndst)
{
    cudaMemsetAsync(cnt, 0, (size_t)Ndst * sizeof(int));
    hist_k<<<(NEDG + 255) / 256, 256>>>(dst, cnt, NEDG);
    int NB = (Ndst + 1023) / 1024;
    scan1_k<<<NB, 1024>>>(cnt, off, part, Ndst);
    scan2_k<<<1, 512>>>(part, NB);
    scan3_k<<<NB, 1024>>>(off, part, Ndst);
    fill_k<<<(NEDG + 255) / 256, 256>>>(src, dst, off, csr, NEDG);
}

extern "C" void kernel_launch(void* const* d_in, const int* in_sizes, int n_in,
                              void* d_out, int out_size)
{
    const int*   var_x    = (const int*)  d_in[0];
    const int*   clause_x = (const int*)  d_in[1];
    const int*   pos_src  = (const int*)  d_in[2];
    const int*   pos_dst  = (const int*)  d_in[3];
    const int*   neg_src  = (const int*)  d_in[4];
    const int*   neg_dst  = (const int*)  d_in[5];
    const int*   posr_src = (const int*)  d_in[6];
    const int*   posr_dst = (const int*)  d_in[7];
    const int*   negr_src = (const int*)  d_in[8];
    const int*   negr_dst = (const int*)  d_in[9];
    const float* embed    = (const float*)d_in[10];
    const float* eW1      = (const float*)d_in[11];
    const float* eb1      = (const float*)d_in[12];
    const float* eW2      = (const float*)d_in[13];
    const float* eb2      = (const float*)d_in[14];
    const float* eW3      = (const float*)d_in[15];
    const float* eb3      = (const float*)d_in[16];
    const float* Wih      = (const float*)d_in[17];
    const float* Whh      = (const float*)d_in[18];
    const float* bih      = (const float*)d_in[19];
    const float* bhh      = (const float*)d_in[20];
    const float* gW       = (const float*)d_in[21];
    const float* gb       = (const float*)d_in[22];
    const float* mW1      = (const float*)d_in[23];
    const float* mb1      = (const float*)d_in[24];
    const float* mW2      = (const float*)d_in[25];
    const float* mb2      = (const float*)d_in[26];
    const float* mW3      = (const float*)d_in[27];
    const float* mb3      = (const float*)d_in[28];
    float* out = (float*)d_out;

    cudaFuncSetAttribute(mlp3_dual, cudaFuncAttributeMaxDynamicSharedMemorySize, MLP_SMEM);
    cudaFuncSetAttribute(gemm_lstm, cudaFuncAttributeMaxDynamicSharedMemorySize, LSTM_SMEM);

    __half *hv, *hv2, *hc, *hc2, *t1, *t2, *m, *wh;
    float *cv, *cc, *z, *red, *sum, *pb;
    unsigned* maxu;
    int *off, *csr, *cnt, *part;
    cudaGetSymbolAddress((void**)&hv,   g_hv);
    cudaGetSymbolAddress((void**)&hv2,  g_hv2);
    cudaGetSymbolAddress((void**)&hc,   g_hc);
    cudaGetSymbolAddress((void**)&hc2,  g_hc2);
    cudaGetSymbolAddress((void**)&t1,   g_t1);
    cudaGetSymbolAddress((void**)&t2,   g_t2);
    cudaGetSymbolAddress((void**)&m,    g_m);
    cudaGetSymbolAddress((void**)&cv,   g_cv);
    cudaGetSymbolAddress((void**)&cc,   g_cc);
    cudaGetSymbolAddress((void**)&z,    g_z);
    cudaGetSymbolAddress((void**)&red,  g_red);
    cudaGetSymbolAddress((void**)&sum,  g_sum);
    cudaGetSymbolAddress((void**)&maxu, g_maxu);
    cudaGetSymbolAddress((void**)&wh,   g_wh);
    cudaGetSymbolAddress((void**)&pb,   g_pb);
    cudaGetSymbolAddress((void**)&off,  g_off);
    cudaGetSymbolAddress((void**)&csr,  g_csr);
    cudaGetSymbolAddress((void**)&cnt,  g_cnt);
    cudaGetSymbolAddress((void**)&part, g_part);

    int* off_e[4] = {off, off + NCLS, off + 2 * NCLS, off + 3 * NCLS};
    int* csr_e[4] = {csr, csr + NEDG, csr + 2 * NEDG, csr + 3 * NEDG};

    const __half* E1 = wh + OFFH_E1;
    const __half* E2 = wh + OFFH_E2;
    const __half* E3 = wh + OFFH_E3;
    const __half* WIH = wh + OFFH_WIH;
    const __half* WHH = wh + OFFH_WHH;

    const int vgrid = (NVAR + 127) / 128;   // 782
    const int cgrid = (NCLS + 127) / 128;   // 3125
    const int EB = 16384;                    // per-etype weight block (halfs)

    prep_all<<<(PREP_N + 255) / 256, 256>>>(eW1, eW2, eW3, Wih, Whh, bih, bhh, wh, pb);
    init_embed<<<(NVAR * HDIM + 255) / 256, 256>>>(var_x,    embed, hv, cv, NVAR);
    init_embed<<<(NCLS * HDIM + 255) / 256, 256>>>(clause_x, embed, hc, cc, NCLS);

    __half* hcs[2] = {hc, hc2};
    __half* hvs[2] = {hv, hv2};
    int hci = 0, hvi = 0;

    for (int s = 0; s < NSTEPS; s++) {
        // ---- relation 0: var -> clause (etypes 0,1 fused) ----
        mlp3_dual<<<vgrid, 256, MLP_SMEM>>>(cv,
            E1 + 0 * EB, E2 + 0 * EB, E3 + 0 * EB,
            E1 + 1 * EB, E2 + 1 * EB, E3 + 1 * EB,
            eb1 + 0 * HDIM, eb2 + 0 * HDIM, eb3 + 0 * HDIM,
            eb1 + 1 * HDIM, eb2 + 1 * HDIM, eb3 + 1 * HDIM,
            t1, t2, NVAR);
        if (s == 0) {
            build_csr(pos_src,  pos_dst,  off_e[0], csr_e[0], cnt, part, NCLS);
            build_csr(neg_src,  neg_dst,  off_e[1], csr_e[1], cnt, part, NCLS);
            build_csr(posr_src, posr_dst, off_e[2], csr_e[2], cnt, part, NVAR);
            build_csr(negr_src, negr_dst, off_e[3], csr_e[3], cnt, part, NVAR);
        }
        gather2<<<(NCLS * 32 + 255) / 256, 256>>>(t1, off_e[0], csr_e[0],
                                                  t2, off_e[1], csr_e[1], m, NCLS);
        {
            dim3 grid(4, cgrid);
            gemm_lstm<<<grid, 256, LSTM_SMEM>>>(m, hcs[hci], WIH, WHH, pb,
                                                hcs[hci ^ 1], cc, NCLS);
            hci ^= 1;
        }

        // ---- relation 1: clause -> var (etypes 2,3 fused) ----
        mlp3_dual<<<cgrid, 256, MLP_SMEM>>>(cc,
            E1 + 2 * EB, E2 + 2 * EB, E3 + 2 * EB,
            E1 + 3 * EB, E2 + 3 * EB, E3 + 3 * EB,
            eb1 + 2 * HDIM, eb2 + 2 * HDIM, eb3 + 2 * HDIM,
            eb1 + 3 * HDIM, eb2 + 3 * HDIM, eb3 + 3 * HDIM,
            t1, t2, NCLS);
        gather2<<<(NVAR * 32 + 255) / 256, 256>>>(t1, off_e[2], csr_e[2],
                                                  t2, off_e[3], csr_e[3], m, NVAR);
        {
            dim3 grid(4, vgrid);
            gemm_lstm<<<grid, 256, LSTM_SMEM>>>(m, hvs[hvi], WIH + 65536, WHH + 65536,
                                                pb + 512, hvs[hvi ^ 1], cv, NVAR);
            hvi ^= 1;
        }
    }

    // ---- GlobalAttentionPooling + final MLP ----
    pool_reset<<<1, 128>>>(maxu, sum, red);
    gate_logits<<<(NCLS * 32 + 255) / 256, 256>>>(cc, gW, gb, z, maxu, NCLS);
    softmax_accum<<<(NCLS + 63) / 64, 128>>>(cc, z, maxu, sum, red, NCLS);
    final_mlp<<<1, 128>>>(red, sum, mW1, mb1, mW2, mb2, mW3, mb3, out);
}